// round 1
// baseline (speedup 1.0000x reference)
#include <cuda_runtime.h>
#include <stdint.h>
#include <stddef.h>

#define ND 128   // node feature dim
#define ED 32    // edge feature dim
#define OD 128   // output dim
#define TE 128   // edges per block (main kernel)
#define MAXN 10000

// Scratch (device globals: allocation-free rule)
__device__ float g_Pr[MAXN * OD];   // h @ W1[0:128]
__device__ float g_Pc[MAXN * OD];   // h @ W1[128:256]
__device__ int   g_idx64;           // 1 if edge_index is int64, 0 if int32

// ---------------------------------------------------------------------------
__global__ void zero_out_kernel(float* __restrict__ out, int n) {
    int i = blockIdx.x * blockDim.x + threadIdx.x;
    if (i < n) out[i] = 0.0f;
}

// Detect whether edge_index is int64 (little-endian high words all zero) or int32.
__global__ void detect_idx_kernel(const int* __restrict__ ei) {
    if (blockIdx.x == 0 && threadIdx.x == 0) {
        int odd_nonzero = 0;
        for (int i = 0; i < 64; i++)
            if (ei[2 * i + 1] != 0) odd_nonzero++;
        g_idx64 = (odd_nonzero == 0) ? 1 : 0;
    }
}

// ---------------------------------------------------------------------------
// Kernel A: Pr = h @ W1[0:128,:], Pc = h @ W1[128:256,:]
// Block: 256 threads, 64-node tile. Thread tile: 8 nodes x (4+4) cols.
__global__ __launch_bounds__(256) void precompute_P_kernel(
    const float* __restrict__ h, const float* __restrict__ W1, int N) {
    __shared__ float s_h[64][ND];    // 32 KB
    __shared__ float s_w[8][256];    // 8 KB: [kk][j<128]=W1a row, [kk][j>=128]=W1b row
    const int tid = threadIdx.x;
    const int n0 = blockIdx.x * 64;

    for (int t = tid; t < 64 * 32; t += 256) {
        int r = t >> 5, c4 = (t & 31) << 2;
        float4 v = make_float4(0.f, 0.f, 0.f, 0.f);
        if (n0 + r < N) v = *(const float4*)(h + (size_t)(n0 + r) * ND + c4);
        *(float4*)&s_h[r][c4] = v;
    }

    const int cg = tid & 31;       // col group
    const int ng = tid >> 5;       // node group
    const int n_base = ng * 8;
    const int c_lo = cg * 4;       // cols [c_lo..c_lo+3] of Pr, same of Pc

    float acc[8][8];
#pragma unroll
    for (int i = 0; i < 8; i++)
#pragma unroll
        for (int j = 0; j < 8; j++) acc[i][j] = 0.f;

    for (int k0 = 0; k0 < ND; k0 += 8) {
        __syncthreads();
        for (int t = tid; t < 8 * 64; t += 256) {
            int kk = t >> 6, j = (t & 63) << 2;
            int srow = (j < 128) ? (k0 + kk) : (ND + k0 + kk);
            *(float4*)&s_w[kk][j] = *(const float4*)(W1 + (size_t)srow * OD + (j & 127));
        }
        __syncthreads();
#pragma unroll
        for (int kk = 0; kk < 8; kk++) {
            float4 wl = *(const float4*)&s_w[kk][c_lo];
            float4 wh = *(const float4*)&s_w[kk][128 + c_lo];
#pragma unroll
            for (int i = 0; i < 8; i++) {
                float a = s_h[n_base + i][k0 + kk];
                acc[i][0] = fmaf(a, wl.x, acc[i][0]);
                acc[i][1] = fmaf(a, wl.y, acc[i][1]);
                acc[i][2] = fmaf(a, wl.z, acc[i][2]);
                acc[i][3] = fmaf(a, wl.w, acc[i][3]);
                acc[i][4] = fmaf(a, wh.x, acc[i][4]);
                acc[i][5] = fmaf(a, wh.y, acc[i][5]);
                acc[i][6] = fmaf(a, wh.z, acc[i][6]);
                acc[i][7] = fmaf(a, wh.w, acc[i][7]);
            }
        }
    }
#pragma unroll
    for (int i = 0; i < 8; i++) {
        int node = n0 + n_base + i;
        if (node < N) {
            *(float4*)(g_Pr + (size_t)node * OD + c_lo) =
                make_float4(acc[i][0], acc[i][1], acc[i][2], acc[i][3]);
            *(float4*)(g_Pc + (size_t)node * OD + c_lo) =
                make_float4(acc[i][4], acc[i][5], acc[i][6], acc[i][7]);
        }
    }
}

// ---------------------------------------------------------------------------
// Main kernel: per 128-edge tile:
//   hidden = relu(Pr[row] + Pc[col] + ef@W1c + b1)  -> smem
//   msg    = hidden @ W2 + b2
//   red.global.add.v4 -> out[row]
struct SmemMain {
    float w2[OD][OD];        // 64 KB   [k][j]
    float hid[TE][ND + 4];   // 67.6 KB
    float w1c[ED][OD];       // 16 KB   W1 rows 256..287
    float ef[TE][ED + 1];    // 16.9 KB
    int rows[TE];
    int cols[TE];
};

__device__ __forceinline__ float f4get(float4 v, int k) {
    return k == 0 ? v.x : (k == 1 ? v.y : (k == 2 ? v.z : v.w));
}

__global__ __launch_bounds__(256, 1) void mpnn_edge_kernel(
    const void* __restrict__ edge_index_raw,
    const float* __restrict__ edge_features,
    const float* __restrict__ W1,
    const float* __restrict__ b1,
    const float* __restrict__ W2,
    const float* __restrict__ b2,
    float* __restrict__ out,
    long long E) {
    extern __shared__ char smem_raw[];
    SmemMain& sm = *reinterpret_cast<SmemMain*>(smem_raw);
    const int tid = threadIdx.x;
    const long long e0 = (long long)blockIdx.x * TE;
    const int is64 = g_idx64;

    // ---- cooperative loads ----
    for (int t = tid; t < TE; t += 256) {
        long long e = e0 + t;
        int r = 0, c = 0;
        if (e < E) {
            if (is64) {
                r = (int)((const long long*)edge_index_raw)[e];
                c = (int)((const long long*)edge_index_raw)[E + e];
            } else {
                r = ((const int*)edge_index_raw)[e];
                c = ((const int*)edge_index_raw)[E + e];
            }
        }
        sm.rows[t] = r;
        sm.cols[t] = c;
    }
    for (int t = tid; t < TE * (ED / 4); t += 256) {
        int r = t >> 3;
        int c4 = (t & 7) << 2;
        long long e = e0 + r;
        float4 v = make_float4(0.f, 0.f, 0.f, 0.f);
        if (e < E) v = *(const float4*)(edge_features + e * ED + c4);
        sm.ef[r][c4 + 0] = v.x;
        sm.ef[r][c4 + 1] = v.y;
        sm.ef[r][c4 + 2] = v.z;
        sm.ef[r][c4 + 3] = v.w;
    }
    for (int t = tid; t < ED * (OD / 4); t += 256) {
        int k = t >> 5, j = (t & 31) << 2;
        *(float4*)&sm.w1c[k][j] = *(const float4*)(W1 + (size_t)(2 * ND + k) * OD + j);
    }
    for (int t = tid; t < OD * (OD / 4); t += 256) {
        int k = t >> 5, j = (t & 31) << 2;
        *(float4*)&sm.w2[k][j] = *(const float4*)(W2 + (size_t)k * OD + j);
    }
    __syncthreads();

    const int eg = tid >> 4;        // 0..15 edge group
    const int cg = tid & 15;        // 0..15 col group
    const int e_base = eg * 8;
    const int c_lo = cg * 4;        // cols [c_lo..c_lo+3]
    const int c_hi = 64 + cg * 4;   // cols [c_hi..c_hi+3]

    // ---- phase 2: hidden ----
    float acc[8][8];
    {
        float4 b1l = *(const float4*)(b1 + c_lo);
        float4 b1h = *(const float4*)(b1 + c_hi);
#pragma unroll
        for (int i = 0; i < 8; i++) {
            int r = sm.rows[e_base + i];
            int c = sm.cols[e_base + i];
            float4 p0 = *(const float4*)(g_Pr + (size_t)r * OD + c_lo);
            float4 p1 = *(const float4*)(g_Pr + (size_t)r * OD + c_hi);
            float4 q0 = *(const float4*)(g_Pc + (size_t)c * OD + c_lo);
            float4 q1 = *(const float4*)(g_Pc + (size_t)c * OD + c_hi);
            acc[i][0] = b1l.x + p0.x + q0.x;
            acc[i][1] = b1l.y + p0.y + q0.y;
            acc[i][2] = b1l.z + p0.z + q0.z;
            acc[i][3] = b1l.w + p0.w + q0.w;
            acc[i][4] = b1h.x + p1.x + q1.x;
            acc[i][5] = b1h.y + p1.y + q1.y;
            acc[i][6] = b1h.z + p1.z + q1.z;
            acc[i][7] = b1h.w + p1.w + q1.w;
        }
#pragma unroll 8
        for (int k = 0; k < ED; k++) {
            float4 wl = *(const float4*)&sm.w1c[k][c_lo];
            float4 wh = *(const float4*)&sm.w1c[k][c_hi];
#pragma unroll
            for (int i = 0; i < 8; i++) {
                float ev = sm.ef[e_base + i][k];
                acc[i][0] = fmaf(ev, wl.x, acc[i][0]);
                acc[i][1] = fmaf(ev, wl.y, acc[i][1]);
                acc[i][2] = fmaf(ev, wl.z, acc[i][2]);
                acc[i][3] = fmaf(ev, wl.w, acc[i][3]);
                acc[i][4] = fmaf(ev, wh.x, acc[i][4]);
                acc[i][5] = fmaf(ev, wh.y, acc[i][5]);
                acc[i][6] = fmaf(ev, wh.z, acc[i][6]);
                acc[i][7] = fmaf(ev, wh.w, acc[i][7]);
            }
        }
#pragma unroll
        for (int i = 0; i < 8; i++) {
#pragma unroll
            for (int j = 0; j < 8; j++) acc[i][j] = fmaxf(acc[i][j], 0.f);
            *(float4*)&sm.hid[e_base + i][c_lo] =
                make_float4(acc[i][0], acc[i][1], acc[i][2], acc[i][3]);
            *(float4*)&sm.hid[e_base + i][c_hi] =
                make_float4(acc[i][4], acc[i][5], acc[i][6], acc[i][7]);
        }
    }
    __syncthreads();

    // ---- phase 3: messages = hidden @ W2 + b2 ----
    float m[8][8];
    {
        float4 b2l = *(const float4*)(b2 + c_lo);
        float4 b2h = *(const float4*)(b2 + c_hi);
#pragma unroll
        for (int i = 0; i < 8; i++) {
            m[i][0] = b2l.x; m[i][1] = b2l.y; m[i][2] = b2l.z; m[i][3] = b2l.w;
            m[i][4] = b2h.x; m[i][5] = b2h.y; m[i][6] = b2h.z; m[i][7] = b2h.w;
        }
#pragma unroll 4
        for (int k4 = 0; k4 < OD / 4; k4++) {
            float4 a4[8];
#pragma unroll
            for (int i = 0; i < 8; i++)
                a4[i] = *(const float4*)&sm.hid[e_base + i][k4 * 4];
#pragma unroll
            for (int kk = 0; kk < 4; kk++) {
                float4 wl = *(const float4*)&sm.w2[k4 * 4 + kk][c_lo];
                float4 wh = *(const float4*)&sm.w2[k4 * 4 + kk][c_hi];
#pragma unroll
                for (int i = 0; i < 8; i++) {
                    float av = f4get(a4[i], kk);
                    m[i][0] = fmaf(av, wl.x, m[i][0]);
                    m[i][1] = fmaf(av, wl.y, m[i][1]);
                    m[i][2] = fmaf(av, wl.z, m[i][2]);
                    m[i][3] = fmaf(av, wl.w, m[i][3]);
                    m[i][4] = fmaf(av, wh.x, m[i][4]);
                    m[i][5] = fmaf(av, wh.y, m[i][5]);
                    m[i][6] = fmaf(av, wh.z, m[i][6]);
                    m[i][7] = fmaf(av, wh.w, m[i][7]);
                }
            }
        }
    }

    // ---- scatter-add ----
#pragma unroll
    for (int i = 0; i < 8; i++) {
        long long e = e0 + e_base + i;
        if (e < E) {
            float* dst = out + (size_t)sm.rows[e_base + i] * OD;
            asm volatile("red.global.add.v4.f32 [%0], {%1,%2,%3,%4};"
                         :: "l"(dst + c_lo),
                            "f"(m[i][0]), "f"(m[i][1]), "f"(m[i][2]), "f"(m[i][3])
                         : "memory");
            asm volatile("red.global.add.v4.f32 [%0], {%1,%2,%3,%4};"
                         :: "l"(dst + c_hi),
                            "f"(m[i][4]), "f"(m[i][5]), "f"(m[i][6]), "f"(m[i][7])
                         : "memory");
        }
    }
}

// ---------------------------------------------------------------------------
extern "C" void kernel_launch(void* const* d_in, const int* in_sizes, int n_in,
                              void* d_out, int out_size) {
    const float* h = (const float*)d_in[0];
    const void* edge_index = d_in[1];
    const float* ef = (const float*)d_in[2];
    const float *W1 = 0, *b1 = 0, *W2 = 0, *b2 = 0;
    // "n" may or may not be materialized as an input; locate weights by size.
    for (int i = 3; i < n_in; i++) {
        int s = in_sizes[i];
        if (s == (2 * ND + ED) * OD) W1 = (const float*)d_in[i];
        else if (s == OD * OD) W2 = (const float*)d_in[i];
        else if (s == OD) { if (!b1) b1 = (const float*)d_in[i]; else b2 = (const float*)d_in[i]; }
    }
    if (!W1 || !b1 || !W2 || !b2) return;

    int N = in_sizes[0] / ND;
    if (N > MAXN) N = MAXN;
    long long E = (long long)(in_sizes[1] / 2);
    float* out = (float*)d_out;

    zero_out_kernel<<<(out_size + 255) / 256, 256>>>(out, out_size);
    detect_idx_kernel<<<1, 32>>>((const int*)edge_index);
    precompute_P_kernel<<<(N + 63) / 64, 256>>>(h, W1, N);

    cudaFuncSetAttribute(mpnn_edge_kernel,
                         cudaFuncAttributeMaxDynamicSharedMemorySize,
                         (int)sizeof(SmemMain));
    int nblk = (int)((E + TE - 1) / TE);
    mpnn_edge_kernel<<<nblk, 256, (int)sizeof(SmemMain)>>>(
        edge_index, ef, W1, b1, W2, b2, out, E);
}

// round 3
// speedup vs baseline: 2.0865x; 2.0865x over previous
#include <cuda_runtime.h>
#include <cuda_bf16.h>
#include <stdint.h>
#include <stddef.h>

#define ND 128
#define ED 32
#define OD 128
#define TE 128
#define MAXN 10000
#define NSM 148

// ---------------- device scratch ----------------
__device__ float g_Pr[MAXN * OD];
__device__ float g_Pc[MAXN * OD];
__device__ int   g_idx64;
__device__ __nv_bfloat16 g_W2_hi[OD * OD];     // [k][n]
__device__ __nv_bfloat16 g_W2_lo[OD * OD];
__device__ __nv_bfloat16 g_W1c_hi[ED * OD];    // [k][n], k = edge-feat dim
__device__ __nv_bfloat16 g_W1c_lo[ED * OD];

// ---------------- smem layout (bytes) ----------------
// pitches chosen so row stride mod 128B is 16 -> conflict-free ldmatrix
#define PITCH_EF_B 80     // 32 bf16 cols + pad  (80 % 16 == 0, 80*i mod 128 distinct)
#define PITCH_W_B  272    // 128 bf16 cols + pad (272 mod 128 == 16)
#define SM_ROWS 0
#define SM_COLS 512
#define SM_B1   1024
#define SM_B2   1536
#define SM_EFH  2048                      // 128 * 80   = 10240
#define SM_EFL  (SM_EFH + 10240)
#define SM_W1H  (SM_EFL + 10240)          // 32 * 272   = 8704
#define SM_W1L  (SM_W1H + 8704)
#define SM_W2H  (SM_W1L + 8704)           // 128 * 272  = 34816
#define SM_W2L  (SM_W2H + 34816)
#define SM_TOTAL (SM_W2L + 34816)         // = 109568 bytes

// ---------------- helpers ----------------
__device__ __forceinline__ uint32_t smem_u32(const void* p) {
    uint32_t a;
    asm("{ .reg .u64 t; cvta.to.shared.u64 t, %1; cvt.u32.u64 %0, t; }" : "=r"(a) : "l"(p));
    return a;
}
__device__ __forceinline__ void ldmx4(uint32_t* r, uint32_t addr) {
    asm volatile("ldmatrix.sync.aligned.m8n8.x4.shared.b16 {%0,%1,%2,%3}, [%4];"
                 : "=r"(r[0]), "=r"(r[1]), "=r"(r[2]), "=r"(r[3]) : "r"(addr));
}
__device__ __forceinline__ void ldmx2t(uint32_t* r, uint32_t addr) {
    asm volatile("ldmatrix.sync.aligned.m8n8.x2.trans.shared.b16 {%0,%1}, [%2];"
                 : "=r"(r[0]), "=r"(r[1]) : "r"(addr));
}
__device__ __forceinline__ void mma_bf16(float* d, const uint32_t* a, const uint32_t* b) {
    asm volatile(
        "mma.sync.aligned.m16n8k16.row.col.f32.bf16.bf16.f32 "
        "{%0,%1,%2,%3},{%4,%5,%6,%7},{%8,%9},{%0,%1,%2,%3};"
        : "+f"(d[0]), "+f"(d[1]), "+f"(d[2]), "+f"(d[3])
        : "r"(a[0]), "r"(a[1]), "r"(a[2]), "r"(a[3]), "r"(b[0]), "r"(b[1]));
}
// pack two floats to bf16x2 (x0 -> low 16 bits)
__device__ __forceinline__ uint32_t pack2bf(float x0, float x1) {
    uint32_t r;
    asm("cvt.rn.bf16x2.f32 %0, %1, %2;" : "=r"(r) : "f"(x1), "f"(x0));
    return r;
}
__device__ __forceinline__ void split2(float x0, float x1, uint32_t& hi, uint32_t& lo) {
    __nv_bfloat16 h0 = __float2bfloat16_rn(x0);
    __nv_bfloat16 h1 = __float2bfloat16_rn(x1);
    hi = ((uint32_t)__bfloat16_as_ushort(h1) << 16) | __bfloat16_as_ushort(h0);
    lo = pack2bf(x0 - __bfloat162float(h0), x1 - __bfloat162float(h1));
}

// ---------------------------------------------------------------------------
__global__ void zero_out_kernel(float* __restrict__ out, int n) {
    int i = blockIdx.x * blockDim.x + threadIdx.x;
    if (i < n) out[i] = 0.0f;
}
__global__ void detect_idx_kernel(const int* __restrict__ ei) {
    if (threadIdx.x == 0) {
        int nz = 0;
        for (int i = 0; i < 64; i++)
            if (ei[2 * i + 1] != 0) nz++;
        g_idx64 = (nz == 0) ? 1 : 0;
    }
}
__global__ void prep_weights_kernel(const float* __restrict__ W1, const float* __restrict__ W2) {
    int t = blockIdx.x * blockDim.x + threadIdx.x;
    if (t < OD * OD) {
        float x = W2[t];
        __nv_bfloat16 h = __float2bfloat16_rn(x);
        g_W2_hi[t] = h;
        g_W2_lo[t] = __float2bfloat16_rn(x - __bfloat162float(h));
    }
    if (t < ED * OD) {
        float x = W1[(size_t)(2 * ND) * OD + t];
        __nv_bfloat16 h = __float2bfloat16_rn(x);
        g_W1c_hi[t] = h;
        g_W1c_lo[t] = __float2bfloat16_rn(x - __bfloat162float(h));
    }
}

// ---------------------------------------------------------------------------
// Pr = h @ W1[0:128], Pc = h @ W1[128:256]  (exact fp32, unchanged from R1)
__global__ __launch_bounds__(256) void precompute_P_kernel(
    const float* __restrict__ h, const float* __restrict__ W1, int N) {
    __shared__ float s_h[64][ND];
    __shared__ float s_w[8][256];
    const int tid = threadIdx.x;
    const int n0 = blockIdx.x * 64;
    for (int t = tid; t < 64 * 32; t += 256) {
        int r = t >> 5, c4 = (t & 31) << 2;
        float4 v = make_float4(0.f, 0.f, 0.f, 0.f);
        if (n0 + r < N) v = *(const float4*)(h + (size_t)(n0 + r) * ND + c4);
        *(float4*)&s_h[r][c4] = v;
    }
    const int cg = tid & 31, ng = tid >> 5;
    const int n_base = ng * 8, c_lo = cg * 4;
    float acc[8][8];
#pragma unroll
    for (int i = 0; i < 8; i++)
#pragma unroll
        for (int j = 0; j < 8; j++) acc[i][j] = 0.f;
    for (int k0 = 0; k0 < ND; k0 += 8) {
        __syncthreads();
        for (int t = tid; t < 8 * 64; t += 256) {
            int kk = t >> 6, j = (t & 63) << 2;
            int srow = (j < 128) ? (k0 + kk) : (ND + k0 + kk);
            *(float4*)&s_w[kk][j] = *(const float4*)(W1 + (size_t)srow * OD + (j & 127));
        }
        __syncthreads();
#pragma unroll
        for (int kk = 0; kk < 8; kk++) {
            float4 wl = *(const float4*)&s_w[kk][c_lo];
            float4 wh = *(const float4*)&s_w[kk][128 + c_lo];
#pragma unroll
            for (int i = 0; i < 8; i++) {
                float a = s_h[n_base + i][k0 + kk];
                acc[i][0] = fmaf(a, wl.x, acc[i][0]); acc[i][1] = fmaf(a, wl.y, acc[i][1]);
                acc[i][2] = fmaf(a, wl.z, acc[i][2]); acc[i][3] = fmaf(a, wl.w, acc[i][3]);
                acc[i][4] = fmaf(a, wh.x, acc[i][4]); acc[i][5] = fmaf(a, wh.y, acc[i][5]);
                acc[i][6] = fmaf(a, wh.z, acc[i][6]); acc[i][7] = fmaf(a, wh.w, acc[i][7]);
            }
        }
    }
#pragma unroll
    for (int i = 0; i < 8; i++) {
        int node = n0 + n_base + i;
        if (node < N) {
            *(float4*)(g_Pr + (size_t)node * OD + c_lo) =
                make_float4(acc[i][0], acc[i][1], acc[i][2], acc[i][3]);
            *(float4*)(g_Pc + (size_t)node * OD + c_lo) =
                make_float4(acc[i][4], acc[i][5], acc[i][6], acc[i][7]);
        }
    }
}

// ---------------------------------------------------------------------------
// Persistent HMMA edge kernel (8 warps; warp owns 16 edges of the 128-edge tile).
__global__ __launch_bounds__(256, 1) void mpnn_edge_mma_kernel(
    const void* __restrict__ edge_index_raw,
    const float* __restrict__ edge_features,
    const float* __restrict__ b1g,
    const float* __restrict__ b2g,
    float* __restrict__ out,
    long long E, int n_tiles) {
    extern __shared__ char sm[];
    const uint32_t sb = smem_u32(sm);
    const int tid = threadIdx.x;
    const int wid = tid >> 5;
    const int lane = tid & 31;
    const int is64 = g_idx64;

    int* s_rows = (int*)(sm + SM_ROWS);
    int* s_cols = (int*)(sm + SM_COLS);

    // ---- stage weights + biases into smem once ----
    for (int t = tid; t < 2048; t += 256) {           // W2: 128 rows x 16 chunks
        int k = t >> 4, n8 = (t & 15) << 3;
        *(uint4*)(sm + SM_W2H + k * PITCH_W_B + n8 * 2) = *(const uint4*)(g_W2_hi + k * OD + n8);
        *(uint4*)(sm + SM_W2L + k * PITCH_W_B + n8 * 2) = *(const uint4*)(g_W2_lo + k * OD + n8);
    }
    for (int t = tid; t < 512; t += 256) {            // W1c: 32 rows x 16 chunks
        int k = t >> 4, n8 = (t & 15) << 3;
        *(uint4*)(sm + SM_W1H + k * PITCH_W_B + n8 * 2) = *(const uint4*)(g_W1c_hi + k * OD + n8);
        *(uint4*)(sm + SM_W1L + k * PITCH_W_B + n8 * 2) = *(const uint4*)(g_W1c_lo + k * OD + n8);
    }
    if (tid < 128) {
        ((float*)(sm + SM_B1))[tid] = b1g[tid];
        ((float*)(sm + SM_B2))[tid] = b2g[tid];
    }
    __syncthreads();

    const int m0 = wid * 16;           // warp's edge strip
    const int qrow = lane >> 2;        // 0..7
    const int qcol = (lane & 3) * 2;   // even col in 8-col chunk
    const int l16 = lane & 15;
    const uint32_t efA_h = sb + SM_EFH + (m0 + l16) * PITCH_EF_B + ((lane >> 4) * 8) * 2;
    const uint32_t efA_l = sb + SM_EFL + (m0 + l16) * PITCH_EF_B + ((lane >> 4) * 8) * 2;

    for (int tile = blockIdx.x; tile < n_tiles; tile += gridDim.x) {
        const long long e0 = (long long)tile * TE;
        __syncthreads();   // previous tile done with s_rows / ef smem

        // ---- stage indices ----
        if (tid < TE) {
            long long e = e0 + tid;
            int r = 0, c = 0;
            if (e < E) {
                if (is64) {
                    r = (int)((const long long*)edge_index_raw)[e];
                    c = (int)((const long long*)edge_index_raw)[E + e];
                } else {
                    r = ((const int*)edge_index_raw)[e];
                    c = ((const int*)edge_index_raw)[E + e];
                }
            }
            s_rows[tid] = r; s_cols[tid] = c;
        }
        // ---- stage edge features (fp32 -> bf16 hi/lo) ----
        {
            int er = tid >> 1;
            int c0 = (tid & 1) * 16;
            long long e = e0 + er;
            float v[16];
            if (e < E) {
                const float4* p = (const float4*)(edge_features + e * ED + c0);
#pragma unroll
                for (int q = 0; q < 4; q++) {
                    float4 f = p[q];
                    v[q * 4 + 0] = f.x; v[q * 4 + 1] = f.y; v[q * 4 + 2] = f.z; v[q * 4 + 3] = f.w;
                }
            } else {
#pragma unroll
                for (int q = 0; q < 16; q++) v[q] = 0.f;
            }
            uint32_t hi[8], lo[8];
#pragma unroll
            for (int q = 0; q < 8; q++) split2(v[2 * q], v[2 * q + 1], hi[q], lo[q]);
            char* ph = sm + SM_EFH + er * PITCH_EF_B + c0 * 2;
            char* pl = sm + SM_EFL + er * PITCH_EF_B + c0 * 2;
            *(uint4*)(ph) = make_uint4(hi[0], hi[1], hi[2], hi[3]);
            *(uint4*)(ph + 16) = make_uint4(hi[4], hi[5], hi[6], hi[7]);
            *(uint4*)(pl) = make_uint4(lo[0], lo[1], lo[2], lo[3]);
            *(uint4*)(pl + 16) = make_uint4(lo[4], lo[5], lo[6], lo[7]);
        }
        __syncthreads();

        const int e_lo = m0 + qrow, e_hi = e_lo + 8;
        const int r_lo = s_rows[e_lo], r_hi = s_rows[e_hi];
        const int c_lo = s_cols[e_lo], c_hi = s_cols[e_hi];
        const bool v_lo = (e0 + e_lo) < E;
        const bool v_hi = (e0 + e_hi) < E;

        // ---- issue gather half 1 (chunks 0..7) early ----
        float2 gprl[8], gprh[8], gpcl[8], gpch[8];
#pragma unroll
        for (int c = 0; c < 8; c++) {
            int col = c * 8 + qcol;
            gprl[c] = *(const float2*)(g_Pr + (size_t)r_lo * OD + col);
            gprh[c] = *(const float2*)(g_Pr + (size_t)r_hi * OD + col);
            gpcl[c] = *(const float2*)(g_Pc + (size_t)c_lo * OD + col);
            gpch[c] = *(const float2*)(g_Pc + (size_t)c_hi * OD + col);
        }

        // ---- GEMM1: acc = ef @ W1c (3x bf16 split) ----
        float acc[16][4];
#pragma unroll
        for (int n = 0; n < 16; n++)
#pragma unroll
            for (int j = 0; j < 4; j++) acc[n][j] = 0.f;
        {
            uint32_t eh[2][4], el[2][4];
            ldmx4(eh[0], efA_h);       ldmx4(eh[1], efA_h + 32);
            ldmx4(el[0], efA_l);       ldmx4(el[1], efA_l + 32);
#pragma unroll
            for (int n = 0; n < 16; n++) {
                uint32_t bh0[2], bh1[2], bl0[2], bl1[2];
                uint32_t ba = sb + l16 * PITCH_W_B + n * 16;
                ldmx2t(bh0, ba + SM_W1H);
                ldmx2t(bh1, ba + SM_W1H + 16 * PITCH_W_B);
                ldmx2t(bl0, ba + SM_W1L);
                ldmx2t(bl1, ba + SM_W1L + 16 * PITCH_W_B);
                mma_bf16(acc[n], eh[0], bh0);
                mma_bf16(acc[n], eh[1], bh1);
                mma_bf16(acc[n], eh[0], bl0);
                mma_bf16(acc[n], eh[1], bl1);
                mma_bf16(acc[n], el[0], bh0);
                mma_bf16(acc[n], el[1], bh1);
            }
        }

        // ---- epilogue1: hidden = relu(acc + Pr + Pc + b1) -> A frags in regs ----
        uint32_t ah[8][4], al[8][4];
#pragma unroll
        for (int c = 0; c < 8; c++) {
            float2 b1c = *(const float2*)(sm + SM_B1 + (c * 8 + qcol) * 4);
            float h0 = fmaxf(acc[c][0] + gprl[c].x + gpcl[c].x + b1c.x, 0.f);
            float h1 = fmaxf(acc[c][1] + gprl[c].y + gpcl[c].y + b1c.y, 0.f);
            float h2 = fmaxf(acc[c][2] + gprh[c].x + gpch[c].x + b1c.x, 0.f);
            float h3 = fmaxf(acc[c][3] + gprh[c].y + gpch[c].y + b1c.y, 0.f);
            uint32_t hi01, lo01, hi23, lo23;
            split2(h0, h1, hi01, lo01);
            split2(h2, h3, hi23, lo23);
            int kc = c >> 1, o = (c & 1) * 2;
            ah[kc][o] = hi01; ah[kc][o + 1] = hi23;
            al[kc][o] = lo01; al[kc][o + 1] = lo23;
        }
        // gather half 2 (chunks 8..15)
#pragma unroll
        for (int c = 0; c < 8; c++) {
            int col = (c + 8) * 8 + qcol;
            gprl[c] = *(const float2*)(g_Pr + (size_t)r_lo * OD + col);
            gprh[c] = *(const float2*)(g_Pr + (size_t)r_hi * OD + col);
            gpcl[c] = *(const float2*)(g_Pc + (size_t)c_lo * OD + col);
            gpch[c] = *(const float2*)(g_Pc + (size_t)c_hi * OD + col);
        }
#pragma unroll
        for (int c = 0; c < 8; c++) {
            int cc = c + 8;
            float2 b1c = *(const float2*)(sm + SM_B1 + (cc * 8 + qcol) * 4);
            float h0 = fmaxf(acc[cc][0] + gprl[c].x + gpcl[c].x + b1c.x, 0.f);
            float h1 = fmaxf(acc[cc][1] + gprl[c].y + gpcl[c].y + b1c.y, 0.f);
            float h2 = fmaxf(acc[cc][2] + gprh[c].x + gpch[c].x + b1c.x, 0.f);
            float h3 = fmaxf(acc[cc][3] + gprh[c].y + gpch[c].y + b1c.y, 0.f);
            uint32_t hi01, lo01, hi23, lo23;
            split2(h0, h1, hi01, lo01);
            split2(h2, h3, hi23, lo23);
            int kc = cc >> 1, o = (cc & 1) * 2;
            ah[kc][o] = hi01; ah[kc][o + 1] = hi23;
            al[kc][o] = lo01; al[kc][o + 1] = lo23;
        }

        // ---- GEMM2: acc = hidden @ W2 (3x bf16 split) ----
#pragma unroll
        for (int n = 0; n < 16; n++)
#pragma unroll
            for (int j = 0; j < 4; j++) acc[n][j] = 0.f;
#pragma unroll
        for (int n = 0; n < 16; n++) {
#pragma unroll
            for (int k = 0; k < 8; k++) {
                uint32_t bh[2], bl[2];
                uint32_t ba = sb + (k * 16 + l16) * PITCH_W_B + n * 16;
                ldmx2t(bh, ba + SM_W2H);
                ldmx2t(bl, ba + SM_W2L);
                mma_bf16(acc[n], ah[k], bh);
                mma_bf16(acc[n], ah[k], bl);
                mma_bf16(acc[n], al[k], bh);
            }
        }

        // ---- epilogue2: + b2, scatter red.v2 ----
        float* dlo = out + (size_t)r_lo * OD;
        float* dhi = out + (size_t)r_hi * OD;
#pragma unroll
        for (int n = 0; n < 16; n++) {
            int col = n * 8 + qcol;
            float2 b2c = *(const float2*)(sm + SM_B2 + col * 4);
            if (v_lo) {
                float x0 = acc[n][0] + b2c.x, x1 = acc[n][1] + b2c.y;
                asm volatile("red.global.add.v2.f32 [%0], {%1,%2};"
                             :: "l"(dlo + col), "f"(x0), "f"(x1) : "memory");
            }
            if (v_hi) {
                float x0 = acc[n][2] + b2c.x, x1 = acc[n][3] + b2c.y;
                asm volatile("red.global.add.v2.f32 [%0], {%1,%2};"
                             :: "l"(dhi + col), "f"(x0), "f"(x1) : "memory");
            }
        }
    }
}

// ---------------------------------------------------------------------------
extern "C" void kernel_launch(void* const* d_in, const int* in_sizes, int n_in,
                              void* d_out, int out_size) {
    const float* h = (const float*)d_in[0];
    const void* edge_index = d_in[1];
    const float* ef = (const float*)d_in[2];
    const float *W1 = 0, *b1 = 0, *W2 = 0, *b2 = 0;
    for (int i = 3; i < n_in; i++) {
        int s = in_sizes[i];
        if (s == (2 * ND + ED) * OD) W1 = (const float*)d_in[i];
        else if (s == OD * OD) W2 = (const float*)d_in[i];
        else if (s == OD) { if (!b1) b1 = (const float*)d_in[i]; else b2 = (const float*)d_in[i]; }
    }
    if (!W1 || !b1 || !W2 || !b2) return;

    int N = in_sizes[0] / ND;
    if (N > MAXN) N = MAXN;
    long long E = (long long)(in_sizes[1] / 2);
    float* out = (float*)d_out;
    int n_tiles = (int)((E + TE - 1) / TE);

    zero_out_kernel<<<(out_size + 255) / 256, 256>>>(out, out_size);
    detect_idx_kernel<<<1, 32>>>((const int*)edge_index);
    prep_weights_kernel<<<64, 256>>>(W1, W2);
    precompute_P_kernel<<<(N + 63) / 64, 256>>>(h, W1, N);

    cudaFuncSetAttribute(mpnn_edge_mma_kernel,
                         cudaFuncAttributeMaxDynamicSharedMemorySize, SM_TOTAL);
    int grid = NSM;
    if (grid > n_tiles) grid = n_tiles;
    mpnn_edge_mma_kernel<<<grid, 256, SM_TOTAL>>>(
        edge_index, ef, b1, b2, out, E, n_tiles);
}

// round 4
// speedup vs baseline: 2.5143x; 1.2050x over previous
#include <cuda_runtime.h>
#include <cuda_fp16.h>
#include <stdint.h>
#include <stddef.h>

#define ND 128
#define ED 32
#define OD 128
#define TE 128
#define MAXN 10000
#define NSM 148

// ---------------- device scratch ----------------
__device__ float g_Pr[MAXN * OD];
__device__ float g_Pc[MAXN * OD];
__device__ int   g_idx64;
__device__ __half g_W2h[OD * OD];     // [k][n] fp16
__device__ __half g_W1ch[ED * OD];    // [k][n] fp16 (W1 rows 256..287)

// ---------------- smem layout (bytes) ----------------
#define PITCH_EF_B 80     // 32 fp16 cols + pad
#define PITCH_W_B  272    // 128 fp16 cols + pad (272 mod 128 == 16)
#define SM_ROWS 0
#define SM_COLS 512
#define SM_B1   1024
#define SM_B2   1536
#define SM_EFH  2048                      // 128*80 = 10240
#define SM_EFL  (SM_EFH + 10240)
#define SM_W1H  (SM_EFL + 10240)          // 32*272 = 8704
#define SM_W2H  (SM_W1H + 8704)           // 128*272 = 34816
#define SM_TOTAL (SM_W2H + 34816)         // 66048

// ---------------- helpers ----------------
__device__ __forceinline__ uint32_t smem_u32(const void* p) {
    uint32_t a;
    asm("{ .reg .u64 t; cvta.to.shared.u64 t, %1; cvt.u32.u64 %0, t; }" : "=r"(a) : "l"(p));
    return a;
}
__device__ __forceinline__ void ldmx4(uint32_t* r, uint32_t addr) {
    asm volatile("ldmatrix.sync.aligned.m8n8.x4.shared.b16 {%0,%1,%2,%3}, [%4];"
                 : "=r"(r[0]), "=r"(r[1]), "=r"(r[2]), "=r"(r[3]) : "r"(addr));
}
__device__ __forceinline__ void ldmx4t(uint32_t* r, uint32_t addr) {
    asm volatile("ldmatrix.sync.aligned.m8n8.x4.trans.shared.b16 {%0,%1,%2,%3}, [%4];"
                 : "=r"(r[0]), "=r"(r[1]), "=r"(r[2]), "=r"(r[3]) : "r"(addr));
}
__device__ __forceinline__ void mma_f16(float* d, const uint32_t* a, const uint32_t* b) {
    asm volatile(
        "mma.sync.aligned.m16n8k16.row.col.f32.f16.f16.f32 "
        "{%0,%1,%2,%3},{%4,%5,%6,%7},{%8,%9},{%0,%1,%2,%3};"
        : "+f"(d[0]), "+f"(d[1]), "+f"(d[2]), "+f"(d[3])
        : "r"(a[0]), "r"(a[1]), "r"(a[2]), "r"(a[3]), "r"(b[0]), "r"(b[1]));
}
__device__ __forceinline__ uint32_t pack2h(float x0, float x1) {  // x0 -> low
    uint32_t r;
    asm("cvt.rn.f16x2.f32 %0, %1, %2;" : "=r"(r) : "f"(x1), "f"(x0));
    return r;
}
__device__ __forceinline__ void split2h(float x0, float x1, uint32_t& hi, uint32_t& lo) {
    __half h0 = __float2half_rn(x0);
    __half h1 = __float2half_rn(x1);
    hi = ((uint32_t)__half_as_ushort(h1) << 16) | __half_as_ushort(h0);
    lo = pack2h(x0 - __half2float(h0), x1 - __half2float(h1));
}

// ---------------------------------------------------------------------------
__global__ void zero_out_kernel(float* __restrict__ out, int n) {
    int i = blockIdx.x * blockDim.x + threadIdx.x;
    if (i < n) out[i] = 0.0f;
}
__global__ void detect_idx_kernel(const int* __restrict__ ei) {
    if (threadIdx.x == 0) {
        int nz = 0;
        for (int i = 0; i < 64; i++)
            if (ei[2 * i + 1] != 0) nz++;
        g_idx64 = (nz == 0) ? 1 : 0;
    }
}
__global__ void prep_weights_kernel(const float* __restrict__ W1, const float* __restrict__ W2) {
    int t = blockIdx.x * blockDim.x + threadIdx.x;
    if (t < OD * OD) g_W2h[t] = __float2half_rn(W2[t]);
    if (t < ED * OD) g_W1ch[t] = __float2half_rn(W1[(size_t)(2 * ND) * OD + t]);
}

// ---------------------------------------------------------------------------
// Pr = h @ W1[0:128], Pc = h @ W1[128:256]  (exact fp32)
// 32-node tiles: 313 blocks, ~64 regs -> multi-CTA/SM, good wave balance.
__global__ __launch_bounds__(256) void precompute_P_kernel(
    const float* __restrict__ h, const float* __restrict__ W1, int N) {
    __shared__ float s_h[32][ND];     // 16 KB
    __shared__ float s_w[8][256];     // 8 KB
    const int tid = threadIdx.x;
    const int n0 = blockIdx.x * 32;

    for (int t = tid; t < 32 * 32; t += 256) {
        int r = t >> 5, c4 = (t & 31) << 2;
        float4 v = make_float4(0.f, 0.f, 0.f, 0.f);
        if (n0 + r < N) v = *(const float4*)(h + (size_t)(n0 + r) * ND + c4);
        *(float4*)&s_h[r][c4] = v;
    }
    const int cg = tid & 31;          // col group: 8 cols of the 256 concat cols
    const int ng = tid >> 5;          // node group: 4 nodes
    const int n_base = ng * 4;
    const int c_lo = cg * 8;

    float acc[4][8];
#pragma unroll
    for (int i = 0; i < 4; i++)
#pragma unroll
        for (int j = 0; j < 8; j++) acc[i][j] = 0.f;

    for (int k0 = 0; k0 < ND; k0 += 8) {
        __syncthreads();
        for (int t = tid; t < 8 * 64; t += 256) {
            int kk = t >> 6, j = (t & 63) << 2;
            int srow = (j < 128) ? (k0 + kk) : (ND + k0 + kk);
            *(float4*)&s_w[kk][j] = *(const float4*)(W1 + (size_t)srow * OD + (j & 127));
        }
        __syncthreads();
#pragma unroll
        for (int kk = 0; kk < 8; kk++) {
            float4 w0 = *(const float4*)&s_w[kk][c_lo];
            float4 w1 = *(const float4*)&s_w[kk][c_lo + 4];
#pragma unroll
            for (int i = 0; i < 4; i++) {
                float a = s_h[n_base + i][k0 + kk];
                acc[i][0] = fmaf(a, w0.x, acc[i][0]); acc[i][1] = fmaf(a, w0.y, acc[i][1]);
                acc[i][2] = fmaf(a, w0.z, acc[i][2]); acc[i][3] = fmaf(a, w0.w, acc[i][3]);
                acc[i][4] = fmaf(a, w1.x, acc[i][4]); acc[i][5] = fmaf(a, w1.y, acc[i][5]);
                acc[i][6] = fmaf(a, w1.z, acc[i][6]); acc[i][7] = fmaf(a, w1.w, acc[i][7]);
            }
        }
    }
    float* base = (c_lo < 128) ? g_Pr : g_Pc;
    int col = c_lo & 127;
#pragma unroll
    for (int i = 0; i < 4; i++) {
        int node = n0 + n_base + i;
        if (node < N) {
            *(float4*)(base + (size_t)node * OD + col) =
                make_float4(acc[i][0], acc[i][1], acc[i][2], acc[i][3]);
            *(float4*)(base + (size_t)node * OD + col + 4) =
                make_float4(acc[i][4], acc[i][5], acc[i][6], acc[i][7]);
        }
    }
}

// ---------------------------------------------------------------------------
// Persistent HMMA edge kernel. fp16 split-A / single-B: 2 MMAs per (n8,k16).
__global__ __launch_bounds__(256, 1) void mpnn_edge_mma_kernel(
    const void* __restrict__ edge_index_raw,
    const float* __restrict__ edge_features,
    const float* __restrict__ b1g,
    const float* __restrict__ b2g,
    float* __restrict__ out,
    long long E, int n_tiles) {
    extern __shared__ char sm[];
    const uint32_t sb = smem_u32(sm);
    const int tid = threadIdx.x;
    const int wid = tid >> 5;
    const int lane = tid & 31;
    const int is64 = g_idx64;

    int* s_rows = (int*)(sm + SM_ROWS);
    int* s_cols = (int*)(sm + SM_COLS);

    // ---- stage weights + biases once ----
    for (int t = tid; t < 2048; t += 256) {           // W2: 128 rows x 16 chunks of 8 halves
        int k = t >> 4, n8 = (t & 15) << 3;
        *(uint4*)(sm + SM_W2H + k * PITCH_W_B + n8 * 2) = *(const uint4*)(g_W2h + k * OD + n8);
    }
    for (int t = tid; t < 512; t += 256) {            // W1c: 32 rows x 16 chunks
        int k = t >> 4, n8 = (t & 15) << 3;
        *(uint4*)(sm + SM_W1H + k * PITCH_W_B + n8 * 2) = *(const uint4*)(g_W1ch + k * OD + n8);
    }
    if (tid < 128) {
        ((float*)(sm + SM_B1))[tid] = b1g[tid];
        ((float*)(sm + SM_B2))[tid] = b2g[tid];
    }
    __syncthreads();

    const int m0 = wid * 16;
    const int qrow = lane >> 2;
    const int qcol = (lane & 3) * 2;
    const int l16 = lane & 15;
    const uint32_t efA_h = sb + SM_EFH + (m0 + l16) * PITCH_EF_B + ((lane >> 4) * 8) * 2;
    const uint32_t efA_l = sb + SM_EFL + (m0 + l16) * PITCH_EF_B + ((lane >> 4) * 8) * 2;
    // B-operand ldmatrix.x4.trans base lane offset: rows = l16, col pair-half by lane>>4
    const uint32_t blane_off = l16 * PITCH_W_B + (lane >> 4) * 16;

    for (int tile = blockIdx.x; tile < n_tiles; tile += gridDim.x) {
        const long long e0 = (long long)tile * TE;
        __syncthreads();

        // ---- stage indices ----
        if (tid < TE) {
            long long e = e0 + tid;
            int r = 0, c = 0;
            if (e < E) {
                if (is64) {
                    r = (int)((const long long*)edge_index_raw)[e];
                    c = (int)((const long long*)edge_index_raw)[E + e];
                } else {
                    r = ((const int*)edge_index_raw)[e];
                    c = ((const int*)edge_index_raw)[E + e];
                }
            }
            s_rows[tid] = r; s_cols[tid] = c;
        }
        // ---- stage edge features (fp32 -> fp16 hi/lo) ----
        {
            int er = tid >> 1;
            int c0 = (tid & 1) * 16;
            long long e = e0 + er;
            float v[16];
            if (e < E) {
                const float4* p = (const float4*)(edge_features + e * ED + c0);
#pragma unroll
                for (int q = 0; q < 4; q++) {
                    float4 f = p[q];
                    v[q * 4 + 0] = f.x; v[q * 4 + 1] = f.y; v[q * 4 + 2] = f.z; v[q * 4 + 3] = f.w;
                }
            } else {
#pragma unroll
                for (int q = 0; q < 16; q++) v[q] = 0.f;
            }
            uint32_t hi[8], lo[8];
#pragma unroll
            for (int q = 0; q < 8; q++) split2h(v[2 * q], v[2 * q + 1], hi[q], lo[q]);
            char* ph = sm + SM_EFH + er * PITCH_EF_B + c0 * 2;
            char* pl = sm + SM_EFL + er * PITCH_EF_B + c0 * 2;
            *(uint4*)(ph) = make_uint4(hi[0], hi[1], hi[2], hi[3]);
            *(uint4*)(ph + 16) = make_uint4(hi[4], hi[5], hi[6], hi[7]);
            *(uint4*)(pl) = make_uint4(lo[0], lo[1], lo[2], lo[3]);
            *(uint4*)(pl + 16) = make_uint4(lo[4], lo[5], lo[6], lo[7]);
        }
        __syncthreads();

        const int e_lo = m0 + qrow, e_hi = e_lo + 8;
        const int r_lo = s_rows[e_lo], r_hi = s_rows[e_hi];
        const int c_lo = s_cols[e_lo], c_hi = s_cols[e_hi];
        const bool v_lo = (e0 + e_lo) < E;
        const bool v_hi = (e0 + e_hi) < E;

        // ---- gather half 1 (cols 0..63) early ----
        float2 gprl[8], gprh[8], gpcl[8], gpch[8];
#pragma unroll
        for (int c = 0; c < 8; c++) {
            int col = c * 8 + qcol;
            gprl[c] = *(const float2*)(g_Pr + (size_t)r_lo * OD + col);
            gprh[c] = *(const float2*)(g_Pr + (size_t)r_hi * OD + col);
            gpcl[c] = *(const float2*)(g_Pc + (size_t)c_lo * OD + col);
            gpch[c] = *(const float2*)(g_Pc + (size_t)c_hi * OD + col);
        }

        // ---- GEMM1: acc = ef @ W1c  (split-A fp16, single-B) ----
        float acc[16][4];
#pragma unroll
        for (int n = 0; n < 16; n++)
#pragma unroll
            for (int j = 0; j < 4; j++) acc[n][j] = 0.f;
        {
            uint32_t eh[2][4], el[2][4];
            ldmx4(eh[0], efA_h);       ldmx4(eh[1], efA_h + 32);
            ldmx4(el[0], efA_l);       ldmx4(el[1], efA_l + 32);
#pragma unroll
            for (int n2 = 0; n2 < 8; n2++) {
#pragma unroll
                for (int k = 0; k < 2; k++) {
                    uint32_t b[4];
                    ldmx4t(b, sb + SM_W1H + k * 16 * PITCH_W_B + n2 * 32 + blane_off);
                    mma_f16(acc[2 * n2],     eh[k], b);
                    mma_f16(acc[2 * n2],     el[k], b);
                    mma_f16(acc[2 * n2 + 1], eh[k], b + 2);
                    mma_f16(acc[2 * n2 + 1], el[k], b + 2);
                }
            }
        }

        // ---- epilogue1: hidden = relu(acc + Pr + Pc + b1) -> A frags in regs ----
        uint32_t ah[8][4], al[8][4];
#pragma unroll
        for (int c = 0; c < 8; c++) {
            float2 b1c = *(const float2*)(sm + SM_B1 + (c * 8 + qcol) * 4);
            float h0 = fmaxf(acc[c][0] + gprl[c].x + gpcl[c].x + b1c.x, 0.f);
            float h1 = fmaxf(acc[c][1] + gprl[c].y + gpcl[c].y + b1c.y, 0.f);
            float h2 = fmaxf(acc[c][2] + gprh[c].x + gpch[c].x + b1c.x, 0.f);
            float h3 = fmaxf(acc[c][3] + gprh[c].y + gpch[c].y + b1c.y, 0.f);
            uint32_t hi01, lo01, hi23, lo23;
            split2h(h0, h1, hi01, lo01);
            split2h(h2, h3, hi23, lo23);
            int kc = c >> 1, o = (c & 1) * 2;
            ah[kc][o] = hi01; ah[kc][o + 1] = hi23;
            al[kc][o] = lo01; al[kc][o + 1] = lo23;
        }
        // gather half 2 (cols 64..127)
#pragma unroll
        for (int c = 0; c < 8; c++) {
            int col = (c + 8) * 8 + qcol;
            gprl[c] = *(const float2*)(g_Pr + (size_t)r_lo * OD + col);
            gprh[c] = *(const float2*)(g_Pr + (size_t)r_hi * OD + col);
            gpcl[c] = *(const float2*)(g_Pc + (size_t)c_lo * OD + col);
            gpch[c] = *(const float2*)(g_Pc + (size_t)c_hi * OD + col);
        }
#pragma unroll
        for (int c = 0; c < 8; c++) {
            int cc = c + 8;
            float2 b1c = *(const float2*)(sm + SM_B1 + (cc * 8 + qcol) * 4);
            float h0 = fmaxf(acc[cc][0] + gprl[c].x + gpcl[c].x + b1c.x, 0.f);
            float h1 = fmaxf(acc[cc][1] + gprl[c].y + gpcl[c].y + b1c.y, 0.f);
            float h2 = fmaxf(acc[cc][2] + gprh[c].x + gpch[c].x + b1c.x, 0.f);
            float h3 = fmaxf(acc[cc][3] + gprh[c].y + gpch[c].y + b1c.y, 0.f);
            uint32_t hi01, lo01, hi23, lo23;
            split2h(h0, h1, hi01, lo01);
            split2h(h2, h3, hi23, lo23);
            int kc = cc >> 1, o = (cc & 1) * 2;
            ah[kc][o] = hi01; ah[kc][o + 1] = hi23;
            al[kc][o] = lo01; al[kc][o + 1] = lo23;
        }

        // ---- GEMM2: acc = hidden @ W2  (split-A fp16, single-B) ----
#pragma unroll
        for (int n = 0; n < 16; n++)
#pragma unroll
            for (int j = 0; j < 4; j++) acc[n][j] = 0.f;
#pragma unroll
        for (int n2 = 0; n2 < 8; n2++) {
#pragma unroll
            for (int k = 0; k < 8; k++) {
                uint32_t b[4];
                ldmx4t(b, sb + SM_W2H + k * 16 * PITCH_W_B + n2 * 32 + blane_off);
                mma_f16(acc[2 * n2],     ah[k], b);
                mma_f16(acc[2 * n2],     al[k], b);
                mma_f16(acc[2 * n2 + 1], ah[k], b + 2);
                mma_f16(acc[2 * n2 + 1], al[k], b + 2);
            }
        }

        // ---- epilogue2: + b2, scatter red.v2 ----
        float* dlo = out + (size_t)r_lo * OD;
        float* dhi = out + (size_t)r_hi * OD;
#pragma unroll
        for (int n = 0; n < 16; n++) {
            int col = n * 8 + qcol;
            float2 b2c = *(const float2*)(sm + SM_B2 + col * 4);
            if (v_lo) {
                float x0 = acc[n][0] + b2c.x, x1 = acc[n][1] + b2c.y;
                asm volatile("red.global.add.v2.f32 [%0], {%1,%2};"
                             :: "l"(dlo + col), "f"(x0), "f"(x1) : "memory");
            }
            if (v_hi) {
                float x0 = acc[n][2] + b2c.x, x1 = acc[n][3] + b2c.y;
                asm volatile("red.global.add.v2.f32 [%0], {%1,%2};"
                             :: "l"(dhi + col), "f"(x0), "f"(x1) : "memory");
            }
        }
    }
}

// ---------------------------------------------------------------------------
extern "C" void kernel_launch(void* const* d_in, const int* in_sizes, int n_in,
                              void* d_out, int out_size) {
    const float* h = (const float*)d_in[0];
    const void* edge_index = d_in[1];
    const float* ef = (const float*)d_in[2];
    const float *W1 = 0, *b1 = 0, *W2 = 0, *b2 = 0;
    for (int i = 3; i < n_in; i++) {
        int s = in_sizes[i];
        if (s == (2 * ND + ED) * OD) W1 = (const float*)d_in[i];
        else if (s == OD * OD) W2 = (const float*)d_in[i];
        else if (s == OD) { if (!b1) b1 = (const float*)d_in[i]; else b2 = (const float*)d_in[i]; }
    }
    if (!W1 || !b1 || !W2 || !b2) return;

    int N = in_sizes[0] / ND;
    if (N > MAXN) N = MAXN;
    long long E = (long long)(in_sizes[1] / 2);
    float* out = (float*)d_out;
    int n_tiles = (int)((E + TE - 1) / TE);

    zero_out_kernel<<<(out_size + 255) / 256, 256>>>(out, out_size);
    detect_idx_kernel<<<1, 32>>>((const int*)edge_index);
    prep_weights_kernel<<<64, 256>>>(W1, W2);
    precompute_P_kernel<<<(N + 31) / 32, 256>>>(h, W1, N);

    cudaFuncSetAttribute(mpnn_edge_mma_kernel,
                         cudaFuncAttributeMaxDynamicSharedMemorySize, SM_TOTAL);
    int grid = NSM;
    if (grid > n_tiles) grid = n_tiles;
    mpnn_edge_mma_kernel<<<grid, 256, SM_TOTAL>>>(
        edge_index, ef, b1, b2, out, E, n_tiles);
}

// round 5
// speedup vs baseline: 2.7920x; 1.1105x over previous
#include <cuda_runtime.h>
#include <cuda_fp16.h>
#include <stdint.h>
#include <stddef.h>

#define ND 128
#define ED 32
#define OD 128
#define TE 128
#define MAXN 10000
#define NSM 148

// ---------------- device scratch ----------------
__device__ float g_Pr[MAXN * OD];
__device__ float g_Pc[MAXN * OD];
__device__ int   g_idx64;
__device__ __half g_W2h[OD * OD];        // [k][n]
__device__ __half g_W1ch[ED * OD];       // [k][n] (W1 rows 256..287)
__device__ __half g_Wab_hi[ND * 256];    // [k][n]: n<128 -> W1a, n>=128 -> W1b
__device__ __half g_Wab_lo[ND * 256];

// ---------------- edge-kernel smem layout ----------------
#define PITCH_EF_B 80
#define PITCH_W_B  272
#define SM_ROWS 0
#define SM_COLS 512
#define SM_B1   1024
#define SM_B2   1536
#define SM_EFH  2048
#define SM_EFL  (SM_EFH + 10240)
#define SM_W1H  (SM_EFL + 10240)
#define SM_W2H  (SM_W1H + 8704)
#define SM_TOTAL (SM_W2H + 34816)        // 66048

// ---------------- precompute-kernel smem layout ----------------
#define PP_PITCH_H 272                   // 128 fp16 + 16B pad
#define PP_PITCH_W 528                   // 256 fp16 + 16B pad
#define PSM_HH 0
#define PSM_HL 34816
#define PSM_WH 69632
#define PSM_WL 137216
#define PSM_TOTAL 204800

// ---------------- helpers ----------------
__device__ __forceinline__ uint32_t smem_u32(const void* p) {
    uint32_t a;
    asm("{ .reg .u64 t; cvta.to.shared.u64 t, %1; cvt.u32.u64 %0, t; }" : "=r"(a) : "l"(p));
    return a;
}
__device__ __forceinline__ void ldmx4(uint32_t* r, uint32_t addr) {
    asm volatile("ldmatrix.sync.aligned.m8n8.x4.shared.b16 {%0,%1,%2,%3}, [%4];"
                 : "=r"(r[0]), "=r"(r[1]), "=r"(r[2]), "=r"(r[3]) : "r"(addr));
}
__device__ __forceinline__ void ldmx4t(uint32_t* r, uint32_t addr) {
    asm volatile("ldmatrix.sync.aligned.m8n8.x4.trans.shared.b16 {%0,%1,%2,%3}, [%4];"
                 : "=r"(r[0]), "=r"(r[1]), "=r"(r[2]), "=r"(r[3]) : "r"(addr));
}
__device__ __forceinline__ void mma_f16(float* d, const uint32_t* a, const uint32_t* b) {
    asm volatile(
        "mma.sync.aligned.m16n8k16.row.col.f32.f16.f16.f32 "
        "{%0,%1,%2,%3},{%4,%5,%6,%7},{%8,%9},{%0,%1,%2,%3};"
        : "+f"(d[0]), "+f"(d[1]), "+f"(d[2]), "+f"(d[3])
        : "r"(a[0]), "r"(a[1]), "r"(a[2]), "r"(a[3]), "r"(b[0]), "r"(b[1]));
}
__device__ __forceinline__ uint32_t pack2h(float x0, float x1) {  // x0 -> low half
    uint32_t r;
    asm("cvt.rn.f16x2.f32 %0, %1, %2;" : "=r"(r) : "f"(x1), "f"(x0));
    return r;
}
__device__ __forceinline__ void split2h(float x0, float x1, uint32_t& hi, uint32_t& lo) {
    __half h0 = __float2half_rn(x0);
    __half h1 = __float2half_rn(x1);
    hi = ((uint32_t)__half_as_ushort(h1) << 16) | __half_as_ushort(h0);
    lo = pack2h(x0 - __half2float(h0), x1 - __half2float(h1));
}

// ---------------------------------------------------------------------------
__global__ void zero_out_kernel(float* __restrict__ out, int n) {
    int i = blockIdx.x * blockDim.x + threadIdx.x;
    if (i < n) out[i] = 0.0f;
}
__global__ void detect_idx_kernel(const int* __restrict__ ei) {
    if (threadIdx.x == 0) {
        int nz = 0;
        for (int i = 0; i < 64; i++)
            if (ei[2 * i + 1] != 0) nz++;
        g_idx64 = (nz == 0) ? 1 : 0;
    }
}
__global__ void prep_weights_kernel(const float* __restrict__ W1, const float* __restrict__ W2) {
    int t = blockIdx.x * blockDim.x + threadIdx.x;
    if (t < OD * OD) g_W2h[t] = __float2half_rn(W2[t]);
    if (t < ED * OD) g_W1ch[t] = __float2half_rn(W1[(size_t)(2 * ND) * OD + t]);
    if (t < ND * 256) {
        int k = t >> 8, n = t & 255;
        float x = (n < 128) ? W1[(size_t)k * OD + n] : W1[(size_t)(ND + k) * OD + (n - 128)];
        __half hh = __float2half_rn(x);
        g_Wab_hi[t] = hh;
        g_Wab_lo[t] = __float2half_rn(x - __half2float(hh));
    }
}

// ---------------------------------------------------------------------------
// HMMA precompute: [Pr|Pc] = h @ [W1a|W1b], 3-term hi/lo split (~fp32 accuracy).
// Block: 128 nodes x 256 cols, K=128. 8 warps, warp w: rows [16w,16w+16).
__global__ __launch_bounds__(256, 1) void precompute_P_mma_kernel(
    const float* __restrict__ h, int N) {
    extern __shared__ char sm[];
    const uint32_t sb = smem_u32(sm);
    const int tid = threadIdx.x;
    const int wid = tid >> 5;
    const int lane = tid & 31;
    const int l16 = lane & 15;
    const int qrow = lane >> 2;
    const int qcol = (lane & 3) * 2;
    const int n0 = blockIdx.x * 128;

    // ---- stage h (fp32 -> hi/lo fp16) ----
    {
        int row = tid >> 1, c0 = (tid & 1) * 64;
        int node = n0 + row;
        char* ph = sm + PSM_HH + row * PP_PITCH_H + c0 * 2;
        char* pl = sm + PSM_HL + row * PP_PITCH_H + c0 * 2;
#pragma unroll
        for (int q = 0; q < 8; q++) {
            float4 f0 = make_float4(0.f, 0.f, 0.f, 0.f), f1 = f0;
            if (node < N) {
                f0 = *(const float4*)(h + (size_t)node * ND + c0 + q * 8);
                f1 = *(const float4*)(h + (size_t)node * ND + c0 + q * 8 + 4);
            }
            uint32_t h0, l0, h1, l1, h2, l2, h3, l3;
            split2h(f0.x, f0.y, h0, l0); split2h(f0.z, f0.w, h1, l1);
            split2h(f1.x, f1.y, h2, l2); split2h(f1.z, f1.w, h3, l3);
            *(uint4*)(ph + q * 16) = make_uint4(h0, h1, h2, h3);
            *(uint4*)(pl + q * 16) = make_uint4(l0, l1, l2, l3);
        }
    }
    // ---- stage W (fp16 hi/lo from global) ----
    for (int t = tid; t < 4096; t += 256) {
        int k = t >> 5, c8 = (t & 31) << 3;
        *(uint4*)(sm + PSM_WH + k * PP_PITCH_W + c8 * 2) = *(const uint4*)(g_Wab_hi + k * 256 + c8);
        *(uint4*)(sm + PSM_WL + k * PP_PITCH_W + c8 * 2) = *(const uint4*)(g_Wab_lo + k * 256 + c8);
    }
    __syncthreads();

    const int m0 = wid * 16;
    // ---- load A frags (all 8 k-chunks, hi+lo) ----
    uint32_t ahf[8][4], alf[8][4];
    {
        uint32_t ab_h = sb + PSM_HH + (m0 + l16) * PP_PITCH_H + (lane >> 4) * 16;
        uint32_t ab_l = sb + PSM_HL + (m0 + l16) * PP_PITCH_H + (lane >> 4) * 16;
#pragma unroll
        for (int k = 0; k < 8; k++) {
            ldmx4(ahf[k], ab_h + k * 32);
            ldmx4(alf[k], ab_l + k * 32);
        }
    }

    const int node_lo = n0 + m0 + qrow;
    const int node_hi = node_lo + 8;
#pragma unroll
    for (int p = 0; p < 2; p++) {
        float acc[16][4];
#pragma unroll
        for (int i = 0; i < 16; i++)
#pragma unroll
            for (int j = 0; j < 4; j++) acc[i][j] = 0.f;
#pragma unroll
        for (int n2 = 0; n2 < 8; n2++) {
#pragma unroll
            for (int k = 0; k < 8; k++) {
                uint32_t bh[4], bl[4];
                uint32_t ba = (k * 16 + l16) * PP_PITCH_W + (p * 128 + n2 * 16) * 2 +
                              (lane >> 4) * 16;
                ldmx4t(bh, sb + PSM_WH + ba);
                ldmx4t(bl, sb + PSM_WL + ba);
                mma_f16(acc[2 * n2],     ahf[k], bh);
                mma_f16(acc[2 * n2],     ahf[k], bl);
                mma_f16(acc[2 * n2],     alf[k], bh);
                mma_f16(acc[2 * n2 + 1], ahf[k], bh + 2);
                mma_f16(acc[2 * n2 + 1], ahf[k], bl + 2);
                mma_f16(acc[2 * n2 + 1], alf[k], bh + 2);
            }
        }
        float* base = (p == 0) ? g_Pr : g_Pc;
#pragma unroll
        for (int n2 = 0; n2 < 8; n2++) {
#pragma unroll
            for (int hlf = 0; hlf < 2; hlf++) {
                int col = n2 * 16 + hlf * 8 + qcol;
                float* a = acc[2 * n2 + hlf];
                if (node_lo < N)
                    *(float2*)(base + (size_t)node_lo * OD + col) = make_float2(a[0], a[1]);
                if (node_hi < N)
                    *(float2*)(base + (size_t)node_hi * OD + col) = make_float2(a[2], a[3]);
            }
        }
    }
}

// ---------------------------------------------------------------------------
// Persistent HMMA edge kernel. GEMM1: split-A fp16; GEMM2: single fp16 A.
__global__ __launch_bounds__(256, 1) void mpnn_edge_mma_kernel(
    const void* __restrict__ edge_index_raw,
    const float* __restrict__ edge_features,
    const float* __restrict__ b1g,
    const float* __restrict__ b2g,
    float* __restrict__ out,
    long long E, int n_tiles) {
    extern __shared__ char sm[];
    const uint32_t sb = smem_u32(sm);
    const int tid = threadIdx.x;
    const int wid = tid >> 5;
    const int lane = tid & 31;
    const int is64 = g_idx64;

    int* s_rows = (int*)(sm + SM_ROWS);
    int* s_cols = (int*)(sm + SM_COLS);

    for (int t = tid; t < 2048; t += 256) {
        int k = t >> 4, n8 = (t & 15) << 3;
        *(uint4*)(sm + SM_W2H + k * PITCH_W_B + n8 * 2) = *(const uint4*)(g_W2h + k * OD + n8);
    }
    for (int t = tid; t < 512; t += 256) {
        int k = t >> 4, n8 = (t & 15) << 3;
        *(uint4*)(sm + SM_W1H + k * PITCH_W_B + n8 * 2) = *(const uint4*)(g_W1ch + k * OD + n8);
    }
    if (tid < 128) {
        ((float*)(sm + SM_B1))[tid] = b1g[tid];
        ((float*)(sm + SM_B2))[tid] = b2g[tid];
    }
    __syncthreads();

    const int m0 = wid * 16;
    const int qrow = lane >> 2;
    const int qcol = (lane & 3) * 2;
    const int l16 = lane & 15;
    const uint32_t efA_h = sb + SM_EFH + (m0 + l16) * PITCH_EF_B + ((lane >> 4) * 8) * 2;
    const uint32_t efA_l = sb + SM_EFL + (m0 + l16) * PITCH_EF_B + ((lane >> 4) * 8) * 2;
    const uint32_t blane_off = l16 * PITCH_W_B + (lane >> 4) * 16;

    for (int tile = blockIdx.x; tile < n_tiles; tile += gridDim.x) {
        const long long e0 = (long long)tile * TE;
        __syncthreads();

        if (tid < TE) {
            long long e = e0 + tid;
            int r = 0, c = 0;
            if (e < E) {
                if (is64) {
                    r = (int)((const long long*)edge_index_raw)[e];
                    c = (int)((const long long*)edge_index_raw)[E + e];
                } else {
                    r = ((const int*)edge_index_raw)[e];
                    c = ((const int*)edge_index_raw)[E + e];
                }
            }
            s_rows[tid] = r; s_cols[tid] = c;
        }
        {
            int er = tid >> 1;
            int c0 = (tid & 1) * 16;
            long long e = e0 + er;
            float v[16];
            if (e < E) {
                const float4* p = (const float4*)(edge_features + e * ED + c0);
#pragma unroll
                for (int q = 0; q < 4; q++) {
                    float4 f = p[q];
                    v[q * 4 + 0] = f.x; v[q * 4 + 1] = f.y; v[q * 4 + 2] = f.z; v[q * 4 + 3] = f.w;
                }
            } else {
#pragma unroll
                for (int q = 0; q < 16; q++) v[q] = 0.f;
            }
            uint32_t hi[8], lo[8];
#pragma unroll
            for (int q = 0; q < 8; q++) split2h(v[2 * q], v[2 * q + 1], hi[q], lo[q]);
            char* ph = sm + SM_EFH + er * PITCH_EF_B + c0 * 2;
            char* pl = sm + SM_EFL + er * PITCH_EF_B + c0 * 2;
            *(uint4*)(ph) = make_uint4(hi[0], hi[1], hi[2], hi[3]);
            *(uint4*)(ph + 16) = make_uint4(hi[4], hi[5], hi[6], hi[7]);
            *(uint4*)(pl) = make_uint4(lo[0], lo[1], lo[2], lo[3]);
            *(uint4*)(pl + 16) = make_uint4(lo[4], lo[5], lo[6], lo[7]);
        }
        __syncthreads();

        const int e_lo = m0 + qrow, e_hi = e_lo + 8;
        const int r_lo = s_rows[e_lo], r_hi = s_rows[e_hi];
        const int c_lo = s_cols[e_lo], c_hi = s_cols[e_hi];
        const bool v_lo = (e0 + e_lo) < E;
        const bool v_hi = (e0 + e_hi) < E;

        float2 gprl[8], gprh[8], gpcl[8], gpch[8];
#pragma unroll
        for (int c = 0; c < 8; c++) {
            int col = c * 8 + qcol;
            gprl[c] = *(const float2*)(g_Pr + (size_t)r_lo * OD + col);
            gprh[c] = *(const float2*)(g_Pr + (size_t)r_hi * OD + col);
            gpcl[c] = *(const float2*)(g_Pc + (size_t)c_lo * OD + col);
            gpch[c] = *(const float2*)(g_Pc + (size_t)c_hi * OD + col);
        }

        // ---- GEMM1: ef @ W1c (split-A) ----
        float acc[16][4];
#pragma unroll
        for (int n = 0; n < 16; n++)
#pragma unroll
            for (int j = 0; j < 4; j++) acc[n][j] = 0.f;
        {
            uint32_t eh[2][4], el[2][4];
            ldmx4(eh[0], efA_h);       ldmx4(eh[1], efA_h + 32);
            ldmx4(el[0], efA_l);       ldmx4(el[1], efA_l + 32);
#pragma unroll
            for (int n2 = 0; n2 < 8; n2++) {
#pragma unroll
                for (int k = 0; k < 2; k++) {
                    uint32_t b[4];
                    ldmx4t(b, sb + SM_W1H + k * 16 * PITCH_W_B + n2 * 32 + blane_off);
                    mma_f16(acc[2 * n2],     eh[k], b);
                    mma_f16(acc[2 * n2],     el[k], b);
                    mma_f16(acc[2 * n2 + 1], eh[k], b + 2);
                    mma_f16(acc[2 * n2 + 1], el[k], b + 2);
                }
            }
        }

        // ---- epilogue1: hidden = relu(acc + Pr + Pc + b1) -> fp16 A frags ----
        uint32_t ah[8][4];
#pragma unroll
        for (int c = 0; c < 8; c++) {
            float2 b1c = *(const float2*)(sm + SM_B1 + (c * 8 + qcol) * 4);
            float h0 = fmaxf(acc[c][0] + gprl[c].x + gpcl[c].x + b1c.x, 0.f);
            float h1 = fmaxf(acc[c][1] + gprl[c].y + gpcl[c].y + b1c.y, 0.f);
            float h2 = fmaxf(acc[c][2] + gprh[c].x + gpch[c].x + b1c.x, 0.f);
            float h3 = fmaxf(acc[c][3] + gprh[c].y + gpch[c].y + b1c.y, 0.f);
            int kc = c >> 1, o = (c & 1) * 2;
            ah[kc][o] = pack2h(h0, h1);
            ah[kc][o + 1] = pack2h(h2, h3);
        }
#pragma unroll
        for (int c = 0; c < 8; c++) {
            int col = (c + 8) * 8 + qcol;
            gprl[c] = *(const float2*)(g_Pr + (size_t)r_lo * OD + col);
            gprh[c] = *(const float2*)(g_Pr + (size_t)r_hi * OD + col);
            gpcl[c] = *(const float2*)(g_Pc + (size_t)c_lo * OD + col);
            gpch[c] = *(const float2*)(g_Pc + (size_t)c_hi * OD + col);
        }
#pragma unroll
        for (int c = 0; c < 8; c++) {
            int cc = c + 8;
            float2 b1c = *(const float2*)(sm + SM_B1 + (cc * 8 + qcol) * 4);
            float h0 = fmaxf(acc[cc][0] + gprl[c].x + gpcl[c].x + b1c.x, 0.f);
            float h1 = fmaxf(acc[cc][1] + gprl[c].y + gpcl[c].y + b1c.y, 0.f);
            float h2 = fmaxf(acc[cc][2] + gprh[c].x + gpch[c].x + b1c.x, 0.f);
            float h3 = fmaxf(acc[cc][3] + gprh[c].y + gpch[c].y + b1c.y, 0.f);
            int kc = cc >> 1, o = (cc & 1) * 2;
            ah[kc][o] = pack2h(h0, h1);
            ah[kc][o + 1] = pack2h(h2, h3);
        }

        // ---- GEMM2: hidden @ W2 (single fp16 A) ----
#pragma unroll
        for (int n = 0; n < 16; n++)
#pragma unroll
            for (int j = 0; j < 4; j++) acc[n][j] = 0.f;
#pragma unroll
        for (int n2 = 0; n2 < 8; n2++) {
#pragma unroll
            for (int k = 0; k < 8; k++) {
                uint32_t b[4];
                ldmx4t(b, sb + SM_W2H + k * 16 * PITCH_W_B + n2 * 32 + blane_off);
                mma_f16(acc[2 * n2],     ah[k], b);
                mma_f16(acc[2 * n2 + 1], ah[k], b + 2);
            }
        }

        // ---- epilogue2: + b2, scatter red.v2 ----
        float* dlo = out + (size_t)r_lo * OD;
        float* dhi = out + (size_t)r_hi * OD;
#pragma unroll
        for (int n = 0; n < 16; n++) {
            int col = n * 8 + qcol;
            float2 b2c = *(const float2*)(sm + SM_B2 + col * 4);
            if (v_lo) {
                float x0 = acc[n][0] + b2c.x, x1 = acc[n][1] + b2c.y;
                asm volatile("red.global.add.v2.f32 [%0], {%1,%2};"
                             :: "l"(dlo + col), "f"(x0), "f"(x1) : "memory");
            }
            if (v_hi) {
                float x0 = acc[n][2] + b2c.x, x1 = acc[n][3] + b2c.y;
                asm volatile("red.global.add.v2.f32 [%0], {%1,%2};"
                             :: "l"(dhi + col), "f"(x0), "f"(x1) : "memory");
            }
        }
    }
}

// ---------------------------------------------------------------------------
extern "C" void kernel_launch(void* const* d_in, const int* in_sizes, int n_in,
                              void* d_out, int out_size) {
    const float* h = (const float*)d_in[0];
    const void* edge_index = d_in[1];
    const float* ef = (const float*)d_in[2];
    const float *W1 = 0, *b1 = 0, *W2 = 0, *b2 = 0;
    for (int i = 3; i < n_in; i++) {
        int s = in_sizes[i];
        if (s == (2 * ND + ED) * OD) W1 = (const float*)d_in[i];
        else if (s == OD * OD) W2 = (const float*)d_in[i];
        else if (s == OD) { if (!b1) b1 = (const float*)d_in[i]; else b2 = (const float*)d_in[i]; }
    }
    if (!W1 || !b1 || !W2 || !b2) return;

    int N = in_sizes[0] / ND;
    if (N > MAXN) N = MAXN;
    long long E = (long long)(in_sizes[1] / 2);
    float* out = (float*)d_out;
    int n_tiles = (int)((E + TE - 1) / TE);

    zero_out_kernel<<<(out_size + 255) / 256, 256>>>(out, out_size);
    detect_idx_kernel<<<1, 32>>>((const int*)edge_index);
    prep_weights_kernel<<<128, 256>>>(W1, W2);

    cudaFuncSetAttribute(precompute_P_mma_kernel,
                         cudaFuncAttributeMaxDynamicSharedMemorySize, PSM_TOTAL);
    precompute_P_mma_kernel<<<(N + 127) / 128, 256, PSM_TOTAL>>>(h, N);

    cudaFuncSetAttribute(mpnn_edge_mma_kernel,
                         cudaFuncAttributeMaxDynamicSharedMemorySize, SM_TOTAL);
    int grid = NSM;
    if (grid > n_tiles) grid = n_tiles;
    mpnn_edge_mma_kernel<<<grid, 256, SM_TOTAL>>>(
        edge_index, ef, b1, b2, out, E, n_tiles);
}

// round 6
// speedup vs baseline: 3.4304x; 1.2287x over previous
#include <cuda_runtime.h>
#include <cuda_fp16.h>
#include <stdint.h>
#include <stddef.h>

#define ND 128
#define ED 32
#define OD 128
#define TE 128
#define MAXN 10000
#define NSM 148

// ---------------- device scratch ----------------
__device__ float g_Pr[MAXN * OD];
__device__ float g_Pc[MAXN * OD];
__device__ int   g_idx64;
__device__ __half g_W2h[OD * OD];        // [k][n]
__device__ __half g_W1ch[ED * OD];       // [k][n] (W1 rows 256..287)
__device__ __half g_Wab_hi[ND * 256];    // [k][n]: n<128 -> W1a, n>=128 -> W1b
__device__ __half g_Wab_lo[ND * 256];

// ---------------- edge-kernel smem layout ----------------
#define PITCH_EF_B 80
#define PITCH_W_B  272
#define SM_ROWS 0
#define SM_COLS 512
#define SM_B1   1024
#define SM_B2   1536
#define SM_EFH  2048                     // 128*80 = 10240
#define SM_W1H  (SM_EFH + 10240)         // 32*272 = 8704
#define SM_W2H  (SM_W1H + 8704)          // 128*272 = 34816
#define SM_TOTAL (SM_W2H + 34816)        // 55808

// ---------------- precompute-kernel smem layout ----------------
#define PP_PITCH_H 272
#define PP_PITCH_W 528
#define PSM_HH 0
#define PSM_HL 34816
#define PSM_WH 69632
#define PSM_WL 137216
#define PSM_TOTAL 204800

// ---------------- helpers ----------------
__device__ __forceinline__ uint32_t smem_u32(const void* p) {
    uint32_t a;
    asm("{ .reg .u64 t; cvta.to.shared.u64 t, %1; cvt.u32.u64 %0, t; }" : "=r"(a) : "l"(p));
    return a;
}
__device__ __forceinline__ void ldmx4(uint32_t* r, uint32_t addr) {
    asm volatile("ldmatrix.sync.aligned.m8n8.x4.shared.b16 {%0,%1,%2,%3}, [%4];"
                 : "=r"(r[0]), "=r"(r[1]), "=r"(r[2]), "=r"(r[3]) : "r"(addr));
}
__device__ __forceinline__ void ldmx4t(uint32_t* r, uint32_t addr) {
    asm volatile("ldmatrix.sync.aligned.m8n8.x4.trans.shared.b16 {%0,%1,%2,%3}, [%4];"
                 : "=r"(r[0]), "=r"(r[1]), "=r"(r[2]), "=r"(r[3]) : "r"(addr));
}
__device__ __forceinline__ void mma_f16(float* d, const uint32_t* a, const uint32_t* b) {
    asm volatile(
        "mma.sync.aligned.m16n8k16.row.col.f32.f16.f16.f32 "
        "{%0,%1,%2,%3},{%4,%5,%6,%7},{%8,%9},{%0,%1,%2,%3};"
        : "+f"(d[0]), "+f"(d[1]), "+f"(d[2]), "+f"(d[3])
        : "r"(a[0]), "r"(a[1]), "r"(a[2]), "r"(a[3]), "r"(b[0]), "r"(b[1]));
}
__device__ __forceinline__ uint32_t pack2h(float x0, float x1) {  // x0 -> low half
    uint32_t r;
    asm("cvt.rn.f16x2.f32 %0, %1, %2;" : "=r"(r) : "f"(x1), "f"(x0));
    return r;
}
__device__ __forceinline__ void split2h(float x0, float x1, uint32_t& hi, uint32_t& lo) {
    __half h0 = __float2half_rn(x0);
    __half h1 = __float2half_rn(x1);
    hi = ((uint32_t)__half_as_ushort(h1) << 16) | __half_as_ushort(h0);
    lo = pack2h(x0 - __half2float(h0), x1 - __half2float(h1));
}

// ---------------------------------------------------------------------------
__global__ void zero_out_kernel(float* __restrict__ out, int n) {
    int i = blockIdx.x * blockDim.x + threadIdx.x;
    if (i < n) out[i] = 0.0f;
}
__global__ void detect_idx_kernel(const int* __restrict__ ei) {
    if (threadIdx.x == 0) {
        int nz = 0;
        for (int i = 0; i < 64; i++)
            if (ei[2 * i + 1] != 0) nz++;
        g_idx64 = (nz == 0) ? 1 : 0;
    }
}
__global__ void prep_weights_kernel(const float* __restrict__ W1, const float* __restrict__ W2) {
    int t = blockIdx.x * blockDim.x + threadIdx.x;
    if (t < OD * OD) g_W2h[t] = __float2half_rn(W2[t]);
    if (t < ED * OD) g_W1ch[t] = __float2half_rn(W1[(size_t)(2 * ND) * OD + t]);
    if (t < ND * 256) {
        int k = t >> 8, n = t & 255;
        float x = (n < 128) ? W1[(size_t)k * OD + n] : W1[(size_t)(ND + k) * OD + (n - 128)];
        __half hh = __float2half_rn(x);
        g_Wab_hi[t] = hh;
        g_Wab_lo[t] = __float2half_rn(x - __half2float(hh));
    }
}

// ---------------------------------------------------------------------------
// HMMA precompute: [Pr|Pc] = h @ [W1a|W1b], 3-term hi/lo split (~fp32 accuracy).
__global__ __launch_bounds__(256, 1) void precompute_P_mma_kernel(
    const float* __restrict__ h, int N) {
    extern __shared__ char sm[];
    const uint32_t sb = smem_u32(sm);
    const int tid = threadIdx.x;
    const int wid = tid >> 5;
    const int lane = tid & 31;
    const int l16 = lane & 15;
    const int qrow = lane >> 2;
    const int qcol = (lane & 3) * 2;
    const int n0 = blockIdx.x * 128;

    {
        int row = tid >> 1, c0 = (tid & 1) * 64;
        int node = n0 + row;
        char* ph = sm + PSM_HH + row * PP_PITCH_H + c0 * 2;
        char* pl = sm + PSM_HL + row * PP_PITCH_H + c0 * 2;
#pragma unroll
        for (int q = 0; q < 8; q++) {
            float4 f0 = make_float4(0.f, 0.f, 0.f, 0.f), f1 = f0;
            if (node < N) {
                f0 = *(const float4*)(h + (size_t)node * ND + c0 + q * 8);
                f1 = *(const float4*)(h + (size_t)node * ND + c0 + q * 8 + 4);
            }
            uint32_t h0, l0, h1, l1, h2, l2, h3, l3;
            split2h(f0.x, f0.y, h0, l0); split2h(f0.z, f0.w, h1, l1);
            split2h(f1.x, f1.y, h2, l2); split2h(f1.z, f1.w, h3, l3);
            *(uint4*)(ph + q * 16) = make_uint4(h0, h1, h2, h3);
            *(uint4*)(pl + q * 16) = make_uint4(l0, l1, l2, l3);
        }
    }
    for (int t = tid; t < 4096; t += 256) {
        int k = t >> 5, c8 = (t & 31) << 3;
        *(uint4*)(sm + PSM_WH + k * PP_PITCH_W + c8 * 2) = *(const uint4*)(g_Wab_hi + k * 256 + c8);
        *(uint4*)(sm + PSM_WL + k * PP_PITCH_W + c8 * 2) = *(const uint4*)(g_Wab_lo + k * 256 + c8);
    }
    __syncthreads();

    const int m0 = wid * 16;
    uint32_t ahf[8][4], alf[8][4];
    {
        uint32_t ab_h = sb + PSM_HH + (m0 + l16) * PP_PITCH_H + (lane >> 4) * 16;
        uint32_t ab_l = sb + PSM_HL + (m0 + l16) * PP_PITCH_H + (lane >> 4) * 16;
#pragma unroll
        for (int k = 0; k < 8; k++) {
            ldmx4(ahf[k], ab_h + k * 32);
            ldmx4(alf[k], ab_l + k * 32);
        }
    }

    const int node_lo = n0 + m0 + qrow;
    const int node_hi = node_lo + 8;
#pragma unroll
    for (int p = 0; p < 2; p++) {
        float acc[16][4];
#pragma unroll
        for (int i = 0; i < 16; i++)
#pragma unroll
            for (int j = 0; j < 4; j++) acc[i][j] = 0.f;
#pragma unroll
        for (int n2 = 0; n2 < 8; n2++) {
#pragma unroll
            for (int k = 0; k < 8; k++) {
                uint32_t bh[4], bl[4];
                uint32_t ba = (k * 16 + l16) * PP_PITCH_W + (p * 128 + n2 * 16) * 2 +
                              (lane >> 4) * 16;
                ldmx4t(bh, sb + PSM_WH + ba);
                ldmx4t(bl, sb + PSM_WL + ba);
                mma_f16(acc[2 * n2],     ahf[k], bh);
                mma_f16(acc[2 * n2],     ahf[k], bl);
                mma_f16(acc[2 * n2],     alf[k], bh);
                mma_f16(acc[2 * n2 + 1], ahf[k], bh + 2);
                mma_f16(acc[2 * n2 + 1], ahf[k], bl + 2);
                mma_f16(acc[2 * n2 + 1], alf[k], bh + 2);
            }
        }
        float* base = (p == 0) ? g_Pr : g_Pc;
#pragma unroll
        for (int n2 = 0; n2 < 8; n2++) {
#pragma unroll
            for (int hlf = 0; hlf < 2; hlf++) {
                int col = n2 * 16 + hlf * 8 + qcol;
                float* a = acc[2 * n2 + hlf];
                if (node_lo < N)
                    *(float2*)(base + (size_t)node_lo * OD + col) = make_float2(a[0], a[1]);
                if (node_hi < N)
                    *(float2*)(base + (size_t)node_hi * OD + col) = make_float2(a[2], a[3]);
            }
        }
    }
}

// ---------------------------------------------------------------------------
// Persistent HMMA edge kernel, 2 CTAs/SM, streaming strips (low regs).
__global__ __launch_bounds__(256, 2) void mpnn_edge_mma_kernel(
    const void* __restrict__ edge_index_raw,
    const float* __restrict__ edge_features,
    const float* __restrict__ b1g,
    const float* __restrict__ b2g,
    float* __restrict__ out,
    long long E, int n_tiles) {
    extern __shared__ char sm[];
    const uint32_t sb = smem_u32(sm);
    const int tid = threadIdx.x;
    const int wid = tid >> 5;
    const int lane = tid & 31;
    const int is64 = g_idx64;

    int* s_rows = (int*)(sm + SM_ROWS);
    int* s_cols = (int*)(sm + SM_COLS);

    for (int t = tid; t < 2048; t += 256) {
        int k = t >> 4, n8 = (t & 15) << 3;
        *(uint4*)(sm + SM_W2H + k * PITCH_W_B + n8 * 2) = *(const uint4*)(g_W2h + k * OD + n8);
    }
    for (int t = tid; t < 512; t += 256) {
        int k = t >> 4, n8 = (t & 15) << 3;
        *(uint4*)(sm + SM_W1H + k * PITCH_W_B + n8 * 2) = *(const uint4*)(g_W1ch + k * OD + n8);
    }
    if (tid < 128) {
        ((float*)(sm + SM_B1))[tid] = b1g[tid];
        ((float*)(sm + SM_B2))[tid] = b2g[tid];
    }
    __syncthreads();

    const int m0 = wid * 16;
    const int qrow = lane >> 2;
    const int qcol = (lane & 3) * 2;
    const int l16 = lane & 15;
    const uint32_t efA = sb + SM_EFH + (m0 + l16) * PITCH_EF_B + ((lane >> 4) * 8) * 2;
    const uint32_t blane_off = l16 * PITCH_W_B + (lane >> 4) * 16;

    for (int tile = blockIdx.x; tile < n_tiles; tile += gridDim.x) {
        const long long e0 = (long long)tile * TE;
        __syncthreads();

        // ---- stage indices ----
        if (tid < TE) {
            long long e = e0 + tid;
            int r = 0, c = 0;
            if (e < E) {
                if (is64) {
                    r = (int)((const long long*)edge_index_raw)[e];
                    c = (int)((const long long*)edge_index_raw)[E + e];
                } else {
                    r = ((const int*)edge_index_raw)[e];
                    c = ((const int*)edge_index_raw)[E + e];
                }
            }
            s_rows[tid] = r; s_cols[tid] = c;
        }
        // ---- stage edge features (fp32 -> fp16) ----
        {
            int er = tid >> 1;
            int c0 = (tid & 1) * 16;
            long long e = e0 + er;
            float v[16];
            if (e < E) {
                const float4* p = (const float4*)(edge_features + e * ED + c0);
#pragma unroll
                for (int q = 0; q < 4; q++) {
                    float4 f = p[q];
                    v[q * 4 + 0] = f.x; v[q * 4 + 1] = f.y; v[q * 4 + 2] = f.z; v[q * 4 + 3] = f.w;
                }
            } else {
#pragma unroll
                for (int q = 0; q < 16; q++) v[q] = 0.f;
            }
            uint32_t hv[8];
#pragma unroll
            for (int q = 0; q < 8; q++) hv[q] = pack2h(v[2 * q], v[2 * q + 1]);
            char* ph = sm + SM_EFH + er * PITCH_EF_B + c0 * 2;
            *(uint4*)(ph) = make_uint4(hv[0], hv[1], hv[2], hv[3]);
            *(uint4*)(ph + 16) = make_uint4(hv[4], hv[5], hv[6], hv[7]);
        }
        __syncthreads();

        const int e_lo = m0 + qrow, e_hi = e_lo + 8;
        const int r_lo = s_rows[e_lo], r_hi = s_rows[e_hi];
        const int c_lo = s_cols[e_lo], c_hi = s_cols[e_hi];
        const bool v_lo = (e0 + e_lo) < E;
        const bool v_hi = (e0 + e_hi) < E;
        const float* prl_base = g_Pr + (size_t)r_lo * OD;
        const float* prh_base = g_Pr + (size_t)r_hi * OD;
        const float* pcl_base = g_Pc + (size_t)c_lo * OD;
        const float* pch_base = g_Pc + (size_t)c_hi * OD;

        // ---- A frags of ef ----
        uint32_t eh[2][4];
        ldmx4(eh[0], efA);
        ldmx4(eh[1], efA + 32);

        // ---- GEMM1 + epilogue1, streamed in 4-chunk groups ----
        uint32_t ah[8][4];
#pragma unroll
        for (int g = 0; g < 4; g++) {
            // gather 4 chunks (cols 32g .. 32g+31)
            float2 prl[4], prh[4], pcl[4], pch[4];
#pragma unroll
            for (int cc = 0; cc < 4; cc++) {
                int col = (4 * g + cc) * 8 + qcol;
                prl[cc] = *(const float2*)(prl_base + col);
                prh[cc] = *(const float2*)(prh_base + col);
                pcl[cc] = *(const float2*)(pcl_base + col);
                pch[cc] = *(const float2*)(pch_base + col);
            }
#pragma unroll
            for (int t = 0; t < 2; t++) {
                int n2 = 2 * g + t;
                float a8[8];
#pragma unroll
                for (int j = 0; j < 8; j++) a8[j] = 0.f;
#pragma unroll
                for (int k = 0; k < 2; k++) {
                    uint32_t b[4];
                    ldmx4t(b, sb + SM_W1H + k * 16 * PITCH_W_B + n2 * 32 + blane_off);
                    mma_f16(a8,     eh[k], b);
                    mma_f16(a8 + 4, eh[k], b + 2);
                }
#pragma unroll
                for (int u = 0; u < 2; u++) {
                    int cc = 2 * t + u;
                    int c = 4 * g + cc;
                    float2 b1c = *(const float2*)(sm + SM_B1 + (c * 8 + qcol) * 4);
                    float h0 = fmaxf(a8[u*4+0] + prl[cc].x + pcl[cc].x + b1c.x, 0.f);
                    float h1 = fmaxf(a8[u*4+1] + prl[cc].y + pcl[cc].y + b1c.y, 0.f);
                    float h2 = fmaxf(a8[u*4+2] + prh[cc].x + pch[cc].x + b1c.x, 0.f);
                    float h3 = fmaxf(a8[u*4+3] + prh[cc].y + pch[cc].y + b1c.y, 0.f);
                    ah[c >> 1][(c & 1) * 2]     = pack2h(h0, h1);
                    ah[c >> 1][(c & 1) * 2 + 1] = pack2h(h2, h3);
                }
            }
        }

        // ---- GEMM2 + scatter, streamed per 16-col strip ----
        float* dlo = out + (size_t)r_lo * OD;
        float* dhi = out + (size_t)r_hi * OD;
#pragma unroll
        for (int n2 = 0; n2 < 8; n2++) {
            float a8[8];
#pragma unroll
            for (int j = 0; j < 8; j++) a8[j] = 0.f;
#pragma unroll
            for (int k = 0; k < 8; k++) {
                uint32_t b[4];
                ldmx4t(b, sb + SM_W2H + k * 16 * PITCH_W_B + n2 * 32 + blane_off);
                mma_f16(a8,     ah[k], b);
                mma_f16(a8 + 4, ah[k], b + 2);
            }
#pragma unroll
            for (int u = 0; u < 2; u++) {
                int col = (2 * n2 + u) * 8 + qcol;
                float2 b2c = *(const float2*)(sm + SM_B2 + col * 4);
                if (v_lo) {
                    float x0 = a8[u*4+0] + b2c.x, x1 = a8[u*4+1] + b2c.y;
                    asm volatile("red.global.add.v2.f32 [%0], {%1,%2};"
                                 :: "l"(dlo + col), "f"(x0), "f"(x1) : "memory");
                }
                if (v_hi) {
                    float x0 = a8[u*4+2] + b2c.x, x1 = a8[u*4+3] + b2c.y;
                    asm volatile("red.global.add.v2.f32 [%0], {%1,%2};"
                                 :: "l"(dhi + col), "f"(x0), "f"(x1) : "memory");
                }
            }
        }
    }
}

// ---------------------------------------------------------------------------
extern "C" void kernel_launch(void* const* d_in, const int* in_sizes, int n_in,
                              void* d_out, int out_size) {
    const float* h = (const float*)d_in[0];
    const void* edge_index = d_in[1];
    const float* ef = (const float*)d_in[2];
    const float *W1 = 0, *b1 = 0, *W2 = 0, *b2 = 0;
    for (int i = 3; i < n_in; i++) {
        int s = in_sizes[i];
        if (s == (2 * ND + ED) * OD) W1 = (const float*)d_in[i];
        else if (s == OD * OD) W2 = (const float*)d_in[i];
        else if (s == OD) { if (!b1) b1 = (const float*)d_in[i]; else b2 = (const float*)d_in[i]; }
    }
    if (!W1 || !b1 || !W2 || !b2) return;

    int N = in_sizes[0] / ND;
    if (N > MAXN) N = MAXN;
    long long E = (long long)(in_sizes[1] / 2);
    float* out = (float*)d_out;
    int n_tiles = (int)((E + TE - 1) / TE);

    zero_out_kernel<<<(out_size + 255) / 256, 256>>>(out, out_size);
    detect_idx_kernel<<<1, 32>>>((const int*)edge_index);
    prep_weights_kernel<<<128, 256>>>(W1, W2);

    cudaFuncSetAttribute(precompute_P_mma_kernel,
                         cudaFuncAttributeMaxDynamicSharedMemorySize, PSM_TOTAL);
    precompute_P_mma_kernel<<<(N + 127) / 128, 256, PSM_TOTAL>>>(h, N);

    cudaFuncSetAttribute(mpnn_edge_mma_kernel,
                         cudaFuncAttributeMaxDynamicSharedMemorySize, SM_TOTAL);
    int grid = 2 * NSM;
    if (grid > n_tiles) grid = n_tiles;
    mpnn_edge_mma_kernel<<<grid, 256, SM_TOTAL>>>(
        edge_index, ef, b1, b2, out, E, n_tiles);
}

// round 7
// speedup vs baseline: 3.6478x; 1.0634x over previous
#include <cuda_runtime.h>
#include <cuda_fp16.h>
#include <stdint.h>
#include <stddef.h>

#define ND 128
#define ED 32
#define OD 128
#define TE 128
#define MAXN 10000
#define NSM 148

// ---------------- device scratch ----------------
__device__ float g_Pr[MAXN * OD];
__device__ float g_Pc[MAXN * OD];
__device__ float g_H[MAXN * OD];         // scatter-accumulated hidden
__device__ int   g_deg[MAXN];
__device__ int   g_idx64;
__device__ __half g_W1ch[ED * OD];       // [k][n] fp16 (W1 rows 256..287)
__device__ __half g_Wab_hi[ND * 256];    // [k][n]: n<128 -> W1a, n>=128 -> W1b
__device__ __half g_Wab_lo[ND * 256];
__device__ __half g_W2_hi[OD * OD];      // [k][n]
__device__ __half g_W2_lo[OD * OD];

// ---------------- edge-kernel smem ----------------
#define PITCH_EF_B 80
#define PITCH_W_B  272
#define E_ROWS 0
#define E_COLS 512
#define E_B1   1024
#define E_EF   2048                      // 128*80 = 10240
#define E_W1   12288                     // 32*272 = 8704
#define E_TOTAL 20992

// ---------------- precompute / final GEMM smem (shared layout) ----------------
#define F_AH 0                           // 128*272 = 34816 (A hi)
#define F_AL 34816                       // A lo
#define F_WH 69632                       // W hi (128 rows x 128 cols)
#define F_WL 104448                      // W lo
#define F_B2 139264                      // float[128]
#define F_DEG 139776                     // float[128]
#define F_TOTAL 140288

// ---------------- helpers ----------------
__device__ __forceinline__ uint32_t smem_u32(const void* p) {
    uint32_t a;
    asm("{ .reg .u64 t; cvta.to.shared.u64 t, %1; cvt.u32.u64 %0, t; }" : "=r"(a) : "l"(p));
    return a;
}
__device__ __forceinline__ void ldmx4(uint32_t* r, uint32_t addr) {
    asm volatile("ldmatrix.sync.aligned.m8n8.x4.shared.b16 {%0,%1,%2,%3}, [%4];"
                 : "=r"(r[0]), "=r"(r[1]), "=r"(r[2]), "=r"(r[3]) : "r"(addr));
}
__device__ __forceinline__ void ldmx4t(uint32_t* r, uint32_t addr) {
    asm volatile("ldmatrix.sync.aligned.m8n8.x4.trans.shared.b16 {%0,%1,%2,%3}, [%4];"
                 : "=r"(r[0]), "=r"(r[1]), "=r"(r[2]), "=r"(r[3]) : "r"(addr));
}
__device__ __forceinline__ void mma_f16(float* d, const uint32_t* a, const uint32_t* b) {
    asm volatile(
        "mma.sync.aligned.m16n8k16.row.col.f32.f16.f16.f32 "
        "{%0,%1,%2,%3},{%4,%5,%6,%7},{%8,%9},{%0,%1,%2,%3};"
        : "+f"(d[0]), "+f"(d[1]), "+f"(d[2]), "+f"(d[3])
        : "r"(a[0]), "r"(a[1]), "r"(a[2]), "r"(a[3]), "r"(b[0]), "r"(b[1]));
}
__device__ __forceinline__ uint32_t pack2h(float x0, float x1) {  // x0 -> low half
    uint32_t r;
    asm("cvt.rn.f16x2.f32 %0, %1, %2;" : "=r"(r) : "f"(x1), "f"(x0));
    return r;
}
__device__ __forceinline__ void split2h(float x0, float x1, uint32_t& hi, uint32_t& lo) {
    __half h0 = __float2half_rn(x0);
    __half h1 = __float2half_rn(x1);
    hi = ((uint32_t)__half_as_ushort(h1) << 16) | __half_as_ushort(h0);
    lo = pack2h(x0 - __half2float(h0), x1 - __half2float(h1));
}

// ---------------------------------------------------------------------------
__global__ void zero_scratch_kernel(int nH, int nDeg) {
    int i = blockIdx.x * blockDim.x + threadIdx.x;
    if (i < nH) g_H[i] = 0.0f;
    if (i < nDeg) g_deg[i] = 0;
}
__global__ void detect_idx_kernel(const int* __restrict__ ei) {
    if (threadIdx.x == 0) {
        int nz = 0;
        for (int i = 0; i < 64; i++)
            if (ei[2 * i + 1] != 0) nz++;
        g_idx64 = (nz == 0) ? 1 : 0;
    }
}
__global__ void prep_weights_kernel(const float* __restrict__ W1, const float* __restrict__ W2) {
    int t = blockIdx.x * blockDim.x + threadIdx.x;
    if (t < OD * OD) {
        float x = W2[t];
        __half hh = __float2half_rn(x);
        g_W2_hi[t] = hh;
        g_W2_lo[t] = __float2half_rn(x - __half2float(hh));
    }
    if (t < ED * OD) g_W1ch[t] = __float2half_rn(W1[(size_t)(2 * ND) * OD + t]);
    if (t < ND * 256) {
        int k = t >> 8, n = t & 255;
        float x = (n < 128) ? W1[(size_t)k * OD + n] : W1[(size_t)(ND + k) * OD + (n - 128)];
        __half hh = __float2half_rn(x);
        g_Wab_hi[t] = hh;
        g_Wab_lo[t] = __float2half_rn(x - __half2float(hh));
    }
}

// ---------------------------------------------------------------------------
// HMMA precompute: grid (nb, 2). blockIdx.y==0 -> Pr = h@W1a ; ==1 -> Pc = h@W1b.
// 3-term hi/lo split (~fp32 accuracy). 128 nodes x 128 cols per block.
__global__ __launch_bounds__(256, 1) void precompute_P_mma_kernel(
    const float* __restrict__ h, int N) {
    extern __shared__ char sm[];
    const uint32_t sb = smem_u32(sm);
    const int tid = threadIdx.x;
    const int wid = tid >> 5;
    const int lane = tid & 31;
    const int l16 = lane & 15;
    const int qrow = lane >> 2;
    const int qcol = (lane & 3) * 2;
    const int n0 = blockIdx.x * 128;
    const int p = blockIdx.y;

    // stage h (fp32 -> hi/lo fp16)
    {
        int row = tid >> 1, c0 = (tid & 1) * 64;
        int node = n0 + row;
        char* ph = sm + F_AH + row * PITCH_W_B + c0 * 2;
        char* pl = sm + F_AL + row * PITCH_W_B + c0 * 2;
#pragma unroll
        for (int q = 0; q < 8; q++) {
            float4 f0 = make_float4(0.f, 0.f, 0.f, 0.f), f1 = f0;
            if (node < N) {
                f0 = *(const float4*)(h + (size_t)node * ND + c0 + q * 8);
                f1 = *(const float4*)(h + (size_t)node * ND + c0 + q * 8 + 4);
            }
            uint32_t h0, l0, h1, l1, h2, l2, h3, l3;
            split2h(f0.x, f0.y, h0, l0); split2h(f0.z, f0.w, h1, l1);
            split2h(f1.x, f1.y, h2, l2); split2h(f1.z, f1.w, h3, l3);
            *(uint4*)(ph + q * 16) = make_uint4(h0, h1, h2, h3);
            *(uint4*)(pl + q * 16) = make_uint4(l0, l1, l2, l3);
        }
    }
    // stage W half (hi/lo)
    for (int t = tid; t < 2048; t += 256) {
        int k = t >> 4, c8 = (t & 15) << 3;
        *(uint4*)(sm + F_WH + k * PITCH_W_B + c8 * 2) =
            *(const uint4*)(g_Wab_hi + k * 256 + p * 128 + c8);
        *(uint4*)(sm + F_WL + k * PITCH_W_B + c8 * 2) =
            *(const uint4*)(g_Wab_lo + k * 256 + p * 128 + c8);
    }
    __syncthreads();

    const int m0 = wid * 16;
    uint32_t ahf[8][4], alf[8][4];
    {
        uint32_t ab_h = sb + F_AH + (m0 + l16) * PITCH_W_B + (lane >> 4) * 16;
        uint32_t ab_l = sb + F_AL + (m0 + l16) * PITCH_W_B + (lane >> 4) * 16;
#pragma unroll
        for (int k = 0; k < 8; k++) {
            ldmx4(ahf[k], ab_h + k * 32);
            ldmx4(alf[k], ab_l + k * 32);
        }
    }

    float acc[16][4];
#pragma unroll
    for (int i = 0; i < 16; i++)
#pragma unroll
        for (int j = 0; j < 4; j++) acc[i][j] = 0.f;
#pragma unroll
    for (int n2 = 0; n2 < 8; n2++) {
#pragma unroll
        for (int k = 0; k < 8; k++) {
            uint32_t bh[4], bl[4];
            uint32_t ba = (k * 16 + l16) * PITCH_W_B + n2 * 32 + (lane >> 4) * 16;
            ldmx4t(bh, sb + F_WH + ba);
            ldmx4t(bl, sb + F_WL + ba);
            mma_f16(acc[2 * n2],     ahf[k], bh);
            mma_f16(acc[2 * n2],     ahf[k], bl);
            mma_f16(acc[2 * n2],     alf[k], bh);
            mma_f16(acc[2 * n2 + 1], ahf[k], bh + 2);
            mma_f16(acc[2 * n2 + 1], ahf[k], bl + 2);
            mma_f16(acc[2 * n2 + 1], alf[k], bh + 2);
        }
    }
    float* base = (p == 0) ? g_Pr : g_Pc;
    const int node_lo = n0 + m0 + qrow;
    const int node_hi = node_lo + 8;
#pragma unroll
    for (int n2 = 0; n2 < 8; n2++) {
#pragma unroll
        for (int hlf = 0; hlf < 2; hlf++) {
            int col = n2 * 16 + hlf * 8 + qcol;
            float* a = acc[2 * n2 + hlf];
            if (node_lo < N)
                *(float2*)(base + (size_t)node_lo * OD + col) = make_float2(a[0], a[1]);
            if (node_hi < N)
                *(float2*)(base + (size_t)node_hi * OD + col) = make_float2(a[2], a[3]);
        }
    }
}

// ---------------------------------------------------------------------------
// Edge kernel: hidden = relu(Pr[r]+Pc[c]+ef@W1c+b1) -> RED into g_H[r].
// Only GEMM1 on tensor cores (32 MMAs/warp/tile). 3 CTAs/SM persistent.
__global__ __launch_bounds__(256, 3) void edge_hidden_kernel(
    const void* __restrict__ edge_index_raw,
    const float* __restrict__ edge_features,
    const float* __restrict__ b1g,
    long long E, int n_tiles) {
    extern __shared__ char sm[];
    const uint32_t sb = smem_u32(sm);
    const int tid = threadIdx.x;
    const int wid = tid >> 5;
    const int lane = tid & 31;
    const int is64 = g_idx64;

    int* s_rows = (int*)(sm + E_ROWS);
    int* s_cols = (int*)(sm + E_COLS);

    for (int t = tid; t < 512; t += 256) {
        int k = t >> 4, n8 = (t & 15) << 3;
        *(uint4*)(sm + E_W1 + k * PITCH_W_B + n8 * 2) = *(const uint4*)(g_W1ch + k * OD + n8);
    }
    if (tid < 128) ((float*)(sm + E_B1))[tid] = b1g[tid];
    __syncthreads();

    const int m0 = wid * 16;
    const int qrow = lane >> 2;
    const int qcol = (lane & 3) * 2;
    const int l16 = lane & 15;
    const uint32_t efA = sb + E_EF + (m0 + l16) * PITCH_EF_B + ((lane >> 4) * 8) * 2;
    const uint32_t blane_off = l16 * PITCH_W_B + (lane >> 4) * 16;

    for (int tile = blockIdx.x; tile < n_tiles; tile += gridDim.x) {
        const long long e0 = (long long)tile * TE;
        __syncthreads();

        // stage indices (+deg)
        if (tid < TE) {
            long long e = e0 + tid;
            int r = 0, c = 0;
            if (e < E) {
                if (is64) {
                    r = (int)((const long long*)edge_index_raw)[e];
                    c = (int)((const long long*)edge_index_raw)[E + e];
                } else {
                    r = ((const int*)edge_index_raw)[e];
                    c = ((const int*)edge_index_raw)[E + e];
                }
                atomicAdd(&g_deg[r], 1);
            }
            s_rows[tid] = r; s_cols[tid] = c;
        }
        // stage edge features (fp32 -> fp16)
        {
            int er = tid >> 1;
            int c0 = (tid & 1) * 16;
            long long e = e0 + er;
            float v[16];
            if (e < E) {
                const float4* p = (const float4*)(edge_features + e * ED + c0);
#pragma unroll
                for (int q = 0; q < 4; q++) {
                    float4 f = p[q];
                    v[q * 4 + 0] = f.x; v[q * 4 + 1] = f.y; v[q * 4 + 2] = f.z; v[q * 4 + 3] = f.w;
                }
            } else {
#pragma unroll
                for (int q = 0; q < 16; q++) v[q] = 0.f;
            }
            uint32_t hv[8];
#pragma unroll
            for (int q = 0; q < 8; q++) hv[q] = pack2h(v[2 * q], v[2 * q + 1]);
            char* ph = sm + E_EF + er * PITCH_EF_B + c0 * 2;
            *(uint4*)(ph) = make_uint4(hv[0], hv[1], hv[2], hv[3]);
            *(uint4*)(ph + 16) = make_uint4(hv[4], hv[5], hv[6], hv[7]);
        }
        __syncthreads();

        const int e_lo = m0 + qrow, e_hi = e_lo + 8;
        const int r_lo = s_rows[e_lo], r_hi = s_rows[e_hi];
        const int c_lo = s_cols[e_lo], c_hi = s_cols[e_hi];
        const bool v_lo = (e0 + e_lo) < E;
        const bool v_hi = (e0 + e_hi) < E;
        const float* prl_base = g_Pr + (size_t)r_lo * OD;
        const float* prh_base = g_Pr + (size_t)r_hi * OD;
        const float* pcl_base = g_Pc + (size_t)c_lo * OD;
        const float* pch_base = g_Pc + (size_t)c_hi * OD;
        float* Hlo = g_H + (size_t)r_lo * OD;
        float* Hhi = g_H + (size_t)r_hi * OD;

        uint32_t eh[2][4];
        ldmx4(eh[0], efA);
        ldmx4(eh[1], efA + 32);

#pragma unroll
        for (int g = 0; g < 4; g++) {
            float2 prl[4], prh[4], pcl[4], pch[4];
#pragma unroll
            for (int cc = 0; cc < 4; cc++) {
                int col = (4 * g + cc) * 8 + qcol;
                prl[cc] = *(const float2*)(prl_base + col);
                prh[cc] = *(const float2*)(prh_base + col);
                pcl[cc] = *(const float2*)(pcl_base + col);
                pch[cc] = *(const float2*)(pch_base + col);
            }
#pragma unroll
            for (int t = 0; t < 2; t++) {
                int n2 = 2 * g + t;
                float a8[8];
#pragma unroll
                for (int j = 0; j < 8; j++) a8[j] = 0.f;
#pragma unroll
                for (int k = 0; k < 2; k++) {
                    uint32_t b[4];
                    ldmx4t(b, sb + E_W1 + k * 16 * PITCH_W_B + n2 * 32 + blane_off);
                    mma_f16(a8,     eh[k], b);
                    mma_f16(a8 + 4, eh[k], b + 2);
                }
#pragma unroll
                for (int u = 0; u < 2; u++) {
                    int cc = 2 * t + u;
                    int c = 4 * g + cc;
                    int col = c * 8 + qcol;
                    float2 b1c = *(const float2*)(sm + E_B1 + col * 4);
                    float h0 = fmaxf(a8[u*4+0] + prl[cc].x + pcl[cc].x + b1c.x, 0.f);
                    float h1 = fmaxf(a8[u*4+1] + prl[cc].y + pcl[cc].y + b1c.y, 0.f);
                    float h2 = fmaxf(a8[u*4+2] + prh[cc].x + pch[cc].x + b1c.x, 0.f);
                    float h3 = fmaxf(a8[u*4+3] + prh[cc].y + pch[cc].y + b1c.y, 0.f);
                    if (v_lo)
                        asm volatile("red.global.add.v2.f32 [%0], {%1,%2};"
                                     :: "l"(Hlo + col), "f"(h0), "f"(h1) : "memory");
                    if (v_hi)
                        asm volatile("red.global.add.v2.f32 [%0], {%1,%2};"
                                     :: "l"(Hhi + col), "f"(h2), "f"(h3) : "memory");
                }
            }
        }
    }
}

// ---------------------------------------------------------------------------
// Final: out = g_H @ W2 + deg * b2   (3-term hi/lo split, ~fp32 accuracy)
__global__ __launch_bounds__(256, 1) void final_out_mma_kernel(
    const float* __restrict__ b2g, float* __restrict__ out, int N) {
    extern __shared__ char sm[];
    const uint32_t sb = smem_u32(sm);
    const int tid = threadIdx.x;
    const int wid = tid >> 5;
    const int lane = tid & 31;
    const int l16 = lane & 15;
    const int qrow = lane >> 2;
    const int qcol = (lane & 3) * 2;
    const int n0 = blockIdx.x * 128;

    // stage H (fp32 -> hi/lo fp16)
    {
        int row = tid >> 1, c0 = (tid & 1) * 64;
        int node = n0 + row;
        char* ph = sm + F_AH + row * PITCH_W_B + c0 * 2;
        char* pl = sm + F_AL + row * PITCH_W_B + c0 * 2;
#pragma unroll
        for (int q = 0; q < 8; q++) {
            float4 f0 = make_float4(0.f, 0.f, 0.f, 0.f), f1 = f0;
            if (node < N) {
                f0 = *(const float4*)(g_H + (size_t)node * OD + c0 + q * 8);
                f1 = *(const float4*)(g_H + (size_t)node * OD + c0 + q * 8 + 4);
            }
            uint32_t h0, l0, h1, l1, h2, l2, h3, l3;
            split2h(f0.x, f0.y, h0, l0); split2h(f0.z, f0.w, h1, l1);
            split2h(f1.x, f1.y, h2, l2); split2h(f1.z, f1.w, h3, l3);
            *(uint4*)(ph + q * 16) = make_uint4(h0, h1, h2, h3);
            *(uint4*)(pl + q * 16) = make_uint4(l0, l1, l2, l3);
        }
    }
    // stage W2 hi/lo
    for (int t = tid; t < 2048; t += 256) {
        int k = t >> 4, c8 = (t & 15) << 3;
        *(uint4*)(sm + F_WH + k * PITCH_W_B + c8 * 2) = *(const uint4*)(g_W2_hi + k * OD + c8);
        *(uint4*)(sm + F_WL + k * PITCH_W_B + c8 * 2) = *(const uint4*)(g_W2_lo + k * OD + c8);
    }
    if (tid < 128) {
        int node = n0 + tid;
        ((float*)(sm + F_B2))[tid] = b2g[tid];
        ((float*)(sm + F_DEG))[tid] = (node < N) ? (float)g_deg[node] : 0.f;
    }
    __syncthreads();

    const int m0 = wid * 16;
    uint32_t ahf[8][4], alf[8][4];
    {
        uint32_t ab_h = sb + F_AH + (m0 + l16) * PITCH_W_B + (lane >> 4) * 16;
        uint32_t ab_l = sb + F_AL + (m0 + l16) * PITCH_W_B + (lane >> 4) * 16;
#pragma unroll
        for (int k = 0; k < 8; k++) {
            ldmx4(ahf[k], ab_h + k * 32);
            ldmx4(alf[k], ab_l + k * 32);
        }
    }

    float acc[16][4];
#pragma unroll
    for (int i = 0; i < 16; i++)
#pragma unroll
        for (int j = 0; j < 4; j++) acc[i][j] = 0.f;
#pragma unroll
    for (int n2 = 0; n2 < 8; n2++) {
#pragma unroll
        for (int k = 0; k < 8; k++) {
            uint32_t bh[4], bl[4];
            uint32_t ba = (k * 16 + l16) * PITCH_W_B + n2 * 32 + (lane >> 4) * 16;
            ldmx4t(bh, sb + F_WH + ba);
            ldmx4t(bl, sb + F_WL + ba);
            mma_f16(acc[2 * n2],     ahf[k], bh);
            mma_f16(acc[2 * n2],     ahf[k], bl);
            mma_f16(acc[2 * n2],     alf[k], bh);
            mma_f16(acc[2 * n2 + 1], ahf[k], bh + 2);
            mma_f16(acc[2 * n2 + 1], ahf[k], bl + 2);
            mma_f16(acc[2 * n2 + 1], alf[k], bh + 2);
        }
    }

    const int node_lo = n0 + m0 + qrow;
    const int node_hi = node_lo + 8;
    const float deg_lo = ((float*)(sm + F_DEG))[m0 + qrow];
    const float deg_hi = ((float*)(sm + F_DEG))[m0 + qrow + 8];
#pragma unroll
    for (int n2 = 0; n2 < 8; n2++) {
#pragma unroll
        for (int hlf = 0; hlf < 2; hlf++) {
            int col = n2 * 16 + hlf * 8 + qcol;
            float2 b2c = *(const float2*)(sm + F_B2 + col * 4);
            float* a = acc[2 * n2 + hlf];
            if (node_lo < N)
                *(float2*)(out + (size_t)node_lo * OD + col) =
                    make_float2(a[0] + deg_lo * b2c.x, a[1] + deg_lo * b2c.y);
            if (node_hi < N)
                *(float2*)(out + (size_t)node_hi * OD + col) =
                    make_float2(a[2] + deg_hi * b2c.x, a[3] + deg_hi * b2c.y);
        }
    }
}

// ---------------------------------------------------------------------------
extern "C" void kernel_launch(void* const* d_in, const int* in_sizes, int n_in,
                              void* d_out, int out_size) {
    const float* h = (const float*)d_in[0];
    const void* edge_index = d_in[1];
    const float* ef = (const float*)d_in[2];
    const float *W1 = 0, *b1 = 0, *W2 = 0, *b2 = 0;
    for (int i = 3; i < n_in; i++) {
        int s = in_sizes[i];
        if (s == (2 * ND + ED) * OD) W1 = (const float*)d_in[i];
        else if (s == OD * OD) W2 = (const float*)d_in[i];
        else if (s == OD) { if (!b1) b1 = (const float*)d_in[i]; else b2 = (const float*)d_in[i]; }
    }
    if (!W1 || !b1 || !W2 || !b2) return;

    int N = in_sizes[0] / ND;
    if (N > MAXN) N = MAXN;
    long long E = (long long)(in_sizes[1] / 2);
    float* out = (float*)d_out;
    int n_tiles = (int)((E + TE - 1) / TE);
    int nb = (N + 127) / 128;

    zero_scratch_kernel<<<(N * OD + 255) / 256, 256>>>(N * OD, N);
    detect_idx_kernel<<<1, 32>>>((const int*)edge_index);
    prep_weights_kernel<<<128, 256>>>(W1, W2);

    cudaFuncSetAttribute(precompute_P_mma_kernel,
                         cudaFuncAttributeMaxDynamicSharedMemorySize, F_TOTAL);
    dim3 pgrid(nb, 2);
    precompute_P_mma_kernel<<<pgrid, 256, F_TOTAL>>>(h, N);

    int egrid = 3 * NSM;
    if (egrid > n_tiles) egrid = n_tiles;
    edge_hidden_kernel<<<egrid, 256, E_TOTAL>>>(edge_index, ef, b1, E, n_tiles);

    cudaFuncSetAttribute(final_out_mma_kernel,
                         cudaFuncAttributeMaxDynamicSharedMemorySize, F_TOTAL);
    final_out_mma_kernel<<<nb, 256, F_TOTAL>>>(b2, out, N);
}

// round 8
// speedup vs baseline: 3.8892x; 1.0662x over previous
#include <cuda_runtime.h>
#include <cuda_fp16.h>
#include <stdint.h>
#include <stddef.h>

#define ND 128
#define ED 32
#define OD 128
#define TE 128
#define MAXN 10000
#define MAXE 1048576
#define NSM 148

// ---------------- device scratch ----------------
__device__ float g_Pr[MAXN * OD];
__device__ float g_Pc[MAXN * OD];
__device__ float g_H[MAXN * OD];
__device__ int   g_cnt[MAXN];        // degree (histogram)
__device__ int   g_pos[MAXN];        // scatter cursor
__device__ int   g_srows[MAXE];
__device__ int   g_scols[MAXE];
__device__ int   g_perm[MAXE];
__device__ int   g_idx64;
__device__ __half g_W1ch[ED * OD];
__device__ __half g_Wab_hi[ND * 256];
__device__ __half g_Wab_lo[ND * 256];
__device__ __half g_W2_hi[OD * OD];
__device__ __half g_W2_lo[OD * OD];

// ---------------- edge-kernel smem ----------------
#define PITCH_EF_B 80
#define PITCH_W_B  272
#define E_ROWS 0
#define E_COLS 512
#define E_B1   1024
#define E_EF   2048                      // 128*80 = 10240
#define E_W1   12288                     // 32*272 = 8704
#define E_TOTAL 20992

// ---------------- precompute / final GEMM smem ----------------
#define F_AH 0
#define F_AL 34816
#define F_WH 69632
#define F_WL 104448
#define F_B2 139264
#define F_DEG 139776
#define F_TOTAL 140288

// ---------------- helpers ----------------
__device__ __forceinline__ uint32_t smem_u32(const void* p) {
    uint32_t a;
    asm("{ .reg .u64 t; cvta.to.shared.u64 t, %1; cvt.u32.u64 %0, t; }" : "=r"(a) : "l"(p));
    return a;
}
__device__ __forceinline__ void ldmx4(uint32_t* r, uint32_t addr) {
    asm volatile("ldmatrix.sync.aligned.m8n8.x4.shared.b16 {%0,%1,%2,%3}, [%4];"
                 : "=r"(r[0]), "=r"(r[1]), "=r"(r[2]), "=r"(r[3]) : "r"(addr));
}
__device__ __forceinline__ void ldmx4t(uint32_t* r, uint32_t addr) {
    asm volatile("ldmatrix.sync.aligned.m8n8.x4.trans.shared.b16 {%0,%1,%2,%3}, [%4];"
                 : "=r"(r[0]), "=r"(r[1]), "=r"(r[2]), "=r"(r[3]) : "r"(addr));
}
__device__ __forceinline__ void mma_f16(float* d, const uint32_t* a, const uint32_t* b) {
    asm volatile(
        "mma.sync.aligned.m16n8k16.row.col.f32.f16.f16.f32 "
        "{%0,%1,%2,%3},{%4,%5,%6,%7},{%8,%9},{%0,%1,%2,%3};"
        : "+f"(d[0]), "+f"(d[1]), "+f"(d[2]), "+f"(d[3])
        : "r"(a[0]), "r"(a[1]), "r"(a[2]), "r"(a[3]), "r"(b[0]), "r"(b[1]));
}
__device__ __forceinline__ uint32_t pack2h(float x0, float x1) {
    uint32_t r;
    asm("cvt.rn.f16x2.f32 %0, %1, %2;" : "=r"(r) : "f"(x1), "f"(x0));
    return r;
}
__device__ __forceinline__ void split2h(float x0, float x1, uint32_t& hi, uint32_t& lo) {
    __half h0 = __float2half_rn(x0);
    __half h1 = __float2half_rn(x1);
    hi = ((uint32_t)__half_as_ushort(h1) << 16) | __half_as_ushort(h0);
    lo = pack2h(x0 - __half2float(h0), x1 - __half2float(h1));
}

// ---------------------------------------------------------------------------
__global__ void zero_scratch_kernel(int nH, int nCnt) {
    int i = blockIdx.x * blockDim.x + threadIdx.x;
    if (i < nH) g_H[i] = 0.0f;
    if (i < nCnt) g_cnt[i] = 0;
}
__global__ void detect_idx_kernel(const int* __restrict__ ei) {
    if (threadIdx.x == 0) {
        int nz = 0;
        for (int i = 0; i < 64; i++)
            if (ei[2 * i + 1] != 0) nz++;
        g_idx64 = (nz == 0) ? 1 : 0;
    }
}
__global__ void prep_weights_kernel(const float* __restrict__ W1, const float* __restrict__ W2) {
    int t = blockIdx.x * blockDim.x + threadIdx.x;
    if (t < OD * OD) {
        float x = W2[t];
        __half hh = __float2half_rn(x);
        g_W2_hi[t] = hh;
        g_W2_lo[t] = __float2half_rn(x - __half2float(hh));
    }
    if (t < ED * OD) g_W1ch[t] = __float2half_rn(W1[(size_t)(2 * ND) * OD + t]);
    if (t < ND * 256) {
        int k = t >> 8, n = t & 255;
        float x = (n < 128) ? W1[(size_t)k * OD + n] : W1[(size_t)(ND + k) * OD + (n - 128)];
        __half hh = __float2half_rn(x);
        g_Wab_hi[t] = hh;
        g_Wab_lo[t] = __float2half_rn(x - __half2float(hh));
    }
}

// ---------------- counting sort by row ----------------
__global__ void hist_kernel(const void* __restrict__ ei, long long E) {
    long long e = (long long)blockIdx.x * blockDim.x + threadIdx.x;
    if (e < E) {
        int r = g_idx64 ? (int)((const long long*)ei)[e] : ((const int*)ei)[e];
        atomicAdd(&g_cnt[r], 1);
    }
}
__global__ __launch_bounds__(1024) void scan_kernel(int N) {
    __shared__ int wsum[32];
    int tid = threadIdx.x;
    int per = (N + 1023) / 1024;         // <= 16 for N <= 16384
    int base = tid * per;
    int loc[16];
    int local = 0;
#pragma unroll 16
    for (int i = 0; i < 16; i++) {
        int idx = base + i;
        int v = (i < per && idx < N) ? g_cnt[idx] : 0;
        loc[i] = v;
        local += v;
    }
    int lane = tid & 31, w = tid >> 5;
    int x = local;
    for (int d = 1; d < 32; d <<= 1) {
        int y = __shfl_up_sync(0xFFFFFFFFu, x, d);
        if (lane >= d) x += y;
    }
    if (lane == 31) wsum[w] = x;
    __syncthreads();
    if (w == 0) {
        int s = wsum[lane];
        for (int d = 1; d < 32; d <<= 1) {
            int y = __shfl_up_sync(0xFFFFFFFFu, s, d);
            if (lane >= d) s += y;
        }
        wsum[lane] = s;
    }
    __syncthreads();
    int run = x - local + (w > 0 ? wsum[w - 1] : 0);
#pragma unroll 16
    for (int i = 0; i < 16; i++) {
        int idx = base + i;
        if (i < per && idx < N) {
            g_pos[idx] = run;
            run += loc[i];
        }
    }
}
__global__ void scatter_sort_kernel(const void* __restrict__ ei, long long E) {
    long long e = (long long)blockIdx.x * blockDim.x + threadIdx.x;
    if (e < E) {
        int r, c;
        if (g_idx64) {
            r = (int)((const long long*)ei)[e];
            c = (int)((const long long*)ei)[E + e];
        } else {
            r = ((const int*)ei)[e];
            c = ((const int*)ei)[E + e];
        }
        int pos = atomicAdd(&g_pos[r], 1);
        g_srows[pos] = r;
        g_scols[pos] = c;
        g_perm[pos] = (int)e;
    }
}

// ---------------------------------------------------------------------------
// HMMA precompute: grid (nb, 2). p==0 -> Pr = h@W1a ; p==1 -> Pc = h@W1b.
__global__ __launch_bounds__(256, 1) void precompute_P_mma_kernel(
    const float* __restrict__ h, int N) {
    extern __shared__ char sm[];
    const uint32_t sb = smem_u32(sm);
    const int tid = threadIdx.x;
    const int wid = tid >> 5;
    const int lane = tid & 31;
    const int l16 = lane & 15;
    const int qrow = lane >> 2;
    const int qcol = (lane & 3) * 2;
    const int n0 = blockIdx.x * 128;
    const int p = blockIdx.y;

    {
        int row = tid >> 1, c0 = (tid & 1) * 64;
        int node = n0 + row;
        char* ph = sm + F_AH + row * PITCH_W_B + c0 * 2;
        char* pl = sm + F_AL + row * PITCH_W_B + c0 * 2;
#pragma unroll
        for (int q = 0; q < 8; q++) {
            float4 f0 = make_float4(0.f, 0.f, 0.f, 0.f), f1 = f0;
            if (node < N) {
                f0 = *(const float4*)(h + (size_t)node * ND + c0 + q * 8);
                f1 = *(const float4*)(h + (size_t)node * ND + c0 + q * 8 + 4);
            }
            uint32_t h0, l0, h1, l1, h2, l2, h3, l3;
            split2h(f0.x, f0.y, h0, l0); split2h(f0.z, f0.w, h1, l1);
            split2h(f1.x, f1.y, h2, l2); split2h(f1.z, f1.w, h3, l3);
            *(uint4*)(ph + q * 16) = make_uint4(h0, h1, h2, h3);
            *(uint4*)(pl + q * 16) = make_uint4(l0, l1, l2, l3);
        }
    }
    for (int t = tid; t < 2048; t += 256) {
        int k = t >> 4, c8 = (t & 15) << 3;
        *(uint4*)(sm + F_WH + k * PITCH_W_B + c8 * 2) =
            *(const uint4*)(g_Wab_hi + k * 256 + p * 128 + c8);
        *(uint4*)(sm + F_WL + k * PITCH_W_B + c8 * 2) =
            *(const uint4*)(g_Wab_lo + k * 256 + p * 128 + c8);
    }
    __syncthreads();

    const int m0 = wid * 16;
    uint32_t ahf[8][4], alf[8][4];
    {
        uint32_t ab_h = sb + F_AH + (m0 + l16) * PITCH_W_B + (lane >> 4) * 16;
        uint32_t ab_l = sb + F_AL + (m0 + l16) * PITCH_W_B + (lane >> 4) * 16;
#pragma unroll
        for (int k = 0; k < 8; k++) {
            ldmx4(ahf[k], ab_h + k * 32);
            ldmx4(alf[k], ab_l + k * 32);
        }
    }

    float acc[16][4];
#pragma unroll
    for (int i = 0; i < 16; i++)
#pragma unroll
        for (int j = 0; j < 4; j++) acc[i][j] = 0.f;
#pragma unroll
    for (int n2 = 0; n2 < 8; n2++) {
#pragma unroll
        for (int k = 0; k < 8; k++) {
            uint32_t bh[4], bl[4];
            uint32_t ba = (k * 16 + l16) * PITCH_W_B + n2 * 32 + (lane >> 4) * 16;
            ldmx4t(bh, sb + F_WH + ba);
            ldmx4t(bl, sb + F_WL + ba);
            mma_f16(acc[2 * n2],     ahf[k], bh);
            mma_f16(acc[2 * n2],     ahf[k], bl);
            mma_f16(acc[2 * n2],     alf[k], bh);
            mma_f16(acc[2 * n2 + 1], ahf[k], bh + 2);
            mma_f16(acc[2 * n2 + 1], ahf[k], bl + 2);
            mma_f16(acc[2 * n2 + 1], alf[k], bh + 2);
        }
    }
    float* base = (p == 0) ? g_Pr : g_Pc;
    const int node_lo = n0 + m0 + qrow;
    const int node_hi = node_lo + 8;
#pragma unroll
    for (int n2 = 0; n2 < 8; n2++) {
#pragma unroll
        for (int hlf = 0; hlf < 2; hlf++) {
            int col = n2 * 16 + hlf * 8 + qcol;
            float* a = acc[2 * n2 + hlf];
            if (node_lo < N)
                *(float2*)(base + (size_t)node_lo * OD + col) = make_float2(a[0], a[1]);
            if (node_hi < N)
                *(float2*)(base + (size_t)node_hi * OD + col) = make_float2(a[2], a[3]);
        }
    }
}

// ---------------------------------------------------------------------------
// Edge kernel over SORTED edges: hidden = relu(Pr[r]+Pc[c]+ef@W1c+b1),
// segmented warp-reduction over equal rows, head lanes RED into g_H[r].
__global__ __launch_bounds__(256, 3) void edge_hidden_kernel(
    const float* __restrict__ edge_features,
    const float* __restrict__ b1g,
    long long E, int n_tiles) {
    extern __shared__ char sm[];
    const uint32_t sb = smem_u32(sm);
    const int tid = threadIdx.x;
    const int wid = tid >> 5;
    const int lane = tid & 31;
    const unsigned FULL = 0xFFFFFFFFu;

    int* s_rows = (int*)(sm + E_ROWS);
    int* s_cols = (int*)(sm + E_COLS);

    for (int t = tid; t < 512; t += 256) {
        int k = t >> 4, n8 = (t & 15) << 3;
        *(uint4*)(sm + E_W1 + k * PITCH_W_B + n8 * 2) = *(const uint4*)(g_W1ch + k * OD + n8);
    }
    if (tid < 128) ((float*)(sm + E_B1))[tid] = b1g[tid];
    __syncthreads();

    const int m0 = wid * 16;
    const int qrow = lane >> 2;
    const int qcol = (lane & 3) * 2;
    const int l16 = lane & 15;
    const uint32_t efA = sb + E_EF + (m0 + l16) * PITCH_EF_B + ((lane >> 4) * 8) * 2;
    const uint32_t blane_off = l16 * PITCH_W_B + (lane >> 4) * 16;

    for (int tile = blockIdx.x; tile < n_tiles; tile += gridDim.x) {
        const long long e0 = (long long)tile * TE;
        __syncthreads();

        // stage sorted indices
        if (tid < TE) {
            long long p = e0 + tid;
            int r = 0, c = 0;
            if (p < E) { r = g_srows[p]; c = g_scols[p]; }
            s_rows[tid] = r; s_cols[tid] = c;
        }
        // stage edge features via perm (fp32 -> fp16)
        {
            int er = tid >> 1;
            int c0 = (tid & 1) * 16;
            long long p = e0 + er;
            float v[16];
            if (p < E) {
                long long e = (long long)g_perm[p];
                const float4* pf = (const float4*)(edge_features + e * ED + c0);
#pragma unroll
                for (int q = 0; q < 4; q++) {
                    float4 f = pf[q];
                    v[q * 4 + 0] = f.x; v[q * 4 + 1] = f.y; v[q * 4 + 2] = f.z; v[q * 4 + 3] = f.w;
                }
            } else {
#pragma unroll
                for (int q = 0; q < 16; q++) v[q] = 0.f;
            }
            uint32_t hv[8];
#pragma unroll
            for (int q = 0; q < 8; q++) hv[q] = pack2h(v[2 * q], v[2 * q + 1]);
            char* ph = sm + E_EF + er * PITCH_EF_B + c0 * 2;
            *(uint4*)(ph) = make_uint4(hv[0], hv[1], hv[2], hv[3]);
            *(uint4*)(ph + 16) = make_uint4(hv[4], hv[5], hv[6], hv[7]);
        }
        __syncthreads();

        const int e_lo = m0 + qrow, e_hi = e_lo + 8;
        const int r_lo = s_rows[e_lo], r_hi = s_rows[e_hi];
        const int c_lo = s_cols[e_lo], c_hi = s_cols[e_hi];
        const bool v_lo = (e0 + e_lo) < E;
        const bool v_hi = (e0 + e_hi) < E;
        const float* prl_base = g_Pr + (size_t)r_lo * OD;
        const float* prh_base = g_Pr + (size_t)r_hi * OD;
        const float* pcl_base = g_Pc + (size_t)c_lo * OD;
        const float* pch_base = g_Pc + (size_t)c_hi * OD;
        float* Hlo = g_H + (size_t)r_lo * OD;
        float* Hhi = g_H + (size_t)r_hi * OD;

        // segmentation masks (rows sorted -> runs contiguous along qrow)
        int rt;
        rt = __shfl_down_sync(FULL, r_lo, 4);  const bool s1l = (qrow < 7) && (rt == r_lo);
        rt = __shfl_down_sync(FULL, r_lo, 8);  const bool s2l = (qrow < 6) && (rt == r_lo);
        rt = __shfl_down_sync(FULL, r_lo, 16); const bool s4l = (qrow < 4) && (rt == r_lo);
        rt = __shfl_up_sync(FULL, r_lo, 4);    const bool hl  = (qrow == 0) || (rt != r_lo);
        rt = __shfl_down_sync(FULL, r_hi, 4);  const bool s1h = (qrow < 7) && (rt == r_hi);
        rt = __shfl_down_sync(FULL, r_hi, 8);  const bool s2h = (qrow < 6) && (rt == r_hi);
        rt = __shfl_down_sync(FULL, r_hi, 16); const bool s4h = (qrow < 4) && (rt == r_hi);
        rt = __shfl_up_sync(FULL, r_hi, 4);    const bool hh  = (qrow == 0) || (rt != r_hi);

        uint32_t eh[2][4];
        ldmx4(eh[0], efA);
        ldmx4(eh[1], efA + 32);

#pragma unroll
        for (int g = 0; g < 4; g++) {
            float2 prl[4], prh[4], pcl[4], pch[4];
#pragma unroll
            for (int cc = 0; cc < 4; cc++) {
                int col = (4 * g + cc) * 8 + qcol;
                prl[cc] = *(const float2*)(prl_base + col);
                prh[cc] = *(const float2*)(prh_base + col);
                pcl[cc] = *(const float2*)(pcl_base + col);
                pch[cc] = *(const float2*)(pch_base + col);
            }
#pragma unroll
            for (int t = 0; t < 2; t++) {
                int n2 = 2 * g + t;
                float a8[8];
#pragma unroll
                for (int j = 0; j < 8; j++) a8[j] = 0.f;
#pragma unroll
                for (int k = 0; k < 2; k++) {
                    uint32_t b[4];
                    ldmx4t(b, sb + E_W1 + k * 16 * PITCH_W_B + n2 * 32 + blane_off);
                    mma_f16(a8,     eh[k], b);
                    mma_f16(a8 + 4, eh[k], b + 2);
                }
#pragma unroll
                for (int u = 0; u < 2; u++) {
                    int cc = 2 * t + u;
                    int c = 4 * g + cc;
                    int col = c * 8 + qcol;
                    float2 b1c = *(const float2*)(sm + E_B1 + col * 4);
                    float h0 = fmaxf(a8[u*4+0] + prl[cc].x + pcl[cc].x + b1c.x, 0.f);
                    float h1 = fmaxf(a8[u*4+1] + prl[cc].y + pcl[cc].y + b1c.y, 0.f);
                    float h2 = fmaxf(a8[u*4+2] + prh[cc].x + pch[cc].x + b1c.x, 0.f);
                    float h3 = fmaxf(a8[u*4+3] + prh[cc].y + pch[cc].y + b1c.y, 0.f);
                    if (!v_lo) { h0 = 0.f; h1 = 0.f; }
                    if (!v_hi) { h2 = 0.f; h3 = 0.f; }
                    float s;
                    s = __shfl_down_sync(FULL, h0, 4);  if (s1l) h0 += s;
                    s = __shfl_down_sync(FULL, h0, 8);  if (s2l) h0 += s;
                    s = __shfl_down_sync(FULL, h0, 16); if (s4l) h0 += s;
                    s = __shfl_down_sync(FULL, h1, 4);  if (s1l) h1 += s;
                    s = __shfl_down_sync(FULL, h1, 8);  if (s2l) h1 += s;
                    s = __shfl_down_sync(FULL, h1, 16); if (s4l) h1 += s;
                    s = __shfl_down_sync(FULL, h2, 4);  if (s1h) h2 += s;
                    s = __shfl_down_sync(FULL, h2, 8);  if (s2h) h2 += s;
                    s = __shfl_down_sync(FULL, h2, 16); if (s4h) h2 += s;
                    s = __shfl_down_sync(FULL, h3, 4);  if (s1h) h3 += s;
                    s = __shfl_down_sync(FULL, h3, 8);  if (s2h) h3 += s;
                    s = __shfl_down_sync(FULL, h3, 16); if (s4h) h3 += s;
                    if (hl)
                        asm volatile("red.global.add.v2.f32 [%0], {%1,%2};"
                                     :: "l"(Hlo + col), "f"(h0), "f"(h1) : "memory");
                    if (hh)
                        asm volatile("red.global.add.v2.f32 [%0], {%1,%2};"
                                     :: "l"(Hhi + col), "f"(h2), "f"(h3) : "memory");
                }
            }
        }
    }
}

// ---------------------------------------------------------------------------
// Final: out = g_H @ W2 + deg * b2 (3-term split, ~fp32 accuracy)
__global__ __launch_bounds__(256, 1) void final_out_mma_kernel(
    const float* __restrict__ b2g, float* __restrict__ out, int N) {
    extern __shared__ char sm[];
    const uint32_t sb = smem_u32(sm);
    const int tid = threadIdx.x;
    const int wid = tid >> 5;
    const int lane = tid & 31;
    const int l16 = lane & 15;
    const int qrow = lane >> 2;
    const int qcol = (lane & 3) * 2;
    const int n0 = blockIdx.x * 128;

    {
        int row = tid >> 1, c0 = (tid & 1) * 64;
        int node = n0 + row;
        char* ph = sm + F_AH + row * PITCH_W_B + c0 * 2;
        char* pl = sm + F_AL + row * PITCH_W_B + c0 * 2;
#pragma unroll
        for (int q = 0; q < 8; q++) {
            float4 f0 = make_float4(0.f, 0.f, 0.f, 0.f), f1 = f0;
            if (node < N) {
                f0 = *(const float4*)(g_H + (size_t)node * OD + c0 + q * 8);
                f1 = *(const float4*)(g_H + (size_t)node * OD + c0 + q * 8 + 4);
            }
            uint32_t h0, l0, h1, l1, h2, l2, h3, l3;
            split2h(f0.x, f0.y, h0, l0); split2h(f0.z, f0.w, h1, l1);
            split2h(f1.x, f1.y, h2, l2); split2h(f1.z, f1.w, h3, l3);
            *(uint4*)(ph + q * 16) = make_uint4(h0, h1, h2, h3);
            *(uint4*)(pl + q * 16) = make_uint4(l0, l1, l2, l3);
        }
    }
    for (int t = tid; t < 2048; t += 256) {
        int k = t >> 4, c8 = (t & 15) << 3;
        *(uint4*)(sm + F_WH + k * PITCH_W_B + c8 * 2) = *(const uint4*)(g_W2_hi + k * OD + c8);
        *(uint4*)(sm + F_WL + k * PITCH_W_B + c8 * 2) = *(const uint4*)(g_W2_lo + k * OD + c8);
    }
    if (tid < 128) {
        int node = n0 + tid;
        ((float*)(sm + F_B2))[tid] = b2g[tid];
        ((float*)(sm + F_DEG))[tid] = (node < N) ? (float)g_cnt[node] : 0.f;
    }
    __syncthreads();

    const int m0 = wid * 16;
    uint32_t ahf[8][4], alf[8][4];
    {
        uint32_t ab_h = sb + F_AH + (m0 + l16) * PITCH_W_B + (lane >> 4) * 16;
        uint32_t ab_l = sb + F_AL + (m0 + l16) * PITCH_W_B + (lane >> 4) * 16;
#pragma unroll
        for (int k = 0; k < 8; k++) {
            ldmx4(ahf[k], ab_h + k * 32);
            ldmx4(alf[k], ab_l + k * 32);
        }
    }

    float acc[16][4];
#pragma unroll
    for (int i = 0; i < 16; i++)
#pragma unroll
        for (int j = 0; j < 4; j++) acc[i][j] = 0.f;
#pragma unroll
    for (int n2 = 0; n2 < 8; n2++) {
#pragma unroll
        for (int k = 0; k < 8; k++) {
            uint32_t bh[4], bl[4];
            uint32_t ba = (k * 16 + l16) * PITCH_W_B + n2 * 32 + (lane >> 4) * 16;
            ldmx4t(bh, sb + F_WH + ba);
            ldmx4t(bl, sb + F_WL + ba);
            mma_f16(acc[2 * n2],     ahf[k], bh);
            mma_f16(acc[2 * n2],     ahf[k], bl);
            mma_f16(acc[2 * n2],     alf[k], bh);
            mma_f16(acc[2 * n2 + 1], ahf[k], bh + 2);
            mma_f16(acc[2 * n2 + 1], ahf[k], bl + 2);
            mma_f16(acc[2 * n2 + 1], alf[k], bh + 2);
        }
    }

    const int node_lo = n0 + m0 + qrow;
    const int node_hi = node_lo + 8;
    const float deg_lo = ((float*)(sm + F_DEG))[m0 + qrow];
    const float deg_hi = ((float*)(sm + F_DEG))[m0 + qrow + 8];
#pragma unroll
    for (int n2 = 0; n2 < 8; n2++) {
#pragma unroll
        for (int hlf = 0; hlf < 2; hlf++) {
            int col = n2 * 16 + hlf * 8 + qcol;
            float2 b2c = *(const float2*)(sm + F_B2 + col * 4);
            float* a = acc[2 * n2 + hlf];
            if (node_lo < N)
                *(float2*)(out + (size_t)node_lo * OD + col) =
                    make_float2(a[0] + deg_lo * b2c.x, a[1] + deg_lo * b2c.y);
            if (node_hi < N)
                *(float2*)(out + (size_t)node_hi * OD + col) =
                    make_float2(a[2] + deg_hi * b2c.x, a[3] + deg_hi * b2c.y);
        }
    }
}

// ---------------------------------------------------------------------------
extern "C" void kernel_launch(void* const* d_in, const int* in_sizes, int n_in,
                              void* d_out, int out_size) {
    const float* h = (const float*)d_in[0];
    const void* edge_index = d_in[1];
    const float* ef = (const float*)d_in[2];
    const float *W1 = 0, *b1 = 0, *W2 = 0, *b2 = 0;
    for (int i = 3; i < n_in; i++) {
        int s = in_sizes[i];
        if (s == (2 * ND + ED) * OD) W1 = (const float*)d_in[i];
        else if (s == OD * OD) W2 = (const float*)d_in[i];
        else if (s == OD) { if (!b1) b1 = (const float*)d_in[i]; else b2 = (const float*)d_in[i]; }
    }
    if (!W1 || !b1 || !W2 || !b2) return;

    int N = in_sizes[0] / ND;
    if (N > MAXN) N = MAXN;
    long long E = (long long)(in_sizes[1] / 2);
    if (E > MAXE) E = MAXE;
    float* out = (float*)d_out;
    int n_tiles = (int)((E + TE - 1) / TE);
    int nb = (N + 127) / 128;
    int eb = (int)((E + 255) / 256);

    zero_scratch_kernel<<<(N * OD + 255) / 256, 256>>>(N * OD, N);
    detect_idx_kernel<<<1, 32>>>((const int*)edge_index);
    prep_weights_kernel<<<128, 256>>>(W1, W2);

    // counting sort by destination row
    hist_kernel<<<eb, 256>>>(edge_index, E);
    scan_kernel<<<1, 1024>>>(N);
    scatter_sort_kernel<<<eb, 256>>>(edge_index, E);

    cudaFuncSetAttribute(precompute_P_mma_kernel,
                         cudaFuncAttributeMaxDynamicSharedMemorySize, F_TOTAL);
    dim3 pgrid(nb, 2);
    precompute_P_mma_kernel<<<pgrid, 256, F_TOTAL>>>(h, N);

    int egrid = 3 * NSM;
    if (egrid > n_tiles) egrid = n_tiles;
    edge_hidden_kernel<<<egrid, 256, E_TOTAL>>>(ef, b1, E, n_tiles);

    cudaFuncSetAttribute(final_out_mma_kernel,
                         cudaFuncAttributeMaxDynamicSharedMemorySize, F_TOTAL);
    final_out_mma_kernel<<<nb, 256, F_TOTAL>>>(b2, out, N);
}

// round 9
// speedup vs baseline: 4.2021x; 1.0804x over previous
#include <cuda_runtime.h>
#include <cuda_fp16.h>
#include <stdint.h>
#include <stddef.h>

#define ND 128
#define ED 32
#define OD 128
#define TE 128
#define MAXN 10000
#define MAXE 1048576
#define NSM 148

// ---------------- device scratch ----------------
__device__ float g_Pr[MAXN * OD];
__device__ float g_Pc[MAXN * OD];
__device__ float g_H[MAXN * OD];
__device__ int   g_cnt[MAXN];        // degree (histogram)
__device__ int   g_pos[MAXN];        // scatter cursor
__device__ int   g_srows[MAXE];
__device__ int   g_scols[MAXE];
__device__ int   g_perm[MAXE];
__device__ int   g_idx64;
__device__ __half g_W1ch[ED * OD];
__device__ __half g_Wab_hi[ND * 256];
__device__ __half g_Wab_lo[ND * 256];
__device__ __half g_W2_hi[OD * OD];
__device__ __half g_W2_lo[OD * OD];

// ---------------- edge-kernel smem ----------------
#define PITCH_EF_B 80
#define PITCH_W_B  272
#define E_ROWS 0
#define E_COLS 512
#define E_B1   1024
#define E_EF   2048                      // 128*80 = 10240
#define E_W1   12288                     // 32*272 = 8704
#define E_TOTAL 20992

// ---------------- precompute / final GEMM smem ----------------
#define F_AH 0
#define F_AL 34816
#define F_WH 69632
#define F_WL 104448
#define F_B2 139264
#define F_DEG 139776
#define F_TOTAL 140288

// ---------------- helpers ----------------
__device__ __forceinline__ uint32_t smem_u32(const void* p) {
    uint32_t a;
    asm("{ .reg .u64 t; cvta.to.shared.u64 t, %1; cvt.u32.u64 %0, t; }" : "=r"(a) : "l"(p));
    return a;
}
__device__ __forceinline__ void ldmx4(uint32_t* r, uint32_t addr) {
    asm volatile("ldmatrix.sync.aligned.m8n8.x4.shared.b16 {%0,%1,%2,%3}, [%4];"
                 : "=r"(r[0]), "=r"(r[1]), "=r"(r[2]), "=r"(r[3]) : "r"(addr));
}
__device__ __forceinline__ void ldmx4t(uint32_t* r, uint32_t addr) {
    asm volatile("ldmatrix.sync.aligned.m8n8.x4.trans.shared.b16 {%0,%1,%2,%3}, [%4];"
                 : "=r"(r[0]), "=r"(r[1]), "=r"(r[2]), "=r"(r[3]) : "r"(addr));
}
__device__ __forceinline__ void mma_f16(float* d, const uint32_t* a, const uint32_t* b) {
    asm volatile(
        "mma.sync.aligned.m16n8k16.row.col.f32.f16.f16.f32 "
        "{%0,%1,%2,%3},{%4,%5,%6,%7},{%8,%9},{%0,%1,%2,%3};"
        : "+f"(d[0]), "+f"(d[1]), "+f"(d[2]), "+f"(d[3])
        : "r"(a[0]), "r"(a[1]), "r"(a[2]), "r"(a[3]), "r"(b[0]), "r"(b[1]));
}
__device__ __forceinline__ uint32_t pack2h(float x0, float x1) {
    uint32_t r;
    asm("cvt.rn.f16x2.f32 %0, %1, %2;" : "=r"(r) : "f"(x1), "f"(x0));
    return r;
}
__device__ __forceinline__ void split2h(float x0, float x1, uint32_t& hi, uint32_t& lo) {
    __half h0 = __float2half_rn(x0);
    __half h1 = __float2half_rn(x1);
    hi = ((uint32_t)__half_as_ushort(h1) << 16) | __half_as_ushort(h0);
    lo = pack2h(x0 - __half2float(h0), x1 - __half2float(h1));
}

// ---------------------------------------------------------------------------
__global__ void zero_cnt_kernel(int nCnt) {
    int i = blockIdx.x * blockDim.x + threadIdx.x;
    if (i < nCnt) g_cnt[i] = 0;
}
__global__ void zero_H_kernel(int nH) {
    int i = blockIdx.x * blockDim.x + threadIdx.x;
    if (i < nH) g_H[i] = 0.0f;
}
__global__ void detect_idx_kernel(const int* __restrict__ ei) {
    if (threadIdx.x == 0) {
        int nz = 0;
        for (int i = 0; i < 64; i++)
            if (ei[2 * i + 1] != 0) nz++;
        g_idx64 = (nz == 0) ? 1 : 0;
    }
}
__global__ void prep_weights_kernel(const float* __restrict__ W1, const float* __restrict__ W2) {
    int t = blockIdx.x * blockDim.x + threadIdx.x;
    if (t < OD * OD) {
        float x = W2[t];
        __half hh = __float2half_rn(x);
        g_W2_hi[t] = hh;
        g_W2_lo[t] = __float2half_rn(x - __half2float(hh));
    }
    if (t < ED * OD) g_W1ch[t] = __float2half_rn(W1[(size_t)(2 * ND) * OD + t]);
    if (t < ND * 256) {
        int k = t >> 8, n = t & 255;
        float x = (n < 128) ? W1[(size_t)k * OD + n] : W1[(size_t)(ND + k) * OD + (n - 128)];
        __half hh = __float2half_rn(x);
        g_Wab_hi[t] = hh;
        g_Wab_lo[t] = __float2half_rn(x - __half2float(hh));
    }
}

// ---------------- counting sort by row ----------------
__global__ void hist_kernel(const void* __restrict__ ei, long long E) {
    long long e = (long long)blockIdx.x * blockDim.x + threadIdx.x;
    if (e < E) {
        int r = g_idx64 ? (int)((const long long*)ei)[e] : ((const int*)ei)[e];
        // fire-and-forget RED: no return-value scoreboard stall
        asm volatile("red.global.add.s32 [%0], %1;" :: "l"(&g_cnt[r]), "r"(1) : "memory");
    }
}
__global__ __launch_bounds__(1024) void scan_kernel(int N) {
    __shared__ int wsum[32];
    int tid = threadIdx.x;
    int per = (N + 1023) / 1024;
    int base = tid * per;
    int loc[16];
    int local = 0;
#pragma unroll 16
    for (int i = 0; i < 16; i++) {
        int idx = base + i;
        int v = (i < per && idx < N) ? g_cnt[idx] : 0;
        loc[i] = v;
        local += v;
    }
    int lane = tid & 31, w = tid >> 5;
    int x = local;
    for (int d = 1; d < 32; d <<= 1) {
        int y = __shfl_up_sync(0xFFFFFFFFu, x, d);
        if (lane >= d) x += y;
    }
    if (lane == 31) wsum[w] = x;
    __syncthreads();
    if (w == 0) {
        int s = wsum[lane];
        for (int d = 1; d < 32; d <<= 1) {
            int y = __shfl_up_sync(0xFFFFFFFFu, s, d);
            if (lane >= d) s += y;
        }
        wsum[lane] = s;
    }
    __syncthreads();
    int run = x - local + (w > 0 ? wsum[w - 1] : 0);
#pragma unroll 16
    for (int i = 0; i < 16; i++) {
        int idx = base + i;
        if (i < per && idx < N) {
            g_pos[idx] = run;
            run += loc[i];
        }
    }
}
__global__ void scatter_sort_kernel(const void* __restrict__ ei, long long E) {
    long long e = (long long)blockIdx.x * blockDim.x + threadIdx.x;
    if (e < E) {
        int r, c;
        if (g_idx64) {
            r = (int)((const long long*)ei)[e];
            c = (int)((const long long*)ei)[E + e];
        } else {
            r = ((const int*)ei)[e];
            c = ((const int*)ei)[E + e];
        }
        int pos = atomicAdd(&g_pos[r], 1);
        g_srows[pos] = r;
        g_scols[pos] = c;
        g_perm[pos] = (int)e;
    }
}

// ---------------------------------------------------------------------------
// HMMA precompute: grid (nb, 2). p==0 -> Pr = h@W1a ; p==1 -> Pc = h@W1b.
__global__ __launch_bounds__(256, 1) void precompute_P_mma_kernel(
    const float* __restrict__ h, int N) {
    extern __shared__ char sm[];
    const uint32_t sb = smem_u32(sm);
    const int tid = threadIdx.x;
    const int wid = tid >> 5;
    const int lane = tid & 31;
    const int l16 = lane & 15;
    const int qrow = lane >> 2;
    const int qcol = (lane & 3) * 2;
    const int n0 = blockIdx.x * 128;
    const int p = blockIdx.y;

    {
        int row = tid >> 1, c0 = (tid & 1) * 64;
        int node = n0 + row;
        char* ph = sm + F_AH + row * PITCH_W_B + c0 * 2;
        char* pl = sm + F_AL + row * PITCH_W_B + c0 * 2;
#pragma unroll
        for (int q = 0; q < 8; q++) {
            float4 f0 = make_float4(0.f, 0.f, 0.f, 0.f), f1 = f0;
            if (node < N) {
                f0 = *(const float4*)(h + (size_t)node * ND + c0 + q * 8);
                f1 = *(const float4*)(h + (size_t)node * ND + c0 + q * 8 + 4);
            }
            uint32_t h0, l0, h1, l1, h2, l2, h3, l3;
            split2h(f0.x, f0.y, h0, l0); split2h(f0.z, f0.w, h1, l1);
            split2h(f1.x, f1.y, h2, l2); split2h(f1.z, f1.w, h3, l3);
            *(uint4*)(ph + q * 16) = make_uint4(h0, h1, h2, h3);
            *(uint4*)(pl + q * 16) = make_uint4(l0, l1, l2, l3);
        }
    }
    for (int t = tid; t < 2048; t += 256) {
        int k = t >> 4, c8 = (t & 15) << 3;
        *(uint4*)(sm + F_WH + k * PITCH_W_B + c8 * 2) =
            *(const uint4*)(g_Wab_hi + k * 256 + p * 128 + c8);
        *(uint4*)(sm + F_WL + k * PITCH_W_B + c8 * 2) =
            *(const uint4*)(g_Wab_lo + k * 256 + p * 128 + c8);
    }
    __syncthreads();

    const int m0 = wid * 16;
    uint32_t ahf[8][4], alf[8][4];
    {
        uint32_t ab_h = sb + F_AH + (m0 + l16) * PITCH_W_B + (lane >> 4) * 16;
        uint32_t ab_l = sb + F_AL + (m0 + l16) * PITCH_W_B + (lane >> 4) * 16;
#pragma unroll
        for (int k = 0; k < 8; k++) {
            ldmx4(ahf[k], ab_h + k * 32);
            ldmx4(alf[k], ab_l + k * 32);
        }
    }

    float acc[16][4];
#pragma unroll
    for (int i = 0; i < 16; i++)
#pragma unroll
        for (int j = 0; j < 4; j++) acc[i][j] = 0.f;
#pragma unroll
    for (int n2 = 0; n2 < 8; n2++) {
#pragma unroll
        for (int k = 0; k < 8; k++) {
            uint32_t bh[4], bl[4];
            uint32_t ba = (k * 16 + l16) * PITCH_W_B + n2 * 32 + (lane >> 4) * 16;
            ldmx4t(bh, sb + F_WH + ba);
            ldmx4t(bl, sb + F_WL + ba);
            mma_f16(acc[2 * n2],     ahf[k], bh);
            mma_f16(acc[2 * n2],     ahf[k], bl);
            mma_f16(acc[2 * n2],     alf[k], bh);
            mma_f16(acc[2 * n2 + 1], ahf[k], bh + 2);
            mma_f16(acc[2 * n2 + 1], ahf[k], bl + 2);
            mma_f16(acc[2 * n2 + 1], alf[k], bh + 2);
        }
    }
    float* base = (p == 0) ? g_Pr : g_Pc;
    const int node_lo = n0 + m0 + qrow;
    const int node_hi = node_lo + 8;
#pragma unroll
    for (int n2 = 0; n2 < 8; n2++) {
#pragma unroll
        for (int hlf = 0; hlf < 2; hlf++) {
            int col = n2 * 16 + hlf * 8 + qcol;
            float* a = acc[2 * n2 + hlf];
            if (node_lo < N)
                *(float2*)(base + (size_t)node_lo * OD + col) = make_float2(a[0], a[1]);
            if (node_hi < N)
                *(float2*)(base + (size_t)node_hi * OD + col) = make_float2(a[2], a[3]);
        }
    }
}

// ---------------------------------------------------------------------------
// Edge kernel over SORTED edges: hidden = relu(Pr[r]+Pc[c]+ef@W1c+b1),
// segmented warp-reduction over equal rows, head lanes RED into g_H[r].
__global__ __launch_bounds__(256, 3) void edge_hidden_kernel(
    const float* __restrict__ edge_features,
    const float* __restrict__ b1g,
    long long E, int n_tiles) {
    extern __shared__ char sm[];
    const uint32_t sb = smem_u32(sm);
    const int tid = threadIdx.x;
    const int wid = tid >> 5;
    const int lane = tid & 31;
    const unsigned FULL = 0xFFFFFFFFu;

    int* s_rows = (int*)(sm + E_ROWS);
    int* s_cols = (int*)(sm + E_COLS);

    for (int t = tid; t < 512; t += 256) {
        int k = t >> 4, n8 = (t & 15) << 3;
        *(uint4*)(sm + E_W1 + k * PITCH_W_B + n8 * 2) = *(const uint4*)(g_W1ch + k * OD + n8);
    }
    if (tid < 128) ((float*)(sm + E_B1))[tid] = b1g[tid];
    __syncthreads();

    const int m0 = wid * 16;
    const int qrow = lane >> 2;
    const int qcol = (lane & 3) * 2;
    const int l16 = lane & 15;
    const uint32_t efA = sb + E_EF + (m0 + l16) * PITCH_EF_B + ((lane >> 4) * 8) * 2;
    const uint32_t blane_off = l16 * PITCH_W_B + (lane >> 4) * 16;

    for (int tile = blockIdx.x; tile < n_tiles; tile += gridDim.x) {
        const long long e0 = (long long)tile * TE;
        __syncthreads();

        if (tid < TE) {
            long long p = e0 + tid;
            int r = 0, c = 0;
            if (p < E) { r = g_srows[p]; c = g_scols[p]; }
            s_rows[tid] = r; s_cols[tid] = c;
        }
        {
            int er = tid >> 1;
            int c0 = (tid & 1) * 16;
            long long p = e0 + er;
            float v[16];
            if (p < E) {
                long long e = (long long)g_perm[p];
                const float4* pf = (const float4*)(edge_features + e * ED + c0);
#pragma unroll
                for (int q = 0; q < 4; q++) {
                    float4 f = pf[q];
                    v[q * 4 + 0] = f.x; v[q * 4 + 1] = f.y; v[q * 4 + 2] = f.z; v[q * 4 + 3] = f.w;
                }
            } else {
#pragma unroll
                for (int q = 0; q < 16; q++) v[q] = 0.f;
            }
            uint32_t hv[8];
#pragma unroll
            for (int q = 0; q < 8; q++) hv[q] = pack2h(v[2 * q], v[2 * q + 1]);
            char* ph = sm + E_EF + er * PITCH_EF_B + c0 * 2;
            *(uint4*)(ph) = make_uint4(hv[0], hv[1], hv[2], hv[3]);
            *(uint4*)(ph + 16) = make_uint4(hv[4], hv[5], hv[6], hv[7]);
        }
        __syncthreads();

        const int e_lo = m0 + qrow, e_hi = e_lo + 8;
        const int r_lo = s_rows[e_lo], r_hi = s_rows[e_hi];
        const int c_lo = s_cols[e_lo], c_hi = s_cols[e_hi];
        const bool v_lo = (e0 + e_lo) < E;
        const bool v_hi = (e0 + e_hi) < E;
        const float* prl_base = g_Pr + (size_t)r_lo * OD;
        const float* prh_base = g_Pr + (size_t)r_hi * OD;
        const float* pcl_base = g_Pc + (size_t)c_lo * OD;
        const float* pch_base = g_Pc + (size_t)c_hi * OD;
        float* Hlo = g_H + (size_t)r_lo * OD;
        float* Hhi = g_H + (size_t)r_hi * OD;

        int rt;
        rt = __shfl_down_sync(FULL, r_lo, 4);  const bool s1l = (qrow < 7) && (rt == r_lo);
        rt = __shfl_down_sync(FULL, r_lo, 8);  const bool s2l = (qrow < 6) && (rt == r_lo);
        rt = __shfl_down_sync(FULL, r_lo, 16); const bool s4l = (qrow < 4) && (rt == r_lo);
        rt = __shfl_up_sync(FULL, r_lo, 4);    const bool hl  = (qrow == 0) || (rt != r_lo);
        rt = __shfl_down_sync(FULL, r_hi, 4);  const bool s1h = (qrow < 7) && (rt == r_hi);
        rt = __shfl_down_sync(FULL, r_hi, 8);  const bool s2h = (qrow < 6) && (rt == r_hi);
        rt = __shfl_down_sync(FULL, r_hi, 16); const bool s4h = (qrow < 4) && (rt == r_hi);
        rt = __shfl_up_sync(FULL, r_hi, 4);    const bool hh  = (qrow == 0) || (rt != r_hi);

        uint32_t eh[2][4];
        ldmx4(eh[0], efA);
        ldmx4(eh[1], efA + 32);

#pragma unroll
        for (int g = 0; g < 4; g++) {
            float2 prl[4], prh[4], pcl[4], pch[4];
#pragma unroll
            for (int cc = 0; cc < 4; cc++) {
                int col = (4 * g + cc) * 8 + qcol;
                prl[cc] = *(const float2*)(prl_base + col);
                prh[cc] = *(const float2*)(prh_base + col);
                pcl[cc] = *(const float2*)(pcl_base + col);
                pch[cc] = *(const float2*)(pch_base + col);
            }
#pragma unroll
            for (int t = 0; t < 2; t++) {
                int n2 = 2 * g + t;
                float a8[8];
#pragma unroll
                for (int j = 0; j < 8; j++) a8[j] = 0.f;
#pragma unroll
                for (int k = 0; k < 2; k++) {
                    uint32_t b[4];
                    ldmx4t(b, sb + E_W1 + k * 16 * PITCH_W_B + n2 * 32 + blane_off);
                    mma_f16(a8,     eh[k], b);
                    mma_f16(a8 + 4, eh[k], b + 2);
                }
#pragma unroll
                for (int u = 0; u < 2; u++) {
                    int cc = 2 * t + u;
                    int c = 4 * g + cc;
                    int col = c * 8 + qcol;
                    float2 b1c = *(const float2*)(sm + E_B1 + col * 4);
                    float h0 = fmaxf(a8[u*4+0] + prl[cc].x + pcl[cc].x + b1c.x, 0.f);
                    float h1 = fmaxf(a8[u*4+1] + prl[cc].y + pcl[cc].y + b1c.y, 0.f);
                    float h2 = fmaxf(a8[u*4+2] + prh[cc].x + pch[cc].x + b1c.x, 0.f);
                    float h3 = fmaxf(a8[u*4+3] + prh[cc].y + pch[cc].y + b1c.y, 0.f);
                    if (!v_lo) { h0 = 0.f; h1 = 0.f; }
                    if (!v_hi) { h2 = 0.f; h3 = 0.f; }
                    float s;
                    s = __shfl_down_sync(FULL, h0, 4);  if (s1l) h0 += s;
                    s = __shfl_down_sync(FULL, h0, 8);  if (s2l) h0 += s;
                    s = __shfl_down_sync(FULL, h0, 16); if (s4l) h0 += s;
                    s = __shfl_down_sync(FULL, h1, 4);  if (s1l) h1 += s;
                    s = __shfl_down_sync(FULL, h1, 8);  if (s2l) h1 += s;
                    s = __shfl_down_sync(FULL, h1, 16); if (s4l) h1 += s;
                    s = __shfl_down_sync(FULL, h2, 4);  if (s1h) h2 += s;
                    s = __shfl_down_sync(FULL, h2, 8);  if (s2h) h2 += s;
                    s = __shfl_down_sync(FULL, h2, 16); if (s4h) h2 += s;
                    s = __shfl_down_sync(FULL, h3, 4);  if (s1h) h3 += s;
                    s = __shfl_down_sync(FULL, h3, 8);  if (s2h) h3 += s;
                    s = __shfl_down_sync(FULL, h3, 16); if (s4h) h3 += s;
                    if (hl)
                        asm volatile("red.global.add.v2.f32 [%0], {%1,%2};"
                                     :: "l"(Hlo + col), "f"(h0), "f"(h1) : "memory");
                    if (hh)
                        asm volatile("red.global.add.v2.f32 [%0], {%1,%2};"
                                     :: "l"(Hhi + col), "f"(h2), "f"(h3) : "memory");
                }
            }
        }
    }
}

// ---------------------------------------------------------------------------
// Final: out = g_H @ W2 + deg * b2 (3-term split, ~fp32 accuracy)
__global__ __launch_bounds__(256, 1) void final_out_mma_kernel(
    const float* __restrict__ b2g, float* __restrict__ out, int N) {
    extern __shared__ char sm[];
    const uint32_t sb = smem_u32(sm);
    const int tid = threadIdx.x;
    const int wid = tid >> 5;
    const int lane = tid & 31;
    const int l16 = lane & 15;
    const int qrow = lane >> 2;
    const int qcol = (lane & 3) * 2;
    const int n0 = blockIdx.x * 128;

    {
        int row = tid >> 1, c0 = (tid & 1) * 64;
        int node = n0 + row;
        char* ph = sm + F_AH + row * PITCH_W_B + c0 * 2;
        char* pl = sm + F_AL + row * PITCH_W_B + c0 * 2;
#pragma unroll
        for (int q = 0; q < 8; q++) {
            float4 f0 = make_float4(0.f, 0.f, 0.f, 0.f), f1 = f0;
            if (node < N) {
                f0 = *(const float4*)(g_H + (size_t)node * OD + c0 + q * 8);
                f1 = *(const float4*)(g_H + (size_t)node * OD + c0 + q * 8 + 4);
            }
            uint32_t h0, l0, h1, l1, h2, l2, h3, l3;
            split2h(f0.x, f0.y, h0, l0); split2h(f0.z, f0.w, h1, l1);
            split2h(f1.x, f1.y, h2, l2); split2h(f1.z, f1.w, h3, l3);
            *(uint4*)(ph + q * 16) = make_uint4(h0, h1, h2, h3);
            *(uint4*)(pl + q * 16) = make_uint4(l0, l1, l2, l3);
        }
    }
    for (int t = tid; t < 2048; t += 256) {
        int k = t >> 4, c8 = (t & 15) << 3;
        *(uint4*)(sm + F_WH + k * PITCH_W_B + c8 * 2) = *(const uint4*)(g_W2_hi + k * OD + c8);
        *(uint4*)(sm + F_WL + k * PITCH_W_B + c8 * 2) = *(const uint4*)(g_W2_lo + k * OD + c8);
    }
    if (tid < 128) {
        int node = n0 + tid;
        ((float*)(sm + F_B2))[tid] = b2g[tid];
        ((float*)(sm + F_DEG))[tid] = (node < N) ? (float)g_cnt[node] : 0.f;
    }
    __syncthreads();

    const int m0 = wid * 16;
    uint32_t ahf[8][4], alf[8][4];
    {
        uint32_t ab_h = sb + F_AH + (m0 + l16) * PITCH_W_B + (lane >> 4) * 16;
        uint32_t ab_l = sb + F_AL + (m0 + l16) * PITCH_W_B + (lane >> 4) * 16;
#pragma unroll
        for (int k = 0; k < 8; k++) {
            ldmx4(ahf[k], ab_h + k * 32);
            ldmx4(alf[k], ab_l + k * 32);
        }
    }

    float acc[16][4];
#pragma unroll
    for (int i = 0; i < 16; i++)
#pragma unroll
        for (int j = 0; j < 4; j++) acc[i][j] = 0.f;
#pragma unroll
    for (int n2 = 0; n2 < 8; n2++) {
#pragma unroll
        for (int k = 0; k < 8; k++) {
            uint32_t bh[4], bl[4];
            uint32_t ba = (k * 16 + l16) * PITCH_W_B + n2 * 32 + (lane >> 4) * 16;
            ldmx4t(bh, sb + F_WH + ba);
            ldmx4t(bl, sb + F_WL + ba);
            mma_f16(acc[2 * n2],     ahf[k], bh);
            mma_f16(acc[2 * n2],     ahf[k], bl);
            mma_f16(acc[2 * n2],     alf[k], bh);
            mma_f16(acc[2 * n2 + 1], ahf[k], bh + 2);
            mma_f16(acc[2 * n2 + 1], ahf[k], bl + 2);
            mma_f16(acc[2 * n2 + 1], alf[k], bh + 2);
        }
    }

    const int node_lo = n0 + m0 + qrow;
    const int node_hi = node_lo + 8;
    const float deg_lo = ((float*)(sm + F_DEG))[m0 + qrow];
    const float deg_hi = ((float*)(sm + F_DEG))[m0 + qrow + 8];
#pragma unroll
    for (int n2 = 0; n2 < 8; n2++) {
#pragma unroll
        for (int hlf = 0; hlf < 2; hlf++) {
            int col = n2 * 16 + hlf * 8 + qcol;
            float2 b2c = *(const float2*)(sm + F_B2 + col * 4);
            float* a = acc[2 * n2 + hlf];
            if (node_lo < N)
                *(float2*)(out + (size_t)node_lo * OD + col) =
                    make_float2(a[0] + deg_lo * b2c.x, a[1] + deg_lo * b2c.y);
            if (node_hi < N)
                *(float2*)(out + (size_t)node_hi * OD + col) =
                    make_float2(a[2] + deg_hi * b2c.x, a[3] + deg_hi * b2c.y);
        }
    }
}

// ---------------------------------------------------------------------------
extern "C" void kernel_launch(void* const* d_in, const int* in_sizes, int n_in,
                              void* d_out, int out_size) {
    const float* h = (const float*)d_in[0];
    const void* edge_index = d_in[1];
    const float* ef = (const float*)d_in[2];
    const float *W1 = 0, *b1 = 0, *W2 = 0, *b2 = 0;
    for (int i = 3; i < n_in; i++) {
        int s = in_sizes[i];
        if (s == (2 * ND + ED) * OD) W1 = (const float*)d_in[i];
        else if (s == OD * OD) W2 = (const float*)d_in[i];
        else if (s == OD) { if (!b1) b1 = (const float*)d_in[i]; else b2 = (const float*)d_in[i]; }
    }
    if (!W1 || !b1 || !W2 || !b2) return;

    int N = in_sizes[0] / ND;
    if (N > MAXN) N = MAXN;
    long long E = (long long)(in_sizes[1] / 2);
    if (E > MAXE) E = MAXE;
    float* out = (float*)d_out;
    int n_tiles = (int)((E + TE - 1) / TE);
    int nb = (N + 127) / 128;
    int eb = (int)((E + 255) / 256);

    // Lazily created side streams + events (created on the first, eager call;
    // reused under graph capture where record/wait become graph edges).
    static cudaStream_t s1 = 0, s2 = 0;
    static cudaEvent_t e0 = 0, e1 = 0, e2 = 0;
    if (!s1) {
        cudaStreamCreateWithFlags(&s1, cudaStreamNonBlocking);
        cudaStreamCreateWithFlags(&s2, cudaStreamNonBlocking);
        cudaEventCreateWithFlags(&e0, cudaEventDisableTiming);
        cudaEventCreateWithFlags(&e1, cudaEventDisableTiming);
        cudaEventCreateWithFlags(&e2, cudaEventDisableTiming);
    }

    // fork point
    cudaEventRecord(e0, 0);
    cudaStreamWaitEvent(s1, e0, 0);
    cudaStreamWaitEvent(s2, e0, 0);

    // chain A (default stream): counting sort of edges by destination row
    zero_cnt_kernel<<<(N + 255) / 256, 256>>>(N);
    detect_idx_kernel<<<1, 32>>>((const int*)edge_index);
    hist_kernel<<<eb * 2, 128>>>(edge_index, E);
    scan_kernel<<<1, 1024>>>(N);
    scatter_sort_kernel<<<eb, 256>>>(edge_index, E);

    // chain B (s1): weight prep + P precompute
    prep_weights_kernel<<<128, 256, 0, s1>>>(W1, W2);
    cudaFuncSetAttribute(precompute_P_mma_kernel,
                         cudaFuncAttributeMaxDynamicSharedMemorySize, F_TOTAL);
    {
        dim3 pgrid(nb, 2);
        precompute_P_mma_kernel<<<pgrid, 256, F_TOTAL, s1>>>(h, N);
    }
    cudaEventRecord(e1, s1);

    // chain C (s2): zero H accumulator
    zero_H_kernel<<<(N * OD + 255) / 256, 256, 0, s2>>>(N * OD);
    cudaEventRecord(e2, s2);

    // join
    cudaStreamWaitEvent(0, e1, 0);
    cudaStreamWaitEvent(0, e2, 0);

    int egrid = 3 * NSM;
    if (egrid > n_tiles) egrid = n_tiles;
    edge_hidden_kernel<<<egrid, 256, E_TOTAL>>>(ef, b1, E, n_tiles);

    cudaFuncSetAttribute(final_out_mma_kernel,
                         cudaFuncAttributeMaxDynamicSharedMemorySize, F_TOTAL);
    final_out_mma_kernel<<<nb, 256, F_TOTAL>>>(b2, out, N);
}

// round 10
// speedup vs baseline: 4.2089x; 1.0016x over previous
#include <cuda_runtime.h>
#include <cuda_fp16.h>
#include <stdint.h>
#include <stddef.h>

#define ND 128
#define ED 32
#define OD 128
#define TE 128
#define MAXN 10000
#define MAXE 1048576
#define NSM 148

// ---------------- device scratch ----------------
__device__ float g_Pr[MAXN * OD];     // includes +b1 baked in
__device__ float g_Pc[MAXN * OD];
__device__ float g_H[MAXN * OD];
__device__ int   g_cnt[MAXN];
__device__ int   g_pos[MAXN];
__device__ int   g_srows[MAXE];
__device__ int   g_scols[MAXE];
__device__ int   g_perm[MAXE];
__device__ int   g_idx64;
__device__ __half g_ef16[MAXE * ED];  // preconverted edge features
__device__ __half g_W1ch[ED * OD];
__device__ __half g_Wab_hi[ND * 256];
__device__ __half g_Wab_lo[ND * 256];
__device__ __half g_W2_hi[OD * OD];
__device__ __half g_W2_lo[OD * OD];

// ---------------- edge-kernel smem ----------------
#define PITCH_EF_B 80
#define PITCH_W_B  272
#define E_W1   0                 // 32*272 = 8704
#define E_BUF  8704
#define BUF_ROWS 0
#define BUF_COLS 512
#define BUF_EF   1024            // 128*80 = 10240
#define E_BUFSZ  11264
#define E_TOTAL  (E_BUF + 2 * E_BUFSZ)   // 31232

// ---------------- precompute / final GEMM smem ----------------
#define F_AH 0
#define F_AL 34816
#define F_WH 69632
#define F_WL 104448
#define F_B2 139264
#define F_DEG 139776
#define F_TOTAL 140288

// ---------------- helpers ----------------
__device__ __forceinline__ uint32_t smem_u32(const void* p) {
    uint32_t a;
    asm("{ .reg .u64 t; cvta.to.shared.u64 t, %1; cvt.u32.u64 %0, t; }" : "=r"(a) : "l"(p));
    return a;
}
__device__ __forceinline__ void ldmx4(uint32_t* r, uint32_t addr) {
    asm volatile("ldmatrix.sync.aligned.m8n8.x4.shared.b16 {%0,%1,%2,%3}, [%4];"
                 : "=r"(r[0]), "=r"(r[1]), "=r"(r[2]), "=r"(r[3]) : "r"(addr));
}
__device__ __forceinline__ void ldmx4t(uint32_t* r, uint32_t addr) {
    asm volatile("ldmatrix.sync.aligned.m8n8.x4.trans.shared.b16 {%0,%1,%2,%3}, [%4];"
                 : "=r"(r[0]), "=r"(r[1]), "=r"(r[2]), "=r"(r[3]) : "r"(addr));
}
__device__ __forceinline__ void mma_f16(float* d, const uint32_t* a, const uint32_t* b) {
    asm volatile(
        "mma.sync.aligned.m16n8k16.row.col.f32.f16.f16.f32 "
        "{%0,%1,%2,%3},{%4,%5,%6,%7},{%8,%9},{%0,%1,%2,%3};"
        : "+f"(d[0]), "+f"(d[1]), "+f"(d[2]), "+f"(d[3])
        : "r"(a[0]), "r"(a[1]), "r"(a[2]), "r"(a[3]), "r"(b[0]), "r"(b[1]));
}
__device__ __forceinline__ uint32_t pack2h(float x0, float x1) {
    uint32_t r;
    asm("cvt.rn.f16x2.f32 %0, %1, %2;" : "=r"(r) : "f"(x1), "f"(x0));
    return r;
}
__device__ __forceinline__ void split2h(float x0, float x1, uint32_t& hi, uint32_t& lo) {
    __half h0 = __float2half_rn(x0);
    __half h1 = __float2half_rn(x1);
    hi = ((uint32_t)__half_as_ushort(h1) << 16) | __half_as_ushort(h0);
    lo = pack2h(x0 - __half2float(h0), x1 - __half2float(h1));
}

// ---------------------------------------------------------------------------
__global__ void zero_detect_kernel(const int* __restrict__ ei, int N) {
    int i = blockIdx.x * blockDim.x + threadIdx.x;
    if (i < N) g_cnt[i] = 0;
    if (blockIdx.x == 0 && threadIdx.x == 0) {
        int nz = 0;
        for (int q = 0; q < 64; q++)
            if (ei[2 * q + 1] != 0) nz++;
        g_idx64 = (nz == 0) ? 1 : 0;
    }
}
__global__ void zero_H_kernel(int nH) {
    int i = blockIdx.x * blockDim.x + threadIdx.x;
    if (i < nH) g_H[i] = 0.0f;
}
// Pre-convert edge features to fp16 (each thread: 16 floats = half a row)
__global__ void convert_ef_kernel(const float* __restrict__ ef, long long E) {
    long long t = (long long)blockIdx.x * blockDim.x + threadIdx.x;
    if (t < E * 2) {
        const float4* src = (const float4*)(ef + t * 16);
        uint32_t hv[8];
#pragma unroll
        for (int q = 0; q < 4; q++) {
            float4 f = src[q];
            hv[2 * q]     = pack2h(f.x, f.y);
            hv[2 * q + 1] = pack2h(f.z, f.w);
        }
        uint4* dst = (uint4*)(g_ef16 + t * 16);
        dst[0] = make_uint4(hv[0], hv[1], hv[2], hv[3]);
        dst[1] = make_uint4(hv[4], hv[5], hv[6], hv[7]);
    }
}
__global__ void prep_weights_kernel(const float* __restrict__ W1, const float* __restrict__ W2) {
    int t = blockIdx.x * blockDim.x + threadIdx.x;
    if (t < OD * OD) {
        float x = W2[t];
        __half hh = __float2half_rn(x);
        g_W2_hi[t] = hh;
        g_W2_lo[t] = __float2half_rn(x - __half2float(hh));
    }
    if (t < ED * OD) g_W1ch[t] = __float2half_rn(W1[(size_t)(2 * ND) * OD + t]);
    if (t < ND * 256) {
        int k = t >> 8, n = t & 255;
        float x = (n < 128) ? W1[(size_t)k * OD + n] : W1[(size_t)(ND + k) * OD + (n - 128)];
        __half hh = __float2half_rn(x);
        g_Wab_hi[t] = hh;
        g_Wab_lo[t] = __float2half_rn(x - __half2float(hh));
    }
}

// ---------------- counting sort by row ----------------
__global__ void hist_kernel(const void* __restrict__ ei, long long E) {
    long long e = (long long)blockIdx.x * blockDim.x + threadIdx.x;
    if (e < E) {
        int r = g_idx64 ? (int)((const long long*)ei)[e] : ((const int*)ei)[e];
        asm volatile("red.global.add.s32 [%0], %1;" :: "l"(&g_cnt[r]), "r"(1) : "memory");
    }
}
__global__ __launch_bounds__(1024) void scan_kernel(int N) {
    __shared__ int s[10240];
    __shared__ int wsum[32];
    int tid = threadIdx.x;
    for (int i = tid; i < N; i += 1024) s[i] = g_cnt[i];
    __syncthreads();
    int per = (N + 1023) / 1024;       // <= 10
    int base = tid * per;
    int loc[10];
    int local = 0;
#pragma unroll
    for (int i = 0; i < 10; i++) {
        int idx = base + i;
        int v = (i < per && idx < N) ? s[idx] : 0;
        loc[i] = v;
        local += v;
    }
    int lane = tid & 31, w = tid >> 5;
    int x = local;
    for (int d = 1; d < 32; d <<= 1) {
        int y = __shfl_up_sync(0xFFFFFFFFu, x, d);
        if (lane >= d) x += y;
    }
    if (lane == 31) wsum[w] = x;
    __syncthreads();
    if (w == 0) {
        int v = wsum[lane];
        for (int d = 1; d < 32; d <<= 1) {
            int y = __shfl_up_sync(0xFFFFFFFFu, v, d);
            if (lane >= d) v += y;
        }
        wsum[lane] = v;
    }
    __syncthreads();
    int run = x - local + (w > 0 ? wsum[w - 1] : 0);
#pragma unroll
    for (int i = 0; i < 10; i++) {
        int idx = base + i;
        if (i < per && idx < N) {
            s[idx] = run;
            run += loc[i];
        }
    }
    __syncthreads();
    for (int i = tid; i < N; i += 1024) g_pos[i] = s[i];
}
__global__ void scatter_sort_kernel(const void* __restrict__ ei, long long E) {
    long long e = (long long)blockIdx.x * blockDim.x + threadIdx.x;
    if (e < E) {
        int r, c;
        if (g_idx64) {
            r = (int)((const long long*)ei)[e];
            c = (int)((const long long*)ei)[E + e];
        } else {
            r = ((const int*)ei)[e];
            c = ((const int*)ei)[E + e];
        }
        int pos = atomicAdd(&g_pos[r], 1);
        g_srows[pos] = r;
        g_scols[pos] = c;
        g_perm[pos] = (int)e;
    }
}

// ---------------------------------------------------------------------------
// HMMA precompute: grid (nb, 2). p==0 -> Pr = h@W1a + b1 ; p==1 -> Pc = h@W1b.
__global__ __launch_bounds__(256, 1) void precompute_P_mma_kernel(
    const float* __restrict__ h, const float* __restrict__ b1g, int N) {
    extern __shared__ char sm[];
    const uint32_t sb = smem_u32(sm);
    const int tid = threadIdx.x;
    const int wid = tid >> 5;
    const int lane = tid & 31;
    const int l16 = lane & 15;
    const int qrow = lane >> 2;
    const int qcol = (lane & 3) * 2;
    const int n0 = blockIdx.x * 128;
    const int p = blockIdx.y;

    {
        int row = tid >> 1, c0 = (tid & 1) * 64;
        int node = n0 + row;
        char* ph = sm + F_AH + row * PITCH_W_B + c0 * 2;
        char* pl = sm + F_AL + row * PITCH_W_B + c0 * 2;
#pragma unroll
        for (int q = 0; q < 8; q++) {
            float4 f0 = make_float4(0.f, 0.f, 0.f, 0.f), f1 = f0;
            if (node < N) {
                f0 = *(const float4*)(h + (size_t)node * ND + c0 + q * 8);
                f1 = *(const float4*)(h + (size_t)node * ND + c0 + q * 8 + 4);
            }
            uint32_t h0, l0, h1, l1, h2, l2, h3, l3;
            split2h(f0.x, f0.y, h0, l0); split2h(f0.z, f0.w, h1, l1);
            split2h(f1.x, f1.y, h2, l2); split2h(f1.z, f1.w, h3, l3);
            *(uint4*)(ph + q * 16) = make_uint4(h0, h1, h2, h3);
            *(uint4*)(pl + q * 16) = make_uint4(l0, l1, l2, l3);
        }
    }
    for (int t = tid; t < 2048; t += 256) {
        int k = t >> 4, c8 = (t & 15) << 3;
        *(uint4*)(sm + F_WH + k * PITCH_W_B + c8 * 2) =
            *(const uint4*)(g_Wab_hi + k * 256 + p * 128 + c8);
        *(uint4*)(sm + F_WL + k * PITCH_W_B + c8 * 2) =
            *(const uint4*)(g_Wab_lo + k * 256 + p * 128 + c8);
    }
    __syncthreads();

    const int m0 = wid * 16;
    uint32_t ahf[8][4], alf[8][4];
    {
        uint32_t ab_h = sb + F_AH + (m0 + l16) * PITCH_W_B + (lane >> 4) * 16;
        uint32_t ab_l = sb + F_AL + (m0 + l16) * PITCH_W_B + (lane >> 4) * 16;
#pragma unroll
        for (int k = 0; k < 8; k++) {
            ldmx4(ahf[k], ab_h + k * 32);
            ldmx4(alf[k], ab_l + k * 32);
        }
    }

    float acc[16][4];
#pragma unroll
    for (int i = 0; i < 16; i++)
#pragma unroll
        for (int j = 0; j < 4; j++) acc[i][j] = 0.f;
#pragma unroll
    for (int n2 = 0; n2 < 8; n2++) {
#pragma unroll
        for (int k = 0; k < 8; k++) {
            uint32_t bh[4], bl[4];
            uint32_t ba = (k * 16 + l16) * PITCH_W_B + n2 * 32 + (lane >> 4) * 16;
            ldmx4t(bh, sb + F_WH + ba);
            ldmx4t(bl, sb + F_WL + ba);
            mma_f16(acc[2 * n2],     ahf[k], bh);
            mma_f16(acc[2 * n2],     ahf[k], bl);
            mma_f16(acc[2 * n2],     alf[k], bh);
            mma_f16(acc[2 * n2 + 1], ahf[k], bh + 2);
            mma_f16(acc[2 * n2 + 1], ahf[k], bl + 2);
            mma_f16(acc[2 * n2 + 1], alf[k], bh + 2);
        }
    }
    float* base = (p == 0) ? g_Pr : g_Pc;
    const int node_lo = n0 + m0 + qrow;
    const int node_hi = node_lo + 8;
#pragma unroll
    for (int n2 = 0; n2 < 8; n2++) {
#pragma unroll
        for (int hlf = 0; hlf < 2; hlf++) {
            int col = n2 * 16 + hlf * 8 + qcol;
            float2 b1c = make_float2(0.f, 0.f);
            if (p == 0) b1c = *(const float2*)(b1g + col);
            float* a = acc[2 * n2 + hlf];
            if (node_lo < N)
                *(float2*)(base + (size_t)node_lo * OD + col) =
                    make_float2(a[0] + b1c.x, a[1] + b1c.y);
            if (node_hi < N)
                *(float2*)(base + (size_t)node_hi * OD + col) =
                    make_float2(a[2] + b1c.x, a[3] + b1c.y);
        }
    }
}

// ---------------------------------------------------------------------------
// Edge kernel over SORTED edges, double-buffered staging (1 sync/tile).
// hidden = relu(Pr'[r]+Pc[c]+ef@W1c); segmented warp-reduce; head lanes RED.
__global__ __launch_bounds__(256, 3) void edge_hidden_kernel(
    long long E, int n_tiles) {
    extern __shared__ char sm[];
    const uint32_t sb = smem_u32(sm);
    const int tid = threadIdx.x;
    const int wid = tid >> 5;
    const int lane = tid & 31;
    const unsigned FULL = 0xFFFFFFFFu;

    for (int t = tid; t < 512; t += 256) {
        int k = t >> 4, n8 = (t & 15) << 3;
        *(uint4*)(sm + E_W1 + k * PITCH_W_B + n8 * 2) = *(const uint4*)(g_W1ch + k * OD + n8);
    }

    const int m0 = wid * 16;
    const int qrow = lane >> 2;
    const int qcol = (lane & 3) * 2;
    const int l16 = lane & 15;
    const uint32_t blane_off = l16 * PITCH_W_B + (lane >> 4) * 16;

    // ---- prologue: stage first tile into buf 0 ----
    {
        const long long e00 = (long long)blockIdx.x * TE;
        if (tid < TE) {
            long long p = e00 + tid;
            int r = 0, c = 0;
            if (p < E) { r = g_srows[p]; c = g_scols[p]; }
            *(int*)(sm + E_BUF + BUF_ROWS + tid * 4) = r;
            *(int*)(sm + E_BUF + BUF_COLS + tid * 4) = c;
        }
        {
            int er = tid >> 1, c0h = (tid & 1) * 16;
            long long p = e00 + er;
            uint4 v0 = make_uint4(0, 0, 0, 0), v1 = v0;
            if (p < E) {
                long long e = (long long)g_perm[p];
                const uint4* pf = (const uint4*)(g_ef16 + e * ED + c0h);
                v0 = pf[0]; v1 = pf[1];
            }
            char* ph = sm + E_BUF + BUF_EF + er * PITCH_EF_B + c0h * 2;
            *(uint4*)ph = v0;
            *(uint4*)(ph + 16) = v1;
        }
    }
    __syncthreads();

    int it = 0;
    for (int tile = blockIdx.x; tile < n_tiles; tile += gridDim.x, it++) {
        const long long e0 = (long long)tile * TE;
        const uint32_t cb = E_BUF + (uint32_t)(it & 1) * E_BUFSZ;
        const uint32_t nb2 = E_BUF + (uint32_t)((it + 1) & 1) * E_BUFSZ;
        const int ntile = tile + gridDim.x;
        const bool has_next = ntile < n_tiles;

        // ---- early-issue next tile loads ----
        int nr = 0, nc = 0;
        uint4 nv0 = make_uint4(0, 0, 0, 0), nv1 = nv0;
        if (has_next) {
            long long e0n = (long long)ntile * TE;
            if (tid < TE) {
                long long p = e0n + tid;
                if (p < E) { nr = g_srows[p]; nc = g_scols[p]; }
            }
            {
                long long p = e0n + (tid >> 1);
                if (p < E) {
                    long long e = (long long)g_perm[p];
                    const uint4* pf = (const uint4*)(g_ef16 + e * ED + (tid & 1) * 16);
                    nv0 = pf[0]; nv1 = pf[1];
                }
            }
        }

        // ---- compute current tile ----
        int* s_rows = (int*)(sm + cb + BUF_ROWS);
        int* s_cols = (int*)(sm + cb + BUF_COLS);
        const uint32_t efA = sb + cb + BUF_EF + (m0 + l16) * PITCH_EF_B + ((lane >> 4) * 8) * 2;

        const int e_lo = m0 + qrow, e_hi = e_lo + 8;
        const int r_lo = s_rows[e_lo], r_hi = s_rows[e_hi];
        const int c_lo = s_cols[e_lo], c_hi = s_cols[e_hi];
        const bool v_lo = (e0 + e_lo) < E;
        const bool v_hi = (e0 + e_hi) < E;
        const float* prl_base = g_Pr + (size_t)r_lo * OD;
        const float* prh_base = g_Pr + (size_t)r_hi * OD;
        const float* pcl_base = g_Pc + (size_t)c_lo * OD;
        const float* pch_base = g_Pc + (size_t)c_hi * OD;
        float* Hlo = g_H + (size_t)r_lo * OD;
        float* Hhi = g_H + (size_t)r_hi * OD;

        int rt;
        rt = __shfl_down_sync(FULL, r_lo, 4);  const bool s1l = (qrow < 7) && (rt == r_lo);
        rt = __shfl_down_sync(FULL, r_lo, 8);  const bool s2l = (qrow < 6) && (rt == r_lo);
        rt = __shfl_down_sync(FULL, r_lo, 16); const bool s4l = (qrow < 4) && (rt == r_lo);
        rt = __shfl_up_sync(FULL, r_lo, 4);    const bool hl  = (qrow == 0) || (rt != r_lo);
        rt = __shfl_down_sync(FULL, r_hi, 4);  const bool s1h = (qrow < 7) && (rt == r_hi);
        rt = __shfl_down_sync(FULL, r_hi, 8);  const bool s2h = (qrow < 6) && (rt == r_hi);
        rt = __shfl_down_sync(FULL, r_hi, 16); const bool s4h = (qrow < 4) && (rt == r_hi);
        rt = __shfl_up_sync(FULL, r_hi, 4);    const bool hh  = (qrow == 0) || (rt != r_hi);

        uint32_t eh[2][4];
        ldmx4(eh[0], efA);
        ldmx4(eh[1], efA + 32);

#pragma unroll
        for (int g = 0; g < 4; g++) {
            float2 prl[4], prh[4], pcl[4], pch[4];
#pragma unroll
            for (int cc = 0; cc < 4; cc++) {
                int col = (4 * g + cc) * 8 + qcol;
                prl[cc] = *(const float2*)(prl_base + col);
                prh[cc] = *(const float2*)(prh_base + col);
                pcl[cc] = *(const float2*)(pcl_base + col);
                pch[cc] = *(const float2*)(pch_base + col);
            }
#pragma unroll
            for (int t = 0; t < 2; t++) {
                int n2 = 2 * g + t;
                float a8[8];
#pragma unroll
                for (int j = 0; j < 8; j++) a8[j] = 0.f;
#pragma unroll
                for (int k = 0; k < 2; k++) {
                    uint32_t b[4];
                    ldmx4t(b, sb + E_W1 + k * 16 * PITCH_W_B + n2 * 32 + blane_off);
                    mma_f16(a8,     eh[k], b);
                    mma_f16(a8 + 4, eh[k], b + 2);
                }
#pragma unroll
                for (int u = 0; u < 2; u++) {
                    int cc = 2 * t + u;
                    int c = 4 * g + cc;
                    int col = c * 8 + qcol;
                    float h0 = fmaxf(a8[u*4+0] + prl[cc].x + pcl[cc].x, 0.f);
                    float h1 = fmaxf(a8[u*4+1] + prl[cc].y + pcl[cc].y, 0.f);
                    float h2 = fmaxf(a8[u*4+2] + prh[cc].x + pch[cc].x, 0.f);
                    float h3 = fmaxf(a8[u*4+3] + prh[cc].y + pch[cc].y, 0.f);
                    if (!v_lo) { h0 = 0.f; h1 = 0.f; }
                    if (!v_hi) { h2 = 0.f; h3 = 0.f; }
                    float s;
                    s = __shfl_down_sync(FULL, h0, 4);  if (s1l) h0 += s;
                    s = __shfl_down_sync(FULL, h0, 8);  if (s2l) h0 += s;
                    s = __shfl_down_sync(FULL, h0, 16); if (s4l) h0 += s;
                    s = __shfl_down_sync(FULL, h1, 4);  if (s1l) h1 += s;
                    s = __shfl_down_sync(FULL, h1, 8);  if (s2l) h1 += s;
                    s = __shfl_down_sync(FULL, h1, 16); if (s4l) h1 += s;
                    s = __shfl_down_sync(FULL, h2, 4);  if (s1h) h2 += s;
                    s = __shfl_down_sync(FULL, h2, 8);  if (s2h) h2 += s;
                    s = __shfl_down_sync(FULL, h2, 16); if (s4h) h2 += s;
                    s = __shfl_down_sync(FULL, h3, 4);  if (s1h) h3 += s;
                    s = __shfl_down_sync(FULL, h3, 8);  if (s2h) h3 += s;
                    s = __shfl_down_sync(FULL, h3, 16); if (s4h) h3 += s;
                    if (hl)
                        asm volatile("red.global.add.v2.f32 [%0], {%1,%2};"
                                     :: "l"(Hlo + col), "f"(h0), "f"(h1) : "memory");
                    if (hh)
                        asm volatile("red.global.add.v2.f32 [%0], {%1,%2};"
                                     :: "l"(Hhi + col), "f"(h2), "f"(h3) : "memory");
                }
            }
        }

        // ---- store next tile into alternate buffer (safe: last read of that
        //      buffer was before the previous sync), then the single sync ----
        if (has_next) {
            if (tid < TE) {
                *(int*)(sm + nb2 + BUF_ROWS + tid * 4) = nr;
                *(int*)(sm + nb2 + BUF_COLS + tid * 4) = nc;
            }
            char* ph = sm + nb2 + BUF_EF + (tid >> 1) * PITCH_EF_B + ((tid & 1) * 16) * 2;
            *(uint4*)ph = nv0;
            *(uint4*)(ph + 16) = nv1;
        }
        __syncthreads();
    }
}

// ---------------------------------------------------------------------------
// Final: out = g_H @ W2 + deg * b2 (3-term split, ~fp32 accuracy)
__global__ __launch_bounds__(256, 1) void final_out_mma_kernel(
    const float* __restrict__ b2g, float* __restrict__ out, int N) {
    extern __shared__ char sm[];
    const uint32_t sb = smem_u32(sm);
    const int tid = threadIdx.x;
    const int wid = tid >> 5;
    const int lane = tid & 31;
    const int l16 = lane & 15;
    const int qrow = lane >> 2;
    const int qcol = (lane & 3) * 2;
    const int n0 = blockIdx.x * 128;

    {
        int row = tid >> 1, c0 = (tid & 1) * 64;
        int node = n0 + row;
        char* ph = sm + F_AH + row * PITCH_W_B + c0 * 2;
        char* pl = sm + F_AL + row * PITCH_W_B + c0 * 2;
#pragma unroll
        for (int q = 0; q < 8; q++) {
            float4 f0 = make_float4(0.f, 0.f, 0.f, 0.f), f1 = f0;
            if (node < N) {
                f0 = *(const float4*)(g_H + (size_t)node * OD + c0 + q * 8);
                f1 = *(const float4*)(g_H + (size_t)node * OD + c0 + q * 8 + 4);
            }
            uint32_t h0, l0, h1, l1, h2, l2, h3, l3;
            split2h(f0.x, f0.y, h0, l0); split2h(f0.z, f0.w, h1, l1);
            split2h(f1.x, f1.y, h2, l2); split2h(f1.z, f1.w, h3, l3);
            *(uint4*)(ph + q * 16) = make_uint4(h0, h1, h2, h3);
            *(uint4*)(pl + q * 16) = make_uint4(l0, l1, l2, l3);
        }
    }
    for (int t = tid; t < 2048; t += 256) {
        int k = t >> 4, c8 = (t & 15) << 3;
        *(uint4*)(sm + F_WH + k * PITCH_W_B + c8 * 2) = *(const uint4*)(g_W2_hi + k * OD + c8);
        *(uint4*)(sm + F_WL + k * PITCH_W_B + c8 * 2) = *(const uint4*)(g_W2_lo + k * OD + c8);
    }
    if (tid < 128) {
        int node = n0 + tid;
        ((float*)(sm + F_B2))[tid] = b2g[tid];
        ((float*)(sm + F_DEG))[tid] = (node < N) ? (float)g_cnt[node] : 0.f;
    }
    __syncthreads();

    const int m0 = wid * 16;
    uint32_t ahf[8][4], alf[8][4];
    {
        uint32_t ab_h = sb + F_AH + (m0 + l16) * PITCH_W_B + (lane >> 4) * 16;
        uint32_t ab_l = sb + F_AL + (m0 + l16) * PITCH_W_B + (lane >> 4) * 16;
#pragma unroll
        for (int k = 0; k < 8; k++) {
            ldmx4(ahf[k], ab_h + k * 32);
            ldmx4(alf[k], ab_l + k * 32);
        }
    }

    float acc[16][4];
#pragma unroll
    for (int i = 0; i < 16; i++)
#pragma unroll
        for (int j = 0; j < 4; j++) acc[i][j] = 0.f;
#pragma unroll
    for (int n2 = 0; n2 < 8; n2++) {
#pragma unroll
        for (int k = 0; k < 8; k++) {
            uint32_t bh[4], bl[4];
            uint32_t ba = (k * 16 + l16) * PITCH_W_B + n2 * 32 + (lane >> 4) * 16;
            ldmx4t(bh, sb + F_WH + ba);
            ldmx4t(bl, sb + F_WL + ba);
            mma_f16(acc[2 * n2],     ahf[k], bh);
            mma_f16(acc[2 * n2],     ahf[k], bl);
            mma_f16(acc[2 * n2],     alf[k], bh);
            mma_f16(acc[2 * n2 + 1], ahf[k], bh + 2);
            mma_f16(acc[2 * n2 + 1], ahf[k], bl + 2);
            mma_f16(acc[2 * n2 + 1], alf[k], bh + 2);
        }
    }

    const int node_lo = n0 + m0 + qrow;
    const int node_hi = node_lo + 8;
    const float deg_lo = ((float*)(sm + F_DEG))[m0 + qrow];
    const float deg_hi = ((float*)(sm + F_DEG))[m0 + qrow + 8];
#pragma unroll
    for (int n2 = 0; n2 < 8; n2++) {
#pragma unroll
        for (int hlf = 0; hlf < 2; hlf++) {
            int col = n2 * 16 + hlf * 8 + qcol;
            float2 b2c = *(const float2*)(sm + F_B2 + col * 4);
            float* a = acc[2 * n2 + hlf];
            if (node_lo < N)
                *(float2*)(out + (size_t)node_lo * OD + col) =
                    make_float2(a[0] + deg_lo * b2c.x, a[1] + deg_lo * b2c.y);
            if (node_hi < N)
                *(float2*)(out + (size_t)node_hi * OD + col) =
                    make_float2(a[2] + deg_hi * b2c.x, a[3] + deg_hi * b2c.y);
        }
    }
}

// ---------------------------------------------------------------------------
extern "C" void kernel_launch(void* const* d_in, const int* in_sizes, int n_in,
                              void* d_out, int out_size) {
    const float* h = (const float*)d_in[0];
    const void* edge_index = d_in[1];
    const float* ef = (const float*)d_in[2];
    const float *W1 = 0, *b1 = 0, *W2 = 0, *b2 = 0;
    for (int i = 3; i < n_in; i++) {
        int s = in_sizes[i];
        if (s == (2 * ND + ED) * OD) W1 = (const float*)d_in[i];
        else if (s == OD * OD) W2 = (const float*)d_in[i];
        else if (s == OD) { if (!b1) b1 = (const float*)d_in[i]; else b2 = (const float*)d_in[i]; }
    }
    if (!W1 || !b1 || !W2 || !b2) return;

    int N = in_sizes[0] / ND;
    if (N > MAXN) N = MAXN;
    long long E = (long long)(in_sizes[1] / 2);
    if (E > MAXE) E = MAXE;
    float* out = (float*)d_out;
    int n_tiles = (int)((E + TE - 1) / TE);
    int nb = (N + 127) / 128;
    int eb = (int)((E + 255) / 256);

    static cudaStream_t s1 = 0, s2 = 0;
    static cudaEvent_t e0 = 0, e1 = 0, e2 = 0;
    if (!s1) {
        cudaStreamCreateWithFlags(&s1, cudaStreamNonBlocking);
        cudaStreamCreateWithFlags(&s2, cudaStreamNonBlocking);
        cudaEventCreateWithFlags(&e0, cudaEventDisableTiming);
        cudaEventCreateWithFlags(&e1, cudaEventDisableTiming);
        cudaEventCreateWithFlags(&e2, cudaEventDisableTiming);
    }

    // fork
    cudaEventRecord(e0, 0);
    cudaStreamWaitEvent(s1, e0, 0);
    cudaStreamWaitEvent(s2, e0, 0);

    // chain A (default): counting sort of edges by destination row
    zero_detect_kernel<<<(N + 255) / 256, 256>>>((const int*)edge_index, N);
    hist_kernel<<<eb * 2, 128>>>(edge_index, E);
    scan_kernel<<<1, 1024>>>(N);
    scatter_sort_kernel<<<eb, 256>>>(edge_index, E);

    // chain B (s1): weight prep + P precompute (+b1 baked into Pr)
    prep_weights_kernel<<<128, 256, 0, s1>>>(W1, W2);
    cudaFuncSetAttribute(precompute_P_mma_kernel,
                         cudaFuncAttributeMaxDynamicSharedMemorySize, F_TOTAL);
    {
        dim3 pgrid(nb, 2);
        precompute_P_mma_kernel<<<pgrid, 256, F_TOTAL, s1>>>(h, b1, N);
    }
    cudaEventRecord(e1, s1);

    // chain C (s2): ef fp16 preconvert + zero H
    convert_ef_kernel<<<(int)((E * 2 + 255) / 256), 256, 0, s2>>>(ef, E);
    zero_H_kernel<<<(N * OD + 255) / 256, 256, 0, s2>>>(N * OD);
    cudaEventRecord(e2, s2);

    // join
    cudaStreamWaitEvent(0, e1, 0);
    cudaStreamWaitEvent(0, e2, 0);

    int egrid = 3 * NSM;
    if (egrid > n_tiles) egrid = n_tiles;
    edge_hidden_kernel<<<egrid, 256, E_TOTAL>>>(E, n_tiles);

    cudaFuncSetAttribute(final_out_mma_kernel,
                         cudaFuncAttributeMaxDynamicSharedMemorySize, F_TOTAL);
    final_out_mma_kernel<<<nb, 256, F_TOTAL>>>(b2, out, N);
}

// round 11
// speedup vs baseline: 4.2622x; 1.0127x over previous
#include <cuda_runtime.h>
#include <cuda_fp16.h>
#include <stdint.h>
#include <stddef.h>

#define ND 128
#define ED 32
#define OD 128
#define TE 128
#define MAXN 10000
#define MAXE 1048576
#define NSM 148

// ---------------- device scratch ----------------
__device__ float g_Pr[MAXN * OD];     // includes +b1 baked in
__device__ float g_Pc[MAXN * OD];
__device__ float g_H[MAXN * OD];
__device__ int   g_cnt[MAXN];
__device__ int   g_pos[MAXN];
__device__ int4  g_epack[MAXE];       // {row, col, perm, 0} sorted by row
__device__ int   g_idx64;
__device__ __half g_ef16[MAXE * ED];  // preconverted edge features
__device__ __half g_W1ch[ED * OD];
__device__ __half g_Wab_hi[ND * 256];
__device__ __half g_Wab_lo[ND * 256];
__device__ __half g_W2_hi[OD * OD];
__device__ __half g_W2_lo[OD * OD];

// ---------------- edge-kernel smem ----------------
#define PITCH_EF_B 80
#define PITCH_W_B  272
#define E_W1   0                 // 32*272 = 8704
#define E_BUF  8704
#define BUF_ROWS 0
#define BUF_COLS 512
#define BUF_EF   1024            // 128*80 = 10240
#define E_BUFSZ  11264
#define E_TOTAL  (E_BUF + 2 * E_BUFSZ)   // 31232

// ---------------- precompute / final GEMM smem ----------------
#define F_AH 0
#define F_AL 34816
#define F_WH 69632
#define F_WL 104448
#define F_B2 139264
#define F_DEG 139776
#define F_TOTAL 140288

// ---------------- helpers ----------------
__device__ __forceinline__ uint32_t smem_u32(const void* p) {
    uint32_t a;
    asm("{ .reg .u64 t; cvta.to.shared.u64 t, %1; cvt.u32.u64 %0, t; }" : "=r"(a) : "l"(p));
    return a;
}
__device__ __forceinline__ void ldmx4(uint32_t* r, uint32_t addr) {
    asm volatile("ldmatrix.sync.aligned.m8n8.x4.shared.b16 {%0,%1,%2,%3}, [%4];"
                 : "=r"(r[0]), "=r"(r[1]), "=r"(r[2]), "=r"(r[3]) : "r"(addr));
}
__device__ __forceinline__ void ldmx4t(uint32_t* r, uint32_t addr) {
    asm volatile("ldmatrix.sync.aligned.m8n8.x4.trans.shared.b16 {%0,%1,%2,%3}, [%4];"
                 : "=r"(r[0]), "=r"(r[1]), "=r"(r[2]), "=r"(r[3]) : "r"(addr));
}
__device__ __forceinline__ void mma_f16(float* d, const uint32_t* a, const uint32_t* b) {
    asm volatile(
        "mma.sync.aligned.m16n8k16.row.col.f32.f16.f16.f32 "
        "{%0,%1,%2,%3},{%4,%5,%6,%7},{%8,%9},{%0,%1,%2,%3};"
        : "+f"(d[0]), "+f"(d[1]), "+f"(d[2]), "+f"(d[3])
        : "r"(a[0]), "r"(a[1]), "r"(a[2]), "r"(a[3]), "r"(b[0]), "r"(b[1]));
}
__device__ __forceinline__ uint32_t pack2h(float x0, float x1) {
    uint32_t r;
    asm("cvt.rn.f16x2.f32 %0, %1, %2;" : "=r"(r) : "f"(x1), "f"(x0));
    return r;
}
__device__ __forceinline__ void split2h(float x0, float x1, uint32_t& hi, uint32_t& lo) {
    __half h0 = __float2half_rn(x0);
    __half h1 = __float2half_rn(x1);
    hi = ((uint32_t)__half_as_ushort(h1) << 16) | __half_as_ushort(h0);
    lo = pack2h(x0 - __half2float(h0), x1 - __half2float(h1));
}

// ---------------------------------------------------------------------------
__global__ void zero_detect_kernel(const int* __restrict__ ei, int N) {
    int i = blockIdx.x * blockDim.x + threadIdx.x;
    if (i < N) g_cnt[i] = 0;
    if (blockIdx.x == 0 && threadIdx.x == 0) {
        int nz = 0;
        for (int q = 0; q < 64; q++)
            if (ei[2 * q + 1] != 0) nz++;
        g_idx64 = (nz == 0) ? 1 : 0;
    }
}
__global__ void zero_H_kernel(int nH) {
    int i = blockIdx.x * blockDim.x + threadIdx.x;
    if (i < nH) g_H[i] = 0.0f;
}
__global__ void convert_ef_kernel(const float* __restrict__ ef, long long E) {
    long long t = (long long)blockIdx.x * blockDim.x + threadIdx.x;
    if (t < E * 2) {
        const float4* src = (const float4*)(ef + t * 16);
        uint32_t hv[8];
#pragma unroll
        for (int q = 0; q < 4; q++) {
            float4 f = src[q];
            hv[2 * q]     = pack2h(f.x, f.y);
            hv[2 * q + 1] = pack2h(f.z, f.w);
        }
        uint4* dst = (uint4*)(g_ef16 + t * 16);
        dst[0] = make_uint4(hv[0], hv[1], hv[2], hv[3]);
        dst[1] = make_uint4(hv[4], hv[5], hv[6], hv[7]);
    }
}
__global__ void prep_weights_kernel(const float* __restrict__ W1, const float* __restrict__ W2) {
    int t = blockIdx.x * blockDim.x + threadIdx.x;
    if (t < OD * OD) {
        float x = W2[t];
        __half hh = __float2half_rn(x);
        g_W2_hi[t] = hh;
        g_W2_lo[t] = __float2half_rn(x - __half2float(hh));
    }
    if (t < ED * OD) g_W1ch[t] = __float2half_rn(W1[(size_t)(2 * ND) * OD + t]);
    if (t < ND * 256) {
        int k = t >> 8, n = t & 255;
        float x = (n < 128) ? W1[(size_t)k * OD + n] : W1[(size_t)(ND + k) * OD + (n - 128)];
        __half hh = __float2half_rn(x);
        g_Wab_hi[t] = hh;
        g_Wab_lo[t] = __float2half_rn(x - __half2float(hh));
    }
}

// ---------------- counting sort by row ----------------
__global__ void hist_kernel(const void* __restrict__ ei, long long E) {
    long long e = (long long)blockIdx.x * blockDim.x + threadIdx.x;
    if (e < E) {
        int r = g_idx64 ? (int)((const long long*)ei)[e] : ((const int*)ei)[e];
        asm volatile("red.global.add.s32 [%0], %1;" :: "l"(&g_cnt[r]), "r"(1) : "memory");
    }
}
__global__ __launch_bounds__(1024) void scan_kernel(int N) {
    __shared__ int s[10240];
    __shared__ int wsum[32];
    int tid = threadIdx.x;
    for (int i = tid; i < N; i += 1024) s[i] = g_cnt[i];
    __syncthreads();
    int per = (N + 1023) / 1024;
    int base = tid * per;
    int loc[10];
    int local = 0;
#pragma unroll
    for (int i = 0; i < 10; i++) {
        int idx = base + i;
        int v = (i < per && idx < N) ? s[idx] : 0;
        loc[i] = v;
        local += v;
    }
    int lane = tid & 31, w = tid >> 5;
    int x = local;
    for (int d = 1; d < 32; d <<= 1) {
        int y = __shfl_up_sync(0xFFFFFFFFu, x, d);
        if (lane >= d) x += y;
    }
    if (lane == 31) wsum[w] = x;
    __syncthreads();
    if (w == 0) {
        int v = wsum[lane];
        for (int d = 1; d < 32; d <<= 1) {
            int y = __shfl_up_sync(0xFFFFFFFFu, v, d);
            if (lane >= d) v += y;
        }
        wsum[lane] = v;
    }
    __syncthreads();
    int run = x - local + (w > 0 ? wsum[w - 1] : 0);
#pragma unroll
    for (int i = 0; i < 10; i++) {
        int idx = base + i;
        if (i < per && idx < N) {
            s[idx] = run;
            run += loc[i];
        }
    }
    __syncthreads();
    for (int i = tid; i < N; i += 1024) g_pos[i] = s[i];
}
// 4 edges/thread; all atomics issued before consumers (MLP=4); single STG.128.
__global__ void scatter_sort_kernel(const void* __restrict__ ei, long long E) {
    long long b = ((long long)blockIdx.x * blockDim.x + threadIdx.x) * 4;
    if (b >= E) return;
    int n = (E - b) >= 4 ? 4 : (int)(E - b);
    const int is64 = g_idx64;
    int r[4], c[4], p[4];
#pragma unroll
    for (int i = 0; i < 4; i++) {
        long long e = b + i;
        if (i < n) {
            if (is64) {
                r[i] = (int)((const long long*)ei)[e];
                c[i] = (int)((const long long*)ei)[E + e];
            } else {
                r[i] = ((const int*)ei)[e];
                c[i] = ((const int*)ei)[E + e];
            }
        }
    }
#pragma unroll
    for (int i = 0; i < 4; i++)
        if (i < n) p[i] = atomicAdd(&g_pos[r[i]], 1);
#pragma unroll
    for (int i = 0; i < 4; i++)
        if (i < n) g_epack[p[i]] = make_int4(r[i], c[i], (int)(b + i), 0);
}

// ---------------------------------------------------------------------------
// HMMA precompute: grid (nb, 2). p==0 -> Pr = h@W1a + b1 ; p==1 -> Pc = h@W1b.
__global__ __launch_bounds__(256, 1) void precompute_P_mma_kernel(
    const float* __restrict__ h, const float* __restrict__ b1g, int N) {
    extern __shared__ char sm[];
    const uint32_t sb = smem_u32(sm);
    const int tid = threadIdx.x;
    const int wid = tid >> 5;
    const int lane = tid & 31;
    const int l16 = lane & 15;
    const int qrow = lane >> 2;
    const int qcol = (lane & 3) * 2;
    const int n0 = blockIdx.x * 128;
    const int p = blockIdx.y;

    {
        int row = tid >> 1, c0 = (tid & 1) * 64;
        int node = n0 + row;
        char* ph = sm + F_AH + row * PITCH_W_B + c0 * 2;
        char* pl = sm + F_AL + row * PITCH_W_B + c0 * 2;
#pragma unroll
        for (int q = 0; q < 8; q++) {
            float4 f0 = make_float4(0.f, 0.f, 0.f, 0.f), f1 = f0;
            if (node < N) {
                f0 = *(const float4*)(h + (size_t)node * ND + c0 + q * 8);
                f1 = *(const float4*)(h + (size_t)node * ND + c0 + q * 8 + 4);
            }
            uint32_t h0, l0, h1, l1, h2, l2, h3, l3;
            split2h(f0.x, f0.y, h0, l0); split2h(f0.z, f0.w, h1, l1);
            split2h(f1.x, f1.y, h2, l2); split2h(f1.z, f1.w, h3, l3);
            *(uint4*)(ph + q * 16) = make_uint4(h0, h1, h2, h3);
            *(uint4*)(pl + q * 16) = make_uint4(l0, l1, l2, l3);
        }
    }
    for (int t = tid; t < 2048; t += 256) {
        int k = t >> 4, c8 = (t & 15) << 3;
        *(uint4*)(sm + F_WH + k * PITCH_W_B + c8 * 2) =
            *(const uint4*)(g_Wab_hi + k * 256 + p * 128 + c8);
        *(uint4*)(sm + F_WL + k * PITCH_W_B + c8 * 2) =
            *(const uint4*)(g_Wab_lo + k * 256 + p * 128 + c8);
    }
    __syncthreads();

    const int m0 = wid * 16;
    uint32_t ahf[8][4], alf[8][4];
    {
        uint32_t ab_h = sb + F_AH + (m0 + l16) * PITCH_W_B + (lane >> 4) * 16;
        uint32_t ab_l = sb + F_AL + (m0 + l16) * PITCH_W_B + (lane >> 4) * 16;
#pragma unroll
        for (int k = 0; k < 8; k++) {
            ldmx4(ahf[k], ab_h + k * 32);
            ldmx4(alf[k], ab_l + k * 32);
        }
    }

    float acc[16][4];
#pragma unroll
    for (int i = 0; i < 16; i++)
#pragma unroll
        for (int j = 0; j < 4; j++) acc[i][j] = 0.f;
#pragma unroll
    for (int n2 = 0; n2 < 8; n2++) {
#pragma unroll
        for (int k = 0; k < 8; k++) {
            uint32_t bh[4], bl[4];
            uint32_t ba = (k * 16 + l16) * PITCH_W_B + n2 * 32 + (lane >> 4) * 16;
            ldmx4t(bh, sb + F_WH + ba);
            ldmx4t(bl, sb + F_WL + ba);
            mma_f16(acc[2 * n2],     ahf[k], bh);
            mma_f16(acc[2 * n2],     ahf[k], bl);
            mma_f16(acc[2 * n2],     alf[k], bh);
            mma_f16(acc[2 * n2 + 1], ahf[k], bh + 2);
            mma_f16(acc[2 * n2 + 1], ahf[k], bl + 2);
            mma_f16(acc[2 * n2 + 1], alf[k], bh + 2);
        }
    }
    float* base = (p == 0) ? g_Pr : g_Pc;
    const int node_lo = n0 + m0 + qrow;
    const int node_hi = node_lo + 8;
#pragma unroll
    for (int n2 = 0; n2 < 8; n2++) {
#pragma unroll
        for (int hlf = 0; hlf < 2; hlf++) {
            int col = n2 * 16 + hlf * 8 + qcol;
            float2 b1c = make_float2(0.f, 0.f);
            if (p == 0) b1c = *(const float2*)(b1g + col);
            float* a = acc[2 * n2 + hlf];
            if (node_lo < N)
                *(float2*)(base + (size_t)node_lo * OD + col) =
                    make_float2(a[0] + b1c.x, a[1] + b1c.y);
            if (node_hi < N)
                *(float2*)(base + (size_t)node_hi * OD + col) =
                    make_float2(a[2] + b1c.x, a[3] + b1c.y);
        }
    }
}

// ---------------------------------------------------------------------------
// Edge kernel over SORTED edges (packed int4), double-buffered staging.
__global__ __launch_bounds__(256, 3) void edge_hidden_kernel(
    long long E, int n_tiles) {
    extern __shared__ char sm[];
    const uint32_t sb = smem_u32(sm);
    const int tid = threadIdx.x;
    const int wid = tid >> 5;
    const int lane = tid & 31;
    const unsigned FULL = 0xFFFFFFFFu;

    for (int t = tid; t < 512; t += 256) {
        int k = t >> 4, n8 = (t & 15) << 3;
        *(uint4*)(sm + E_W1 + k * PITCH_W_B + n8 * 2) = *(const uint4*)(g_W1ch + k * OD + n8);
    }

    const int m0 = wid * 16;
    const int qrow = lane >> 2;
    const int qcol = (lane & 3) * 2;
    const int l16 = lane & 15;
    const uint32_t blane_off = l16 * PITCH_W_B + (lane >> 4) * 16;

    // ---- prologue: stage first tile into buf 0 ----
    {
        const long long e00 = (long long)blockIdx.x * TE;
        int perm0 = 0;
        if (tid < TE) {
            long long p = e00 + tid;
            int4 pk = make_int4(0, 0, 0, 0);
            if (p < E) pk = g_epack[p];
            *(int*)(sm + E_BUF + BUF_ROWS + tid * 4) = pk.x;
            *(int*)(sm + E_BUF + BUF_COLS + tid * 4) = pk.y;
            perm0 = pk.z;
        }
        // broadcast perms for ef staging: thread pair (2t,2t+1) stages edge t
        {
            int er = tid >> 1, c0h = (tid & 1) * 16;
            long long p = e00 + er;
            uint4 v0 = make_uint4(0, 0, 0, 0), v1 = v0;
            if (p < E) {
                long long e = (long long)g_epack[p].z;
                const uint4* pf = (const uint4*)(g_ef16 + e * ED + c0h);
                v0 = pf[0]; v1 = pf[1];
            }
            char* ph = sm + E_BUF + BUF_EF + er * PITCH_EF_B + c0h * 2;
            *(uint4*)ph = v0;
            *(uint4*)(ph + 16) = v1;
        }
        (void)perm0;
    }
    __syncthreads();

    int it = 0;
    for (int tile = blockIdx.x; tile < n_tiles; tile += gridDim.x, it++) {
        const long long e0 = (long long)tile * TE;
        const uint32_t cb = E_BUF + (uint32_t)(it & 1) * E_BUFSZ;
        const uint32_t nb2 = E_BUF + (uint32_t)((it + 1) & 1) * E_BUFSZ;
        const int ntile = tile + gridDim.x;
        const bool has_next = ntile < n_tiles;

        // ---- early-issue next tile loads ----
        int4 npk = make_int4(0, 0, 0, 0);
        uint4 nv0 = make_uint4(0, 0, 0, 0), nv1 = nv0;
        if (has_next) {
            long long e0n = (long long)ntile * TE;
            if (tid < TE) {
                long long p = e0n + tid;
                if (p < E) npk = g_epack[p];
            }
            {
                long long p = e0n + (tid >> 1);
                if (p < E) {
                    long long e = (long long)g_epack[p].z;
                    const uint4* pf = (const uint4*)(g_ef16 + e * ED + (tid & 1) * 16);
                    nv0 = pf[0]; nv1 = pf[1];
                }
            }
        }

        // ---- compute current tile ----
        int* s_rows = (int*)(sm + cb + BUF_ROWS);
        int* s_cols = (int*)(sm + cb + BUF_COLS);
        const uint32_t efA = sb + cb + BUF_EF + (m0 + l16) * PITCH_EF_B + ((lane >> 4) * 8) * 2;

        const int e_lo = m0 + qrow, e_hi = e_lo + 8;
        const int r_lo = s_rows[e_lo], r_hi = s_rows[e_hi];
        const int c_lo = s_cols[e_lo], c_hi = s_cols[e_hi];
        const bool v_lo = (e0 + e_lo) < E;
        const bool v_hi = (e0 + e_hi) < E;
        const float* prl_base = g_Pr + (size_t)r_lo * OD;
        const float* prh_base = g_Pr + (size_t)r_hi * OD;
        const float* pcl_base = g_Pc + (size_t)c_lo * OD;
        const float* pch_base = g_Pc + (size_t)c_hi * OD;
        float* Hlo = g_H + (size_t)r_lo * OD;
        float* Hhi = g_H + (size_t)r_hi * OD;

        int rt;
        rt = __shfl_down_sync(FULL, r_lo, 4);  const bool s1l = (qrow < 7) && (rt == r_lo);
        rt = __shfl_down_sync(FULL, r_lo, 8);  const bool s2l = (qrow < 6) && (rt == r_lo);
        rt = __shfl_down_sync(FULL, r_lo, 16); const bool s4l = (qrow < 4) && (rt == r_lo);
        rt = __shfl_up_sync(FULL, r_lo, 4);    const bool hl  = (qrow == 0) || (rt != r_lo);
        rt = __shfl_down_sync(FULL, r_hi, 4);  const bool s1h = (qrow < 7) && (rt == r_hi);
        rt = __shfl_down_sync(FULL, r_hi, 8);  const bool s2h = (qrow < 6) && (rt == r_hi);
        rt = __shfl_down_sync(FULL, r_hi, 16); const bool s4h = (qrow < 4) && (rt == r_hi);
        rt = __shfl_up_sync(FULL, r_hi, 4);    const bool hh  = (qrow == 0) || (rt != r_hi);

        uint32_t eh[2][4];
        ldmx4(eh[0], efA);
        ldmx4(eh[1], efA + 32);

#pragma unroll
        for (int g = 0; g < 4; g++) {
            float2 prl[4], prh[4], pcl[4], pch[4];
#pragma unroll
            for (int cc = 0; cc < 4; cc++) {
                int col = (4 * g + cc) * 8 + qcol;
                prl[cc] = *(const float2*)(prl_base + col);
                prh[cc] = *(const float2*)(prh_base + col);
                pcl[cc] = *(const float2*)(pcl_base + col);
                pch[cc] = *(const float2*)(pch_base + col);
            }
#pragma unroll
            for (int t = 0; t < 2; t++) {
                int n2 = 2 * g + t;
                float a8[8];
#pragma unroll
                for (int j = 0; j < 8; j++) a8[j] = 0.f;
#pragma unroll
                for (int k = 0; k < 2; k++) {
                    uint32_t b[4];
                    ldmx4t(b, sb + E_W1 + k * 16 * PITCH_W_B + n2 * 32 + blane_off);
                    mma_f16(a8,     eh[k], b);
                    mma_f16(a8 + 4, eh[k], b + 2);
                }
#pragma unroll
                for (int u = 0; u < 2; u++) {
                    int cc = 2 * t + u;
                    int c = 4 * g + cc;
                    int col = c * 8 + qcol;
                    float h0 = fmaxf(a8[u*4+0] + prl[cc].x + pcl[cc].x, 0.f);
                    float h1 = fmaxf(a8[u*4+1] + prl[cc].y + pcl[cc].y, 0.f);
                    float h2 = fmaxf(a8[u*4+2] + prh[cc].x + pch[cc].x, 0.f);
                    float h3 = fmaxf(a8[u*4+3] + prh[cc].y + pch[cc].y, 0.f);
                    if (!v_lo) { h0 = 0.f; h1 = 0.f; }
                    if (!v_hi) { h2 = 0.f; h3 = 0.f; }
                    float s;
                    s = __shfl_down_sync(FULL, h0, 4);  if (s1l) h0 += s;
                    s = __shfl_down_sync(FULL, h0, 8);  if (s2l) h0 += s;
                    s = __shfl_down_sync(FULL, h0, 16); if (s4l) h0 += s;
                    s = __shfl_down_sync(FULL, h1, 4);  if (s1l) h1 += s;
                    s = __shfl_down_sync(FULL, h1, 8);  if (s2l) h1 += s;
                    s = __shfl_down_sync(FULL, h1, 16); if (s4l) h1 += s;
                    s = __shfl_down_sync(FULL, h2, 4);  if (s1h) h2 += s;
                    s = __shfl_down_sync(FULL, h2, 8);  if (s2h) h2 += s;
                    s = __shfl_down_sync(FULL, h2, 16); if (s4h) h2 += s;
                    s = __shfl_down_sync(FULL, h3, 4);  if (s1h) h3 += s;
                    s = __shfl_down_sync(FULL, h3, 8);  if (s2h) h3 += s;
                    s = __shfl_down_sync(FULL, h3, 16); if (s4h) h3 += s;
                    if (hl)
                        asm volatile("red.global.add.v2.f32 [%0], {%1,%2};"
                                     :: "l"(Hlo + col), "f"(h0), "f"(h1) : "memory");
                    if (hh)
                        asm volatile("red.global.add.v2.f32 [%0], {%1,%2};"
                                     :: "l"(Hhi + col), "f"(h2), "f"(h3) : "memory");
                }
            }
        }

        // ---- store next tile into alternate buffer, single sync ----
        if (has_next) {
            if (tid < TE) {
                *(int*)(sm + nb2 + BUF_ROWS + tid * 4) = npk.x;
                *(int*)(sm + nb2 + BUF_COLS + tid * 4) = npk.y;
            }
            char* ph = sm + nb2 + BUF_EF + (tid >> 1) * PITCH_EF_B + ((tid & 1) * 16) * 2;
            *(uint4*)ph = nv0;
            *(uint4*)(ph + 16) = nv1;
        }
        __syncthreads();
    }
}

// ---------------------------------------------------------------------------
// Final: out = g_H @ W2 + deg * b2 (3-term split, ~fp32 accuracy)
__global__ __launch_bounds__(256, 1) void final_out_mma_kernel(
    const float* __restrict__ b2g, float* __restrict__ out, int N) {
    extern __shared__ char sm[];
    const uint32_t sb = smem_u32(sm);
    const int tid = threadIdx.x;
    const int wid = tid >> 5;
    const int lane = tid & 31;
    const int l16 = lane & 15;
    const int qrow = lane >> 2;
    const int qcol = (lane & 3) * 2;
    const int n0 = blockIdx.x * 128;

    {
        int row = tid >> 1, c0 = (tid & 1) * 64;
        int node = n0 + row;
        char* ph = sm + F_AH + row * PITCH_W_B + c0 * 2;
        char* pl = sm + F_AL + row * PITCH_W_B + c0 * 2;
#pragma unroll
        for (int q = 0; q < 8; q++) {
            float4 f0 = make_float4(0.f, 0.f, 0.f, 0.f), f1 = f0;
            if (node < N) {
                f0 = *(const float4*)(g_H + (size_t)node * OD + c0 + q * 8);
                f1 = *(const float4*)(g_H + (size_t)node * OD + c0 + q * 8 + 4);
            }
            uint32_t h0, l0, h1, l1, h2, l2, h3, l3;
            split2h(f0.x, f0.y, h0, l0); split2h(f0.z, f0.w, h1, l1);
            split2h(f1.x, f1.y, h2, l2); split2h(f1.z, f1.w, h3, l3);
            *(uint4*)(ph + q * 16) = make_uint4(h0, h1, h2, h3);
            *(uint4*)(pl + q * 16) = make_uint4(l0, l1, l2, l3);
        }
    }
    for (int t = tid; t < 2048; t += 256) {
        int k = t >> 4, c8 = (t & 15) << 3;
        *(uint4*)(sm + F_WH + k * PITCH_W_B + c8 * 2) = *(const uint4*)(g_W2_hi + k * OD + c8);
        *(uint4*)(sm + F_WL + k * PITCH_W_B + c8 * 2) = *(const uint4*)(g_W2_lo + k * OD + c8);
    }
    if (tid < 128) {
        int node = n0 + tid;
        ((float*)(sm + F_B2))[tid] = b2g[tid];
        ((float*)(sm + F_DEG))[tid] = (node < N) ? (float)g_cnt[node] : 0.f;
    }
    __syncthreads();

    const int m0 = wid * 16;
    uint32_t ahf[8][4], alf[8][4];
    {
        uint32_t ab_h = sb + F_AH + (m0 + l16) * PITCH_W_B + (lane >> 4) * 16;
        uint32_t ab_l = sb + F_AL + (m0 + l16) * PITCH_W_B + (lane >> 4) * 16;
#pragma unroll
        for (int k = 0; k < 8; k++) {
            ldmx4(ahf[k], ab_h + k * 32);
            ldmx4(alf[k], ab_l + k * 32);
        }
    }

    float acc[16][4];
#pragma unroll
    for (int i = 0; i < 16; i++)
#pragma unroll
        for (int j = 0; j < 4; j++) acc[i][j] = 0.f;
#pragma unroll
    for (int n2 = 0; n2 < 8; n2++) {
#pragma unroll
        for (int k = 0; k < 8; k++) {
            uint32_t bh[4], bl[4];
            uint32_t ba = (k * 16 + l16) * PITCH_W_B + n2 * 32 + (lane >> 4) * 16;
            ldmx4t(bh, sb + F_WH + ba);
            ldmx4t(bl, sb + F_WL + ba);
            mma_f16(acc[2 * n2],     ahf[k], bh);
            mma_f16(acc[2 * n2],     ahf[k], bl);
            mma_f16(acc[2 * n2],     alf[k], bh);
            mma_f16(acc[2 * n2 + 1], ahf[k], bh + 2);
            mma_f16(acc[2 * n2 + 1], ahf[k], bl + 2);
            mma_f16(acc[2 * n2 + 1], alf[k], bh + 2);
        }
    }

    const int node_lo = n0 + m0 + qrow;
    const int node_hi = node_lo + 8;
    const float deg_lo = ((float*)(sm + F_DEG))[m0 + qrow];
    const float deg_hi = ((float*)(sm + F_DEG))[m0 + qrow + 8];
#pragma unroll
    for (int n2 = 0; n2 < 8; n2++) {
#pragma unroll
        for (int hlf = 0; hlf < 2; hlf++) {
            int col = n2 * 16 + hlf * 8 + qcol;
            float2 b2c = *(const float2*)(sm + F_B2 + col * 4);
            float* a = acc[2 * n2 + hlf];
            if (node_lo < N)
                *(float2*)(out + (size_t)node_lo * OD + col) =
                    make_float2(a[0] + deg_lo * b2c.x, a[1] + deg_lo * b2c.y);
            if (node_hi < N)
                *(float2*)(out + (size_t)node_hi * OD + col) =
                    make_float2(a[2] + deg_hi * b2c.x, a[3] + deg_hi * b2c.y);
        }
    }
}

// ---------------------------------------------------------------------------
extern "C" void kernel_launch(void* const* d_in, const int* in_sizes, int n_in,
                              void* d_out, int out_size) {
    const float* h = (const float*)d_in[0];
    const void* edge_index = d_in[1];
    const float* ef = (const float*)d_in[2];
    const float *W1 = 0, *b1 = 0, *W2 = 0, *b2 = 0;
    for (int i = 3; i < n_in; i++) {
        int s = in_sizes[i];
        if (s == (2 * ND + ED) * OD) W1 = (const float*)d_in[i];
        else if (s == OD * OD) W2 = (const float*)d_in[i];
        else if (s == OD) { if (!b1) b1 = (const float*)d_in[i]; else b2 = (const float*)d_in[i]; }
    }
    if (!W1 || !b1 || !W2 || !b2) return;

    int N = in_sizes[0] / ND;
    if (N > MAXN) N = MAXN;
    long long E = (long long)(in_sizes[1] / 2);
    if (E > MAXE) E = MAXE;
    float* out = (float*)d_out;
    int n_tiles = (int)((E + TE - 1) / TE);
    int nb = (N + 127) / 128;
    int eb = (int)((E + 255) / 256);

    static cudaStream_t s1 = 0, s2 = 0;
    static cudaEvent_t e0 = 0, e1 = 0, e2 = 0;
    if (!s1) {
        cudaStreamCreateWithFlags(&s1, cudaStreamNonBlocking);
        cudaStreamCreateWithFlags(&s2, cudaStreamNonBlocking);
        cudaEventCreateWithFlags(&e0, cudaEventDisableTiming);
        cudaEventCreateWithFlags(&e1, cudaEventDisableTiming);
        cudaEventCreateWithFlags(&e2, cudaEventDisableTiming);
    }

    // fork
    cudaEventRecord(e0, 0);
    cudaStreamWaitEvent(s1, e0, 0);
    cudaStreamWaitEvent(s2, e0, 0);

    // chain A (default): counting sort of edges by destination row
    zero_detect_kernel<<<(N + 255) / 256, 256>>>((const int*)edge_index, N);
    hist_kernel<<<eb * 2, 128>>>(edge_index, E);
    scan_kernel<<<1, 1024>>>(N);
    scatter_sort_kernel<<<(int)((E + 1023) / 1024), 256>>>(edge_index, E);

    // chain B (s1): weight prep + P precompute (+b1 baked into Pr)
    prep_weights_kernel<<<128, 256, 0, s1>>>(W1, W2);
    cudaFuncSetAttribute(precompute_P_mma_kernel,
                         cudaFuncAttributeMaxDynamicSharedMemorySize, F_TOTAL);
    {
        dim3 pgrid(nb, 2);
        precompute_P_mma_kernel<<<pgrid, 256, F_TOTAL, s1>>>(h, b1, N);
    }
    cudaEventRecord(e1, s1);

    // chain C (s2): ef fp16 preconvert + zero H
    convert_ef_kernel<<<(int)((E * 2 + 255) / 256), 256, 0, s2>>>(ef, E);
    zero_H_kernel<<<(N * OD + 255) / 256, 256, 0, s2>>>(N * OD);
    cudaEventRecord(e2, s2);

    // join
    cudaStreamWaitEvent(0, e1, 0);
    cudaStreamWaitEvent(0, e2, 0);

    int egrid = 3 * NSM;
    if (egrid > n_tiles) egrid = n_tiles;
    edge_hidden_kernel<<<egrid, 256, E_TOTAL>>>(E, n_tiles);

    cudaFuncSetAttribute(final_out_mma_kernel,
                         cudaFuncAttributeMaxDynamicSharedMemorySize, F_TOTAL);
    final_out_mma_kernel<<<nb, 256, F_TOTAL>>>(b2, out, N);
}

// round 13
// speedup vs baseline: 4.5802x; 1.0746x over previous
#include <cuda_runtime.h>
#include <cuda_fp16.h>
#include <stdint.h>
#include <stddef.h>

#define ND 128
#define ED 32
#define OD 128
#define TE 128
#define MAXN 10000
#define MAXE 1048576
#define NSM 148

// ---------------- device scratch ----------------
__device__ float g_Pr[MAXN * OD];     // includes +b1 baked in
__device__ float g_Pc[MAXN * OD];
__device__ float g_H[MAXN * OD];
__device__ int   g_cnt[MAXN];
__device__ int   g_pos[MAXN];
__device__ int4  g_epack[MAXE];       // {row, col, perm, 0} sorted by row
__device__ int   g_idx64;
__device__ __half g_ef16[MAXE * ED];  // preconverted edge features
__device__ __half g_W1ch[ED * OD];
__device__ __half g_Wab_hi[ND * 256];
__device__ __half g_Wab_lo[ND * 256];
__device__ __half g_W2_hi[OD * OD];
__device__ __half g_W2_lo[OD * OD];

// ---------------- edge-kernel smem ----------------
#define PITCH_EF_B 80
#define PITCH_W_B  272
#define E_W1   0                 // 32*272 = 8704
#define E_BUF  8704
#define BUF_ROWS 0
#define BUF_COLS 512
#define BUF_EF   1024            // 128*80 = 10240
#define E_BUFSZ  11264
#define E_TOTAL  (E_BUF + 2 * E_BUFSZ)   // 31232

// ---------------- precompute / final GEMM smem ----------------
#define F_AH 0
#define F_AL 34816
#define F_WH 69632
#define F_WL 104448
#define F_B2 139264
#define F_DEG 139776
#define F_TOTAL 140288

// ---------------- helpers ----------------
__device__ __forceinline__ uint32_t smem_u32(const void* p) {
    uint32_t a;
    asm("{ .reg .u64 t; cvta.to.shared.u64 t, %1; cvt.u32.u64 %0, t; }" : "=r"(a) : "l"(p));
    return a;
}
__device__ __forceinline__ void ldmx4(uint32_t* r, uint32_t addr) {
    asm volatile("ldmatrix.sync.aligned.m8n8.x4.shared.b16 {%0,%1,%2,%3}, [%4];"
                 : "=r"(r[0]), "=r"(r[1]), "=r"(r[2]), "=r"(r[3]) : "r"(addr));
}
__device__ __forceinline__ void ldmx4t(uint32_t* r, uint32_t addr) {
    asm volatile("ldmatrix.sync.aligned.m8n8.x4.trans.shared.b16 {%0,%1,%2,%3}, [%4];"
                 : "=r"(r[0]), "=r"(r[1]), "=r"(r[2]), "=r"(r[3]) : "r"(addr));
}
__device__ __forceinline__ void mma_f16(float* d, const uint32_t* a, const uint32_t* b) {
    asm volatile(
        "mma.sync.aligned.m16n8k16.row.col.f32.f16.f16.f32 "
        "{%0,%1,%2,%3},{%4,%5,%6,%7},{%8,%9},{%0,%1,%2,%3};"
        : "+f"(d[0]), "+f"(d[1]), "+f"(d[2]), "+f"(d[3])
        : "r"(a[0]), "r"(a[1]), "r"(a[2]), "r"(a[3]), "r"(b[0]), "r"(b[1]));
}
__device__ __forceinline__ uint32_t pack2h(float x0, float x1) {
    uint32_t r;
    asm("cvt.rn.f16x2.f32 %0, %1, %2;" : "=r"(r) : "f"(x1), "f"(x0));
    return r;
}
__device__ __forceinline__ void split2h(float x0, float x1, uint32_t& hi, uint32_t& lo) {
    __half h0 = __float2half_rn(x0);
    __half h1 = __float2half_rn(x1);
    hi = ((uint32_t)__half_as_ushort(h1) << 16) | __half_as_ushort(h0);
    lo = pack2h(x0 - __half2float(h0), x1 - __half2float(h1));
}

// ---------------------------------------------------------------------------
__global__ void zero_detect_kernel(const int* __restrict__ ei, int N) {
    int i = blockIdx.x * blockDim.x + threadIdx.x;
    if (i < N) g_cnt[i] = 0;
    if (blockIdx.x == 0 && threadIdx.x == 0) {
        int nz = 0;
        for (int q = 0; q < 64; q++)
            if (ei[2 * q + 1] != 0) nz++;
        g_idx64 = (nz == 0) ? 1 : 0;
    }
}
__global__ void zero_H_kernel(int nH) {
    int i = blockIdx.x * blockDim.x + threadIdx.x;
    if (i < nH) g_H[i] = 0.0f;
}
__global__ void convert_ef_kernel(const float* __restrict__ ef, long long E) {
    long long t = (long long)blockIdx.x * blockDim.x + threadIdx.x;
    if (t < E * 2) {
        const float4* src = (const float4*)(ef + t * 16);
        uint32_t hv[8];
#pragma unroll
        for (int q = 0; q < 4; q++) {
            float4 f = src[q];
            hv[2 * q]     = pack2h(f.x, f.y);
            hv[2 * q + 1] = pack2h(f.z, f.w);
        }
        uint4* dst = (uint4*)(g_ef16 + t * 16);
        dst[0] = make_uint4(hv[0], hv[1], hv[2], hv[3]);
        dst[1] = make_uint4(hv[4], hv[5], hv[6], hv[7]);
    }
}
__global__ void prep_weights_kernel(const float* __restrict__ W1, const float* __restrict__ W2) {
    int t = blockIdx.x * blockDim.x + threadIdx.x;
    if (t < OD * OD) {
        float x = W2[t];
        __half hh = __float2half_rn(x);
        g_W2_hi[t] = hh;
        g_W2_lo[t] = __float2half_rn(x - __half2float(hh));
    }
    if (t < ED * OD) g_W1ch[t] = __float2half_rn(W1[(size_t)(2 * ND) * OD + t]);
    if (t < ND * 256) {
        int k = t >> 8, n = t & 255;
        float x = (n < 128) ? W1[(size_t)k * OD + n] : W1[(size_t)(ND + k) * OD + (n - 128)];
        __half hh = __float2half_rn(x);
        g_Wab_hi[t] = hh;
        g_Wab_lo[t] = __float2half_rn(x - __half2float(hh));
    }
}

// ---------------- counting sort by row ----------------
__global__ void hist_kernel(const void* __restrict__ ei, long long E) {
    long long e = (long long)blockIdx.x * blockDim.x + threadIdx.x;
    if (e < E) {
        int r = g_idx64 ? (int)((const long long*)ei)[e] : ((const int*)ei)[e];
        asm volatile("red.global.add.s32 [%0], %1;" :: "l"(&g_cnt[r]), "r"(1) : "memory");
    }
}
__global__ __launch_bounds__(1024) void scan_kernel(int N) {
    __shared__ int s[10240];
    __shared__ int wsum[32];
    int tid = threadIdx.x;
    for (int i = tid; i < N; i += 1024) s[i] = g_cnt[i];
    __syncthreads();
    int per = (N + 1023) / 1024;
    int base = tid * per;
    int loc[10];
    int local = 0;
#pragma unroll
    for (int i = 0; i < 10; i++) {
        int idx = base + i;
        int v = (i < per && idx < N) ? s[idx] : 0;
        loc[i] = v;
        local += v;
    }
    int lane = tid & 31, w = tid >> 5;
    int x = local;
    for (int d = 1; d < 32; d <<= 1) {
        int y = __shfl_up_sync(0xFFFFFFFFu, x, d);
        if (lane >= d) x += y;
    }
    if (lane == 31) wsum[w] = x;
    __syncthreads();
    if (w == 0) {
        int v = wsum[lane];
        for (int d = 1; d < 32; d <<= 1) {
            int y = __shfl_up_sync(0xFFFFFFFFu, v, d);
            if (lane >= d) v += y;
        }
        wsum[lane] = v;
    }
    __syncthreads();
    int run = x - local + (w > 0 ? wsum[w - 1] : 0);
#pragma unroll
    for (int i = 0; i < 10; i++) {
        int idx = base + i;
        if (i < per && idx < N) {
            s[idx] = run;
            run += loc[i];
        }
    }
    __syncthreads();
    for (int i = tid; i < N; i += 1024) g_pos[i] = s[i];
}
// 8 edges/thread; all atomics in flight before consumers (MLP=8); STG.128.
__global__ void scatter_sort_kernel(const void* __restrict__ ei, long long E) {
    long long b = ((long long)blockIdx.x * blockDim.x + threadIdx.x) * 8;
    if (b >= E) return;
    int n = (E - b) >= 8 ? 8 : (int)(E - b);
    const int is64 = g_idx64;
    int r[8], c[8], p[8];
#pragma unroll
    for (int i = 0; i < 8; i++) {
        long long e = b + i;
        if (i < n) {
            if (is64) {
                r[i] = (int)((const long long*)ei)[e];
                c[i] = (int)((const long long*)ei)[E + e];
            } else {
                r[i] = ((const int*)ei)[e];
                c[i] = ((const int*)ei)[E + e];
            }
        }
    }
#pragma unroll
    for (int i = 0; i < 8; i++)
        if (i < n) p[i] = atomicAdd(&g_pos[r[i]], 1);
#pragma unroll
    for (int i = 0; i < 8; i++)
        if (i < n) g_epack[p[i]] = make_int4(r[i], c[i], (int)(b + i), 0);
}

// ---------------------------------------------------------------------------
// HMMA precompute: grid (nb, 2). p==0 -> Pr = h@W1a + b1 ; p==1 -> Pc = h@W1b.
__global__ __launch_bounds__(256, 1) void precompute_P_mma_kernel(
    const float* __restrict__ h, const float* __restrict__ b1g, int N) {
    extern __shared__ char sm[];
    const uint32_t sb = smem_u32(sm);
    const int tid = threadIdx.x;
    const int wid = tid >> 5;
    const int lane = tid & 31;
    const int l16 = lane & 15;
    const int qrow = lane >> 2;
    const int qcol = (lane & 3) * 2;
    const int n0 = blockIdx.x * 128;
    const int p = blockIdx.y;

    {
        int row = tid >> 1, c0 = (tid & 1) * 64;
        int node = n0 + row;
        char* ph = sm + F_AH + row * PITCH_W_B + c0 * 2;
        char* pl = sm + F_AL + row * PITCH_W_B + c0 * 2;
#pragma unroll
        for (int q = 0; q < 8; q++) {
            float4 f0 = make_float4(0.f, 0.f, 0.f, 0.f), f1 = f0;
            if (node < N) {
                f0 = *(const float4*)(h + (size_t)node * ND + c0 + q * 8);
                f1 = *(const float4*)(h + (size_t)node * ND + c0 + q * 8 + 4);
            }
            uint32_t h0, l0, h1, l1, h2, l2, h3, l3;
            split2h(f0.x, f0.y, h0, l0); split2h(f0.z, f0.w, h1, l1);
            split2h(f1.x, f1.y, h2, l2); split2h(f1.z, f1.w, h3, l3);
            *(uint4*)(ph + q * 16) = make_uint4(h0, h1, h2, h3);
            *(uint4*)(pl + q * 16) = make_uint4(l0, l1, l2, l3);
        }
    }
    for (int t = tid; t < 2048; t += 256) {
        int k = t >> 4, c8 = (t & 15) << 3;
        *(uint4*)(sm + F_WH + k * PITCH_W_B + c8 * 2) =
            *(const uint4*)(g_Wab_hi + k * 256 + p * 128 + c8);
        *(uint4*)(sm + F_WL + k * PITCH_W_B + c8 * 2) =
            *(const uint4*)(g_Wab_lo + k * 256 + p * 128 + c8);
    }
    __syncthreads();

    const int m0 = wid * 16;
    uint32_t ahf[8][4], alf[8][4];
    {
        uint32_t ab_h = sb + F_AH + (m0 + l16) * PITCH_W_B + (lane >> 4) * 16;
        uint32_t ab_l = sb + F_AL + (m0 + l16) * PITCH_W_B + (lane >> 4) * 16;
#pragma unroll
        for (int k = 0; k < 8; k++) {
            ldmx4(ahf[k], ab_h + k * 32);
            ldmx4(alf[k], ab_l + k * 32);
        }
    }

    float acc[16][4];
#pragma unroll
    for (int i = 0; i < 16; i++)
#pragma unroll
        for (int j = 0; j < 4; j++) acc[i][j] = 0.f;
#pragma unroll
    for (int n2 = 0; n2 < 8; n2++) {
#pragma unroll
        for (int k = 0; k < 8; k++) {
            uint32_t bh[4], bl[4];
            uint32_t ba = (k * 16 + l16) * PITCH_W_B + n2 * 32 + (lane >> 4) * 16;
            ldmx4t(bh, sb + F_WH + ba);
            ldmx4t(bl, sb + F_WL + ba);
            mma_f16(acc[2 * n2],     ahf[k], bh);
            mma_f16(acc[2 * n2],     ahf[k], bl);
            mma_f16(acc[2 * n2],     alf[k], bh);
            mma_f16(acc[2 * n2 + 1], ahf[k], bh + 2);
            mma_f16(acc[2 * n2 + 1], ahf[k], bl + 2);
            mma_f16(acc[2 * n2 + 1], alf[k], bh + 2);
        }
    }
    float* base = (p == 0) ? g_Pr : g_Pc;
    const int node_lo = n0 + m0 + qrow;
    const int node_hi = node_lo + 8;
#pragma unroll
    for (int n2 = 0; n2 < 8; n2++) {
#pragma unroll
        for (int hlf = 0; hlf < 2; hlf++) {
            int col = n2 * 16 + hlf * 8 + qcol;
            float2 b1c = make_float2(0.f, 0.f);
            if (p == 0) b1c = *(const float2*)(b1g + col);
            float* a = acc[2 * n2 + hlf];
            if (node_lo < N)
                *(float2*)(base + (size_t)node_lo * OD + col) =
                    make_float2(a[0] + b1c.x, a[1] + b1c.y);
            if (node_hi < N)
                *(float2*)(base + (size_t)node_hi * OD + col) =
                    make_float2(a[2] + b1c.x, a[3] + b1c.y);
        }
    }
}

// ---------------------------------------------------------------------------
// Edge kernel over SORTED edges (packed int4), double-buffered staging,
// warp-uniform fast path (all 16 edges same destination row).
__global__ __launch_bounds__(256, 3) void edge_hidden_kernel(
    long long E, int n_tiles) {
    extern __shared__ char sm[];
    const uint32_t sb = smem_u32(sm);
    const int tid = threadIdx.x;
    const int wid = tid >> 5;
    const int lane = tid & 31;
    const unsigned FULL = 0xFFFFFFFFu;

    for (int t = tid; t < 512; t += 256) {
        int k = t >> 4, n8 = (t & 15) << 3;
        *(uint4*)(sm + E_W1 + k * PITCH_W_B + n8 * 2) = *(const uint4*)(g_W1ch + k * OD + n8);
    }

    const int m0 = wid * 16;
    const int qrow = lane >> 2;
    const int qcol = (lane & 3) * 2;
    const int l16 = lane & 15;
    const uint32_t blane_off = l16 * PITCH_W_B + (lane >> 4) * 16;

    // ---- prologue: stage first tile into buf 0 ----
    {
        const long long e00 = (long long)blockIdx.x * TE;
        if (tid < TE) {
            long long p = e00 + tid;
            int4 pk = make_int4(0, 0, 0, 0);
            if (p < E) pk = g_epack[p];
            *(int*)(sm + E_BUF + BUF_ROWS + tid * 4) = pk.x;
            *(int*)(sm + E_BUF + BUF_COLS + tid * 4) = pk.y;
        }
        {
            int er = tid >> 1, c0h = (tid & 1) * 16;
            long long p = e00 + er;
            uint4 v0 = make_uint4(0, 0, 0, 0), v1 = v0;
            if (p < E) {
                long long e = (long long)g_epack[p].z;
                const uint4* pf = (const uint4*)(g_ef16 + e * ED + c0h);
                v0 = pf[0]; v1 = pf[1];
            }
            char* ph = sm + E_BUF + BUF_EF + er * PITCH_EF_B + c0h * 2;
            *(uint4*)ph = v0;
            *(uint4*)(ph + 16) = v1;
        }
    }
    __syncthreads();

    int it = 0;
    for (int tile = blockIdx.x; tile < n_tiles; tile += gridDim.x, it++) {
        const long long e0 = (long long)tile * TE;
        const uint32_t cb = E_BUF + (uint32_t)(it & 1) * E_BUFSZ;
        const uint32_t nb2 = E_BUF + (uint32_t)((it + 1) & 1) * E_BUFSZ;
        const int ntile = tile + gridDim.x;
        const bool has_next = ntile < n_tiles;

        // ---- early-issue next tile loads ----
        int4 npk = make_int4(0, 0, 0, 0);
        uint4 nv0 = make_uint4(0, 0, 0, 0), nv1 = nv0;
        if (has_next) {
            long long e0n = (long long)ntile * TE;
            if (tid < TE) {
                long long p = e0n + tid;
                if (p < E) npk = g_epack[p];
            }
            {
                long long p = e0n + (tid >> 1);
                if (p < E) {
                    long long e = (long long)g_epack[p].z;
                    const uint4* pf = (const uint4*)(g_ef16 + e * ED + (tid & 1) * 16);
                    nv0 = pf[0]; nv1 = pf[1];
                }
            }
        }

        // ---- compute current tile ----
        int* s_rows = (int*)(sm + cb + BUF_ROWS);
        int* s_cols = (int*)(sm + cb + BUF_COLS);
        const uint32_t efA = sb + cb + BUF_EF + (m0 + l16) * PITCH_EF_B + ((lane >> 4) * 8) * 2;

        const int e_lo = m0 + qrow, e_hi = e_lo + 8;
        const int r_lo = s_rows[e_lo], r_hi = s_rows[e_hi];
        const int c_lo = s_cols[e_lo], c_hi = s_cols[e_hi];
        const bool v_lo = (e0 + e_lo) < E;
        const bool v_hi = (e0 + e_hi) < E;
        const float* prl_base = g_Pr + (size_t)r_lo * OD;
        const float* pcl_base = g_Pc + (size_t)c_lo * OD;
        const float* pch_base = g_Pc + (size_t)c_hi * OD;
        float* Hlo = g_H + (size_t)r_lo * OD;

        uint32_t eh[2][4];
        ldmx4(eh[0], efA);
        ldmx4(eh[1], efA + 32);

        // warp-uniform: all 16 edges map to one destination row
        int r0 = __shfl_sync(FULL, r_lo, 0);
        bool uni = __all_sync(FULL, (r_lo == r0) && (r_hi == r0));

        if (uni) {
            // ---- fast path: single row; fold hi into lo; 3-shfl reduce ----
#pragma unroll
            for (int g = 0; g < 4; g++) {
                float2 prl[4], pcl[4], pch[4];
#pragma unroll
                for (int cc = 0; cc < 4; cc++) {
                    int col = (4 * g + cc) * 8 + qcol;
                    prl[cc] = *(const float2*)(prl_base + col);
                    pcl[cc] = *(const float2*)(pcl_base + col);
                    pch[cc] = *(const float2*)(pch_base + col);
                }
#pragma unroll
                for (int t = 0; t < 2; t++) {
                    int n2 = 2 * g + t;
                    float a8[8];
#pragma unroll
                    for (int j = 0; j < 8; j++) a8[j] = 0.f;
#pragma unroll
                    for (int k = 0; k < 2; k++) {
                        uint32_t b[4];
                        ldmx4t(b, sb + E_W1 + k * 16 * PITCH_W_B + n2 * 32 + blane_off);
                        mma_f16(a8,     eh[k], b);
                        mma_f16(a8 + 4, eh[k], b + 2);
                    }
#pragma unroll
                    for (int u = 0; u < 2; u++) {
                        int cc = 2 * t + u;
                        int col = (4 * g + cc) * 8 + qcol;
                        float h0 = fmaxf(a8[u*4+0] + prl[cc].x + pcl[cc].x, 0.f);
                        float h1 = fmaxf(a8[u*4+1] + prl[cc].y + pcl[cc].y, 0.f);
                        float h2 = fmaxf(a8[u*4+2] + prl[cc].x + pch[cc].x, 0.f);
                        float h3 = fmaxf(a8[u*4+3] + prl[cc].y + pch[cc].y, 0.f);
                        if (!v_lo) { h0 = 0.f; h1 = 0.f; }
                        if (!v_hi) { h2 = 0.f; h3 = 0.f; }
                        h0 += h2; h1 += h3;
                        h0 += __shfl_down_sync(FULL, h0, 16);
                        h1 += __shfl_down_sync(FULL, h1, 16);
                        h0 += __shfl_down_sync(FULL, h0, 8);
                        h1 += __shfl_down_sync(FULL, h1, 8);
                        h0 += __shfl_down_sync(FULL, h0, 4);
                        h1 += __shfl_down_sync(FULL, h1, 4);
                        if (qrow == 0)
                            asm volatile("red.global.add.v2.f32 [%0], {%1,%2};"
                                         :: "l"(Hlo + col), "f"(h0), "f"(h1) : "memory");
                    }
                }
            }
        } else {
            // ---- slow path: segmented reduce over runs ----
            const float* prh_base = g_Pr + (size_t)r_hi * OD;
            float* Hhi = g_H + (size_t)r_hi * OD;
            int rt;
            rt = __shfl_down_sync(FULL, r_lo, 4);  const bool s1l = (qrow < 7) && (rt == r_lo);
            rt = __shfl_down_sync(FULL, r_lo, 8);  const bool s2l = (qrow < 6) && (rt == r_lo);
            rt = __shfl_down_sync(FULL, r_lo, 16); const bool s4l = (qrow < 4) && (rt == r_lo);
            rt = __shfl_up_sync(FULL, r_lo, 4);    const bool hl  = (qrow == 0) || (rt != r_lo);
            rt = __shfl_down_sync(FULL, r_hi, 4);  const bool s1h = (qrow < 7) && (rt == r_hi);
            rt = __shfl_down_sync(FULL, r_hi, 8);  const bool s2h = (qrow < 6) && (rt == r_hi);
            rt = __shfl_down_sync(FULL, r_hi, 16); const bool s4h = (qrow < 4) && (rt == r_hi);
            rt = __shfl_up_sync(FULL, r_hi, 4);    const bool hh  = (qrow == 0) || (rt != r_hi);
#pragma unroll
            for (int g = 0; g < 4; g++) {
                float2 prl[4], prh[4], pcl[4], pch[4];
#pragma unroll
                for (int cc = 0; cc < 4; cc++) {
                    int col = (4 * g + cc) * 8 + qcol;
                    prl[cc] = *(const float2*)(prl_base + col);
                    prh[cc] = *(const float2*)(prh_base + col);
                    pcl[cc] = *(const float2*)(pcl_base + col);
                    pch[cc] = *(const float2*)(pch_base + col);
                }
#pragma unroll
                for (int t = 0; t < 2; t++) {
                    int n2 = 2 * g + t;
                    float a8[8];
#pragma unroll
                    for (int j = 0; j < 8; j++) a8[j] = 0.f;
#pragma unroll
                    for (int k = 0; k < 2; k++) {
                        uint32_t b[4];
                        ldmx4t(b, sb + E_W1 + k * 16 * PITCH_W_B + n2 * 32 + blane_off);
                        mma_f16(a8,     eh[k], b);
                        mma_f16(a8 + 4, eh[k], b + 2);
                    }
#pragma unroll
                    for (int u = 0; u < 2; u++) {
                        int cc = 2 * t + u;
                        int col = (4 * g + cc) * 8 + qcol;
                        float h0 = fmaxf(a8[u*4+0] + prl[cc].x + pcl[cc].x, 0.f);
                        float h1 = fmaxf(a8[u*4+1] + prl[cc].y + pcl[cc].y, 0.f);
                        float h2 = fmaxf(a8[u*4+2] + prh[cc].x + pch[cc].x, 0.f);
                        float h3 = fmaxf(a8[u*4+3] + prh[cc].y + pch[cc].y, 0.f);
                        if (!v_lo) { h0 = 0.f; h1 = 0.f; }
                        if (!v_hi) { h2 = 0.f; h3 = 0.f; }
                        float s;
                        s = __shfl_down_sync(FULL, h0, 4);  if (s1l) h0 += s;
                        s = __shfl_down_sync(FULL, h0, 8);  if (s2l) h0 += s;
                        s = __shfl_down_sync(FULL, h0, 16); if (s4l) h0 += s;
                        s = __shfl_down_sync(FULL, h1, 4);  if (s1l) h1 += s;
                        s = __shfl_down_sync(FULL, h1, 8);  if (s2l) h1 += s;
                        s = __shfl_down_sync(FULL, h1, 16); if (s4l) h1 += s;
                        s = __shfl_down_sync(FULL, h2, 4);  if (s1h) h2 += s;
                        s = __shfl_down_sync(FULL, h2, 8);  if (s2h) h2 += s;
                        s = __shfl_down_sync(FULL, h2, 16); if (s4h) h2 += s;
                        s = __shfl_down_sync(FULL, h3, 4);  if (s1h) h3 += s;
                        s = __shfl_down_sync(FULL, h3, 8);  if (s2h) h3 += s;
                        s = __shfl_down_sync(FULL, h3, 16); if (s4h) h3 += s;
                        if (hl)
                            asm volatile("red.global.add.v2.f32 [%0], {%1,%2};"
                                         :: "l"(Hlo + col), "f"(h0), "f"(h1) : "memory");
                        if (hh)
                            asm volatile("red.global.add.v2.f32 [%0], {%1,%2};"
                                         :: "l"(Hhi + col), "f"(h2), "f"(h3) : "memory");
                    }
                }
            }
        }

        // ---- store next tile into alternate buffer, single sync ----
        if (has_next) {
            if (tid < TE) {
                *(int*)(sm + nb2 + BUF_ROWS + tid * 4) = npk.x;
                *(int*)(sm + nb2 + BUF_COLS + tid * 4) = npk.y;
            }
            char* ph = sm + nb2 + BUF_EF + (tid >> 1) * PITCH_EF_B + ((tid & 1) * 16) * 2;
            *(uint4*)ph = nv0;
            *(uint4*)(ph + 16) = nv1;
        }
        __syncthreads();
    }
}

// ---------------------------------------------------------------------------
// Final: out = g_H @ W2 + deg * b2 (3-term split, ~fp32 accuracy)
__global__ __launch_bounds__(256, 1) void final_out_mma_kernel(
    const float* __restrict__ b2g, float* __restrict__ out, int N) {
    extern __shared__ char sm[];
    const uint32_t sb = smem_u32(sm);
    const int tid = threadIdx.x;
    const int wid = tid >> 5;
    const int lane = tid & 31;
    const int l16 = lane & 15;
    const int qrow = lane >> 2;
    const int qcol = (lane & 3) * 2;
    const int n0 = blockIdx.x * 128;

    {
        int row = tid >> 1, c0 = (tid & 1) * 64;
        int node = n0 + row;
        char* ph = sm + F_AH + row * PITCH_W_B + c0 * 2;
        char* pl = sm + F_AL + row * PITCH_W_B + c0 * 2;
#pragma unroll
        for (int q = 0; q < 8; q++) {
            float4 f0 = make_float4(0.f, 0.f, 0.f, 0.f), f1 = f0;
            if (node < N) {
                f0 = *(const float4*)(g_H + (size_t)node * OD + c0 + q * 8);
                f1 = *(const float4*)(g_H + (size_t)node * OD + c0 + q * 8 + 4);
            }
            uint32_t h0, l0, h1, l1, h2, l2, h3, l3;
            split2h(f0.x, f0.y, h0, l0); split2h(f0.z, f0.w, h1, l1);
            split2h(f1.x, f1.y, h2, l2); split2h(f1.z, f1.w, h3, l3);
            *(uint4*)(ph + q * 16) = make_uint4(h0, h1, h2, h3);
            *(uint4*)(pl + q * 16) = make_uint4(l0, l1, l2, l3);
        }
    }
    for (int t = tid; t < 2048; t += 256) {
        int k = t >> 4, c8 = (t & 15) << 3;
        *(uint4*)(sm + F_WH + k * PITCH_W_B + c8 * 2) = *(const uint4*)(g_W2_hi + k * OD + c8);
        *(uint4*)(sm + F_WL + k * PITCH_W_B + c8 * 2) = *(const uint4*)(g_W2_lo + k * OD + c8);
    }
    if (tid < 128) {
        int node = n0 + tid;
        ((float*)(sm + F_B2))[tid] = b2g[tid];
        ((float*)(sm + F_DEG))[tid] = (node < N) ? (float)g_cnt[node] : 0.f;
    }
    __syncthreads();

    const int m0 = wid * 16;
    uint32_t ahf[8][4], alf[8][4];
    {
        uint32_t ab_h = sb + F_AH + (m0 + l16) * PITCH_W_B + (lane >> 4) * 16;
        uint32_t ab_l = sb + F_AL + (m0 + l16) * PITCH_W_B + (lane >> 4) * 16;
#pragma unroll
        for (int k = 0; k < 8; k++) {
            ldmx4(ahf[k], ab_h + k * 32);
            ldmx4(alf[k], ab_l + k * 32);
        }
    }

    float acc[16][4];
#pragma unroll
    for (int i = 0; i < 16; i++)
#pragma unroll
        for (int j = 0; j < 4; j++) acc[i][j] = 0.f;
#pragma unroll
    for (int n2 = 0; n2 < 8; n2++) {
#pragma unroll
        for (int k = 0; k < 8; k++) {
            uint32_t bh[4], bl[4];
            uint32_t ba = (k * 16 + l16) * PITCH_W_B + n2 * 32 + (lane >> 4) * 16;
            ldmx4t(bh, sb + F_WH + ba);
            ldmx4t(bl, sb + F_WL + ba);
            mma_f16(acc[2 * n2],     ahf[k], bh);
            mma_f16(acc[2 * n2],     ahf[k], bl);
            mma_f16(acc[2 * n2],     alf[k], bh);
            mma_f16(acc[2 * n2 + 1], ahf[k], bh + 2);
            mma_f16(acc[2 * n2 + 1], ahf[k], bl + 2);
            mma_f16(acc[2 * n2 + 1], alf[k], bh + 2);
        }
    }

    const int node_lo = n0 + m0 + qrow;
    const int node_hi = node_lo + 8;
    const float deg_lo = ((float*)(sm + F_DEG))[m0 + qrow];
    const float deg_hi = ((float*)(sm + F_DEG))[m0 + qrow + 8];
#pragma unroll
    for (int n2 = 0; n2 < 8; n2++) {
#pragma unroll
        for (int hlf = 0; hlf < 2; hlf++) {
            int col = n2 * 16 + hlf * 8 + qcol;
            float2 b2c = *(const float2*)(sm + F_B2 + col * 4);
            float* a = acc[2 * n2 + hlf];
            if (node_lo < N)
                *(float2*)(out + (size_t)node_lo * OD + col) =
                    make_float2(a[0] + deg_lo * b2c.x, a[1] + deg_lo * b2c.y);
            if (node_hi < N)
                *(float2*)(out + (size_t)node_hi * OD + col) =
                    make_float2(a[2] + deg_hi * b2c.x, a[3] + deg_hi * b2c.y);
        }
    }
}

// ---------------------------------------------------------------------------
extern "C" void kernel_launch(void* const* d_in, const int* in_sizes, int n_in,
                              void* d_out, int out_size) {
    const float* h = (const float*)d_in[0];
    const void* edge_index = d_in[1];
    const float* ef = (const float*)d_in[2];
    const float *W1 = 0, *b1 = 0, *W2 = 0, *b2 = 0;
    for (int i = 3; i < n_in; i++) {
        int s = in_sizes[i];
        if (s == (2 * ND + ED) * OD) W1 = (const float*)d_in[i];
        else if (s == OD * OD) W2 = (const float*)d_in[i];
        else if (s == OD) { if (!b1) b1 = (const float*)d_in[i]; else b2 = (const float*)d_in[i]; }
    }
    if (!W1 || !b1 || !W2 || !b2) return;

    int N = in_sizes[0] / ND;
    if (N > MAXN) N = MAXN;
    long long E = (long long)(in_sizes[1] / 2);
    if (E > MAXE) E = MAXE;
    float* out = (float*)d_out;
    int n_tiles = (int)((E + TE - 1) / TE);
    int nb = (N + 127) / 128;
    int eb = (int)((E + 255) / 256);

    static cudaStream_t s1 = 0, s2 = 0;
    static cudaEvent_t e0 = 0, e1 = 0, e2 = 0;
    if (!s1) {
        cudaStreamCreateWithFlags(&s1, cudaStreamNonBlocking);
        cudaStreamCreateWithFlags(&s2, cudaStreamNonBlocking);
        cudaEventCreateWithFlags(&e0, cudaEventDisableTiming);
        cudaEventCreateWithFlags(&e1, cudaEventDisableTiming);
        cudaEventCreateWithFlags(&e2, cudaEventDisableTiming);
    }

    // fork
    cudaEventRecord(e0, 0);
    cudaStreamWaitEvent(s1, e0, 0);
    cudaStreamWaitEvent(s2, e0, 0);

    // chain A (default): counting sort of edges by destination row
    zero_detect_kernel<<<(N + 255) / 256, 256>>>((const int*)edge_index, N);
    hist_kernel<<<eb * 2, 128>>>(edge_index, E);
    scan_kernel<<<1, 1024>>>(N);
    scatter_sort_kernel<<<(int)((E + 2047) / 2048), 256>>>(edge_index, E);

    // chain B (s1): weight prep + P precompute (+b1 baked into Pr)
    prep_weights_kernel<<<128, 256, 0, s1>>>(W1, W2);
    cudaFuncSetAttribute(precompute_P_mma_kernel,
                         cudaFuncAttributeMaxDynamicSharedMemorySize, F_TOTAL);
    {
        dim3 pgrid(nb, 2);
        precompute_P_mma_kernel<<<pgrid, 256, F_TOTAL, s1>>>(h, b1, N);
    }
    cudaEventRecord(e1, s1);

    // chain C (s2): ef fp16 preconvert + zero H
    convert_ef_kernel<<<(int)((E * 2 + 255) / 256), 256, 0, s2>>>(ef, E);
    zero_H_kernel<<<(N * OD + 255) / 256, 256, 0, s2>>>(N * OD);
    cudaEventRecord(e2, s2);

    // join
    cudaStreamWaitEvent(0, e1, 0);
    cudaStreamWaitEvent(0, e2, 0);

    int egrid = 3 * NSM;
    if (egrid > n_tiles) egrid = n_tiles;
    edge_hidden_kernel<<<egrid, 256, E_TOTAL>>>(E, n_tiles);

    cudaFuncSetAttribute(final_out_mma_kernel,
                         cudaFuncAttributeMaxDynamicSharedMemorySize, F_TOTAL);
    final_out_mma_kernel<<<nb, 256, F_TOTAL>>>(b2, out, N);
}